// round 5
// baseline (speedup 1.0000x reference)
#include <cuda_runtime.h>
#include <math.h>
#include <stdint.h>

#define Vn 100000
#define Dn 256
#define Bn 512
#define Sn 20
#define Nn (Bn*Sn)      // 10240
#define En (8*Nn)       // 81920
#define DEGMAX 128

// ---------------- scratch (device globals; no allocation allowed) ----------------
__device__ float g_inorm[Vn];
__device__ float g_hv[Nn*Dn];
__device__ float g_h[Nn*Dn];
__device__ float g_f[Bn*Dn];
__device__ float g_mscal[Nn];
__device__ float g_srn[Bn*Dn];
__device__ float g_logphi[Bn*2];
__device__ double g_rowsum[Bn];
__device__ double g_msum[Bn];
__device__ int   g_mask_v[Bn*Sn];
__device__ float g_mask_l[Bn*Sn];
// CSR
__device__ int g_deg[Nn];
__device__ int g_off[Nn+1];
__device__ int g_pos[Nn];
__device__ int g_eidx[En];

// ---------------- helpers ----------------
__device__ __forceinline__ unsigned long long ffma2(unsigned long long a, unsigned long long b, unsigned long long c){
    unsigned long long d;
    asm("fma.rn.f32x2 %0, %1, %2, %3;" : "=l"(d) : "l"(a), "l"(b), "l"(c));
    return d;
}
__device__ __forceinline__ float f2lo(unsigned long long u){ return __int_as_float((int)(unsigned)(u & 0xFFFFFFFFull)); }
__device__ __forceinline__ float f2hi(unsigned long long u){ return __int_as_float((int)(unsigned)(u >> 32)); }
__device__ __forceinline__ unsigned long long fpack(float lo, float hi){
    unsigned long long u;
    asm("mov.b64 %0, {%1, %2};" : "=l"(u) : "r"(__float_as_int(lo)), "r"(__float_as_int(hi)));
    return u;
}
__device__ __forceinline__ float tf32r(float x){
    float y; asm("cvt.rna.tf32.f32 %0, %1;" : "=f"(y) : "f"(x)); return y;
}

// mma.sync m16n8k8 tf32: D = A*B + D
#define MMA_TF32(d, a, b0, b1) \
    asm volatile("mma.sync.aligned.m16n8k8.row.col.f32.tf32.tf32.f32 " \
        "{%0,%1,%2,%3}, {%4,%5,%6,%7}, {%8,%9}, {%0,%1,%2,%3};" \
        : "+f"((d)[0]), "+f"((d)[1]), "+f"((d)[2]), "+f"((d)[3]) \
        : "r"((a)[0]), "r"((a)[1]), "r"((a)[2]), "r"((a)[3]), "r"(b0), "r"(b1))

// ---------------- K0: zero scratch (small now) ----------------
__global__ void k_zero(){
    int i = blockIdx.x*blockDim.x + threadIdx.x;
    if (i < Nn) g_deg[i] = 0;
    if (i < Bn){ g_rowsum[i]=0.0; g_msum[i]=0.0; }
}

// ---------------- CSR build ----------------
__global__ void k_count(const int* __restrict__ dst){
    int e = blockIdx.x*blockDim.x + threadIdx.x;
    if (e < En) atomicAdd(&g_deg[dst[e]], 1);
}
__global__ void k_scan(){        // 1 block, 1024 threads, 10 elems/thread
    __shared__ int warp_sums[32];
    int t = threadIdx.x;
    int base = t*10;
    int local[10]; int s = 0;
    #pragma unroll
    for (int i=0;i<10;i++){ local[i]=s; s += g_deg[base+i]; }
    int lane = t&31, w = t>>5;
    int v = s;
    #pragma unroll
    for (int o=1;o<32;o<<=1){ int u=__shfl_up_sync(0xffffffffu,v,o); if(lane>=o) v+=u; }
    if (lane==31) warp_sums[w]=v;
    __syncthreads();
    if (w==0){
        int x = warp_sums[lane];
        #pragma unroll
        for (int o=1;o<32;o<<=1){ int u=__shfl_up_sync(0xffffffffu,x,o); if(lane>=o) x+=u; }
        warp_sums[lane]=x;
    }
    __syncthreads();
    int excl = v - s + (w>0 ? warp_sums[w-1] : 0);
    #pragma unroll
    for (int i=0;i<10;i++){ g_off[base+i]=excl+local[i]; g_pos[base+i]=excl+local[i]; }
    if (t==1023) g_off[Nn]=En;
}
__global__ void k_scatter(const int* __restrict__ dst){
    int e = blockIdx.x*blockDim.x + threadIdx.x;
    if (e < En){
        int p = atomicAdd(&g_pos[dst[e]], 1);
        g_eidx[p] = e;
    }
}

// ---------------- K1: inverse norms of emb rows ----------------
__global__ void k_inorm(const float* __restrict__ emb){
    int row = blockIdx.x*8 + (threadIdx.x>>5);
    int lane = threadIdx.x&31;
    float ss = 0.f;
    const float* p = emb + (size_t)row*Dn;
    for (int k=lane;k<Dn;k+=32){ float x=p[k]; ss += x*x; }
    #pragma unroll
    for (int o=16;o;o>>=1) ss += __shfl_xor_sync(0xffffffffu, ss, o);
    if (lane==0) g_inorm[row] = 1.f / fmaxf(sqrtf(ss), 1e-12f);
}

// ---------------- K2: h_v = l2norm(emb[iid]) ----------------
__global__ void k_hv(const float* __restrict__ emb, const int* __restrict__ iid){
    int i = blockIdx.x*blockDim.x + threadIdx.x;
    int n = i>>8, k = i&255;
    int id = iid[n];
    g_hv[i] = emb[(size_t)id*Dn + k] * g_inorm[id];
}

// ---------------- K3: fused gather GAT: scores + edge softmax + aggregation ----------------
__global__ void __launch_bounds__(256) k_gat(const int* __restrict__ src, const int* __restrict__ dis,
                      const float* __restrict__ dis_emb,
                      const float* __restrict__ pi_w, const float* __restrict__ M_w){
    __shared__ float hd[Dn];
    __shared__ float se[DEGMAX];
    __shared__ int   ssrc[DEGMAX];
    int d = blockIdx.x;
    int t = threadIdx.x;
    int beg = g_off[d], end = g_off[d+1];
    int deg = end - beg; if (deg > DEGMAX) deg = DEGMAX;
    if (deg == 0){
        g_h[(size_t)d*Dn + t] = 0.f;
        return;
    }
    hd[t] = g_hv[(size_t)d*Dn + t];
    __syncthreads();
    int warp = t>>5, lane = t&31;
    for (int slot=warp; slot<deg; slot+=8){
        int e = g_eidx[beg+slot];
        int s = src[e], di = dis[e];
        const float* hs = g_hv + (size_t)s*Dn;
        const float* he = dis_emb + (size_t)di*Dn;
        float e1 = 0.f, g = 0.f;
        for (int k=lane;k<Dn;k+=32){
            float a = hs[k], b = hd[k], c = he[k];
            float p = a*b;
            e1 += p*c*pi_w[k];
            g  += p*M_w[k] + c*M_w[Dn+k];
        }
        #pragma unroll
        for (int o=16;o;o>>=1){
            e1 += __shfl_xor_sync(0xffffffffu, e1, o);
            g  += __shfl_xor_sync(0xffffffffu, g,  o);
        }
        if (lane==0){
            se[slot] = e1 * (1.f/(1.f+__expf(-g)));
            ssrc[slot] = s;
        }
    }
    __syncthreads();
    // per-thread redundant softmax over deg (deg ~ 8)
    float mx = -3.4e38f;
    for (int i=0;i<deg;i++) mx = fmaxf(mx, se[i]);
    float acc = 0.f, asum = 0.f;
    for (int i=0;i<deg;i++){
        float a = __expf(se[i]-mx);
        asum += a;
        acc += a * g_hv[(size_t)ssrc[i]*Dn + t];
    }
    g_h[(size_t)d*Dn + t] = acc / asum;
}

// ---------------- K6: f = concat(h_t, last_feat) @ r_w ----------------
__global__ void k_f(const int* __restrict__ tid_, const int* __restrict__ last_idx,
                    const float* __restrict__ target_emb, const float* __restrict__ r_w){
    __shared__ float sin_[8][2*Dn];
    int b0 = blockIdx.x*8;
    int t = threadIdx.x;
    for (int idx=t; idx<8*2*Dn; idx+=256){
        int j = idx>>9, k = idx&511;
        int b = b0+j;
        float v = (k<Dn) ? target_emb[(size_t)tid_[b]*Dn + k]
                         : g_h[(size_t)last_idx[b]*Dn + (k-Dn)];
        sin_[j][k] = v;
    }
    __syncthreads();
    float acc[8] = {0,0,0,0,0,0,0,0};
    int d = t;
    for (int k=0;k<2*Dn;k++){
        float w = r_w[(size_t)k*Dn + d];
        #pragma unroll
        for (int j=0;j<8;j++) acc[j] += sin_[j][k]*w;
    }
    #pragma unroll
    for (int j=0;j<8;j++) g_f[(size_t)(b0+j)*Dn + d] = acc[j];
}

// ---------------- K7: eagg + m-scalar ----------------
__global__ void __launch_bounds__(256) k_eagg(const int* __restrict__ pid, const int* __restrict__ agg_dst,
                        const float* __restrict__ pos_emb, const float* __restrict__ q_w){
    __shared__ __align__(16) float sT[2*Dn][20];
    __shared__ int s_pid[16], s_sess[16];
    __shared__ float sred[8][16];
    int j0 = blockIdx.x*16;
    int t = threadIdx.x;
    if (t<16){ s_pid[t] = pid[j0+t]; s_sess[t] = agg_dst[j0+t]; }
    __syncthreads();
    for (int idx=t; idx<16*2*Dn; idx+=256){
        int j = idx>>9, k = idx&511;
        float v = (k<Dn) ? g_h[(size_t)(j0+j)*Dn + k]
                         : pos_emb[(size_t)s_pid[j]*Dn + (k-Dn)];
        sT[k][j] = v;
    }
    __syncthreads();

    unsigned long long acc[8];
    #pragma unroll
    for (int p=0;p<8;p++) acc[p]=0ull;
    int d = t;
    #pragma unroll 4
    for (int k=0;k<2*Dn;k++){
        float w = q_w[(size_t)k*Dn + d];
        unsigned long long wd = fpack(w,w);
        const ulonglong2* sp = (const ulonglong2*)&sT[k][0];
        #pragma unroll
        for (int q=0;q<4;q++){
            ulonglong2 pr = sp[q];
            acc[2*q+0] = ffma2(pr.x, wd, acc[2*q+0]);
            acc[2*q+1] = ffma2(pr.y, wd, acc[2*q+1]);
        }
    }
    float partial[16];
    #pragma unroll
    for (int p=0;p<8;p++){
        float t0 = tanhf(f2lo(acc[p]));
        float t1 = tanhf(f2hi(acc[p]));
        int j = 2*p;
        partial[j]   = t0 * g_f[(size_t)s_sess[j]*Dn + d];
        partial[j+1] = t1 * g_f[(size_t)s_sess[j+1]*Dn + d];
    }
    int w = t>>5, lane = t&31;
    #pragma unroll
    for (int j=0;j<16;j++){
        float p = partial[j];
        #pragma unroll
        for (int o=16;o;o>>=1) p += __shfl_xor_sync(0xffffffffu, p, o);
        if (lane==0) sred[w][j] = p;
    }
    __syncthreads();
    if (t<16){
        float s=0.f;
        #pragma unroll
        for (int ww=0;ww<8;ww++) s += sred[ww][t];
        g_mscal[j0+t] = s;
    }
}

// ---------------- K8: sr per session + l2norm ----------------
__global__ void k_sr(){
    __shared__ float sm[Sn];
    __shared__ float sred[8];
    int b = blockIdx.x, t = threadIdx.x;
    if (t<Sn) sm[t] = g_mscal[b*Sn + t];
    __syncthreads();
    float acc = 0.f;
    #pragma unroll
    for (int s=0;s<Sn;s++) acc += g_h[(size_t)(b*Sn+s)*Dn + t]*sm[s];
    float ss = acc*acc;
    #pragma unroll
    for (int o=16;o;o>>=1) ss += __shfl_xor_sync(0xffffffffu, ss, o);
    if ((t&31)==0) sred[t>>5] = ss;
    __syncthreads();
    float tot = 0.f;
    #pragma unroll
    for (int w=0;w<8;w++) tot += sred[w];
    g_srn[(size_t)b*Dn + t] = acc / fmaxf(sqrtf(tot), 1e-12f);
}

// ---------------- K9: phi head ----------------
__global__ void k_phi(const float* __restrict__ sc1_w, const float* __restrict__ sc1_b,
                      const float* __restrict__ sc2_w){
    __shared__ float ssr[8][Dn];
    __shared__ float s_p[8][2];
    int b0 = blockIdx.x*8;
    int t = threadIdx.x;
    for (int idx=t; idx<8*Dn; idx+=256){
        int j = idx>>8, k = idx&255;
        ssr[j][k] = g_srn[(size_t)(b0+j)*Dn + k];
    }
    if (t<16) s_p[t>>1][t&1] = 0.f;
    __syncthreads();
    float acc[8] = {0,0,0,0,0,0,0,0};
    int d = t;
    for (int k=0;k<Dn;k++){
        float w = sc1_w[(size_t)k*Dn + d];
        #pragma unroll
        for (int j=0;j<8;j++) acc[j] += ssr[j][k]*w;
    }
    float bb = sc1_b[d], w0 = sc2_w[d*2], w1 = sc2_w[d*2+1];
    int lane = t&31;
    #pragma unroll
    for (int j=0;j<8;j++){
        float hid = fmaxf(acc[j]+bb, 0.f);
        float p0 = hid*w0, p1 = hid*w1;
        #pragma unroll
        for (int o=16;o;o>>=1){
            p0 += __shfl_xor_sync(0xffffffffu, p0, o);
            p1 += __shfl_xor_sync(0xffffffffu, p1, o);
        }
        if (lane==0){ atomicAdd(&s_p[j][0], p0); atomicAdd(&s_p[j][1], p1); }
    }
    __syncthreads();
    if (t<8){
        float a0 = s_p[t][0], a1 = s_p[t][1];
        float m = fmaxf(a0,a1);
        float lse = m + logf(__expf(a0-m)+__expf(a1-m));
        g_logphi[(b0+t)*2+0] = a0 - lse;
        g_logphi[(b0+t)*2+1] = a1 - lse;
    }
}

// ---------------- K10: masked (in-session) logits + msum ----------------
__global__ void k_masked(const int* __restrict__ iid, const float* __restrict__ emb){
    __shared__ int iids[Sn];
    __shared__ float s_sr[Dn];
    int b = blockIdx.x, t = threadIdx.x;
    if (t<Sn) iids[t] = iid[b*Sn+t];
    if (t<Dn) s_sr[t] = g_srn[(size_t)b*Dn + t];
    __syncthreads();
    int warp = t>>5, lane = t&31;
    for (int slot=warp; slot<Sn; slot+=8){
        int v = iids[slot];
        bool dup = false;
        for (int j=0;j<slot;j++) if (iids[j]==v) { dup=true; break; }
        if (dup){
            if (lane==0) g_mask_v[b*Sn+slot] = -1;
            continue;
        }
        const float* ev = emb + (size_t)v*Dn;
        float dot = 0.f;
        for (int k=lane;k<Dn;k+=32) dot += s_sr[k]*ev[k];
        #pragma unroll
        for (int o=16;o;o>>=1) dot += __shfl_xor_sync(0xffffffffu, dot, o);
        if (lane==0){
            float l = dot * g_inorm[v] * 12.f;
            g_mask_v[b*Sn+slot] = v;
            g_mask_l[b*Sn+slot] = l;
            atomicAdd(&g_msum[b], (double)__expf(l-12.f));
        }
    }
}

// ---------------- K11: mma.sync tf32 3x-split GEMM ----------------
#define PSTRIDE 20
__global__ void __launch_bounds__(256) k_gemm_mma(const float* __restrict__ emb, float* __restrict__ out){
    __shared__ __align__(16) float2 As[128*PSTRIDE];
    __shared__ __align__(16) float2 Bs[128*PSTRIDE];
    int tid = threadIdx.x;
    int w = tid>>5, lane = tid&31;
    int g = lane>>2, t = lane&3;
    int wm = w>>1, wn = w&1;
    int m0 = blockIdx.x*128;       // 0..3
    int v0 = blockIdx.y*128;       // 0..781

    float acc[2][8][4];
    #pragma unroll
    for (int mi=0;mi<2;mi++)
        #pragma unroll
        for (int ni=0;ni<8;ni++)
            #pragma unroll
            for (int q=0;q<4;q++) acc[mi][ni][q]=0.f;

    const float4 z4 = make_float4(0.f,0.f,0.f,0.f);
    float4 pa[2], pb[2];
    #pragma unroll
    for (int it=0; it<2; it++){
        int id = it*256 + tid;
        int row = id>>2, c4 = id&3;
        pa[it] = *(const float4*)(g_srn + (size_t)(m0+row)*Dn + c4*4);
        int vrow = v0 + row;
        pb[it] = (vrow<Vn) ? *(const float4*)(emb + (size_t)vrow*Dn + c4*4) : z4;
    }

    for (int kc=0; kc<16; kc++){
        __syncthreads();
        #pragma unroll
        for (int it=0; it<2; it++){
            int id = it*256 + tid;
            int row = id>>2, c4 = id&3;
            float xs[4] = {pa[it].x, pa[it].y, pa[it].z, pa[it].w};
            float ys[4] = {pb[it].x, pb[it].y, pb[it].z, pb[it].w};
            float2* ap = &As[row*PSTRIDE + c4*4];
            float2* bp = &Bs[row*PSTRIDE + c4*4];
            #pragma unroll
            for (int j=0;j<4;j++){
                float hi = tf32r(xs[j]);
                ap[j] = make_float2(hi, tf32r(xs[j]-hi));
                float hb = tf32r(ys[j]);
                bp[j] = make_float2(hb, tf32r(ys[j]-hb));
            }
        }
        if (kc < 15){
            int k0 = (kc+1)*16;
            #pragma unroll
            for (int it=0; it<2; it++){
                int id = it*256 + tid;
                int row = id>>2, c4 = id&3;
                pa[it] = *(const float4*)(g_srn + (size_t)(m0+row)*Dn + k0 + c4*4);
                int vrow = v0 + row;
                pb[it] = (vrow<Vn) ? *(const float4*)(emb + (size_t)vrow*Dn + k0 + c4*4) : z4;
            }
        }
        __syncthreads();
        #pragma unroll
        for (int k8=0; k8<16; k8+=8){
            unsigned ahi[2][4], alo[2][4];
            #pragma unroll
            for (int mi=0;mi<2;mi++){
                int rb = wm*32 + mi*16 + g;
                float2 a0 = As[rb*PSTRIDE + k8+t];
                float2 a1 = As[(rb+8)*PSTRIDE + k8+t];
                float2 a2 = As[rb*PSTRIDE + k8+t+4];
                float2 a3 = As[(rb+8)*PSTRIDE + k8+t+4];
                ahi[mi][0]=__float_as_uint(a0.x); alo[mi][0]=__float_as_uint(a0.y);
                ahi[mi][1]=__float_as_uint(a1.x); alo[mi][1]=__float_as_uint(a1.y);
                ahi[mi][2]=__float_as_uint(a2.x); alo[mi][2]=__float_as_uint(a2.y);
                ahi[mi][3]=__float_as_uint(a3.x); alo[mi][3]=__float_as_uint(a3.y);
            }
            #pragma unroll
            for (int ni=0;ni<8;ni++){
                int nb = wn*64 + ni*8 + g;
                float2 b0 = Bs[nb*PSTRIDE + k8+t];
                float2 b1 = Bs[nb*PSTRIDE + k8+t+4];
                unsigned bh0=__float_as_uint(b0.x), bl0=__float_as_uint(b0.y);
                unsigned bh1=__float_as_uint(b1.x), bl1=__float_as_uint(b1.y);
                #pragma unroll
                for (int mi=0;mi<2;mi++){
                    MMA_TF32(acc[mi][ni], ahi[mi], bh0, bh1);
                    MMA_TF32(acc[mi][ni], ahi[mi], bl0, bl1);
                    MMA_TF32(acc[mi][ni], alo[mi], bh0, bh1);
                }
            }
        }
    }

    float rsum[4] = {0.f,0.f,0.f,0.f};
    #pragma unroll
    for (int mi=0;mi<2;mi++){
        int r0 = m0 + wm*32 + mi*16 + g;
        #pragma unroll
        for (int ni=0;ni<8;ni++){
            int col = v0 + wn*64 + ni*8 + 2*t;
            if (col < Vn){
                float s0 = 12.f*g_inorm[col], s1 = 12.f*g_inorm[col+1];
                float v00 = acc[mi][ni][0]*s0, v01 = acc[mi][ni][1]*s1;
                float v10 = acc[mi][ni][2]*s0, v11 = acc[mi][ni][3]*s1;
                float2* p0 = (float2*)(out + (size_t)r0*Vn + col);
                float2* p1 = (float2*)(out + (size_t)(r0+8)*Vn + col);
                __stcs(p0, make_float2(v00, v01));
                __stcs(p1, make_float2(v10, v11));
                rsum[mi*2+0] += __expf(v00-12.f) + __expf(v01-12.f);
                rsum[mi*2+1] += __expf(v10-12.f) + __expf(v11-12.f);
            }
        }
    }
    #pragma unroll
    for (int o=1;o<4;o<<=1)
        #pragma unroll
        for (int j=0;j<4;j++) rsum[j] += __shfl_xor_sync(0xffffffffu, rsum[j], o);
    if (t==0){
        #pragma unroll
        for (int j=0;j<4;j++){
            int row = m0 + wm*32 + (j>>1)*16 + (j&1)*8 + g;
            atomicAdd(&g_rowsum[row], (double)rsum[j]);
        }
    }
}

// ---------------- K12: per-row shift for unmasked entries ----------------
__global__ void k_finalize(float* __restrict__ out){
    __shared__ float s_shift;
    int row = blockIdx.y;
    if (threadIdx.x==0){
        double sex = g_rowsum[row] - g_msum[row];
        s_shift = g_logphi[row*2+1] - (float)(12.0 + log(sex));
    }
    __syncthreads();
    float sh = s_shift;
    int i = blockIdx.x*blockDim.x + threadIdx.x;
    if (i < Vn/4){
        float4* p = (float4*)(out + (size_t)row*Vn) + i;
        float4 o = __ldcs(p);
        o.x += sh; o.y += sh; o.z += sh; o.w += sh;
        __stcs(p, o);
    }
}

// ---------------- K13: overwrite masked entries ----------------
__global__ void k_fixup(float* __restrict__ out){
    int b = blockIdx.x, s = threadIdx.x;
    if (s >= Sn) return;
    int v = g_mask_v[b*Sn+s];
    if (v < 0) return;
    float lse_in = (float)(12.0 + log(g_msum[b]));
    out[(size_t)b*Vn + v] = g_mask_l[b*Sn+s] - lse_in + g_logphi[b*2+0];
}

// ---------------- launch ----------------
extern "C" void kernel_launch(void* const* d_in, const int* in_sizes, int n_in,
                              void* d_out, int out_size){
    const int* iid      = (const int*)d_in[0];
    const int* src      = (const int*)d_in[1];
    const int* dst      = (const int*)d_in[2];
    const int* dis      = (const int*)d_in[3];
    const int* pid      = (const int*)d_in[4];
    const int* agg_dst  = (const int*)d_in[6];
    const int* tid_     = (const int*)d_in[7];
    const int* last_idx = (const int*)d_in[8];
    const float* emb        = (const float*)d_in[9];
    const float* pos_emb    = (const float*)d_in[10];
    const float* dis_emb    = (const float*)d_in[11];
    const float* target_emb = (const float*)d_in[12];
    const float* pi_w  = (const float*)d_in[13];
    const float* M_w   = (const float*)d_in[14];
    const float* q_w   = (const float*)d_in[15];
    const float* r_w   = (const float*)d_in[16];
    const float* sc1_w = (const float*)d_in[17];
    const float* sc1_b = (const float*)d_in[18];
    const float* sc2_w = (const float*)d_in[19];
    float* out = (float*)d_out;

    k_zero<<<(Nn+255)/256,256>>>();
    k_count<<<En/256,256>>>(dst);
    k_scan<<<1,1024>>>();
    k_scatter<<<En/256,256>>>(dst);
    k_inorm<<<Vn/8,256>>>(emb);
    k_hv<<<(Nn*Dn)/256,256>>>(emb, iid);
    k_gat<<<Nn,256>>>(src,dis,dis_emb,pi_w,M_w);
    k_f<<<Bn/8,256>>>(tid_,last_idx,target_emb,r_w);
    k_eagg<<<Nn/16,256>>>(pid,agg_dst,pos_emb,q_w);
    k_sr<<<Bn,256>>>();
    k_phi<<<Bn/8,256>>>(sc1_w,sc1_b,sc2_w);
    k_masked<<<Bn,256>>>(iid, emb);
    dim3 gg(4, (Vn+127)/128);
    k_gemm_mma<<<gg, 256>>>(emb, out);
    dim3 gf((Vn/4 + 255)/256, Bn);
    k_finalize<<<gf,256>>>(out);
    k_fixup<<<Bn,32>>>(out);
}

// round 6
// speedup vs baseline: 1.1819x; 1.1819x over previous
#include <cuda_runtime.h>
#include <math.h>
#include <stdint.h>

#define Vn 100000
#define Dn 256
#define Bn 512
#define Sn 20
#define Nn (Bn*Sn)      // 10240
#define En (8*Nn)       // 81920
#define DEGMAX 128

// ---------------- scratch (device globals; no allocation allowed) ----------------
__device__ float g_inorm[Vn];
__device__ float g_hv[Nn*Dn];
__device__ float g_h[Nn*Dn];
__device__ float g_f[Bn*Dn];
__device__ float g_mscal[Nn];
__device__ float g_srn[Bn*Dn];
__device__ float g_logphi[Bn*2];
__device__ double g_rowsum[Bn];
__device__ double g_msum[Bn];
__device__ int   g_mask_v[Bn*Sn];
__device__ float g_mask_l[Bn*Sn];
// CSR
__device__ int g_deg[Nn];
__device__ int g_off[Nn+1];
__device__ int g_pos[Nn];
__device__ int g_eidx[En];
// packed GEMM operands (fragment-pair layout: slot s -> k = (s>>3)*16 + ((s>>2)&1)*8 + (s&3), pair (k, k+4))
__device__ float2 g_ahi[Bn*128];
__device__ float2 g_alo[Bn*128];
__device__ float2 g_bh[(size_t)Vn*128];   // 102.4 MB, tf32-rounded emb

// ---------------- helpers ----------------
__device__ __forceinline__ unsigned long long ffma2(unsigned long long a, unsigned long long b, unsigned long long c){
    unsigned long long d;
    asm("fma.rn.f32x2 %0, %1, %2, %3;" : "=l"(d) : "l"(a), "l"(b), "l"(c));
    return d;
}
__device__ __forceinline__ float f2lo(unsigned long long u){ return __int_as_float((int)(unsigned)(u & 0xFFFFFFFFull)); }
__device__ __forceinline__ float f2hi(unsigned long long u){ return __int_as_float((int)(unsigned)(u >> 32)); }
__device__ __forceinline__ unsigned long long fpack(float lo, float hi){
    unsigned long long u;
    asm("mov.b64 %0, {%1, %2};" : "=l"(u) : "r"(__float_as_int(lo)), "r"(__float_as_int(hi)));
    return u;
}
__device__ __forceinline__ float tf32r(float x){
    float y; asm("cvt.rna.tf32.f32 %0, %1;" : "=f"(y) : "f"(x)); return y;
}

// mma.sync m16n8k8 tf32: D = A*B + D
#define MMA_TF32(d, a, b0, b1) \
    asm volatile("mma.sync.aligned.m16n8k8.row.col.f32.tf32.tf32.f32 " \
        "{%0,%1,%2,%3}, {%4,%5,%6,%7}, {%8,%9}, {%0,%1,%2,%3};" \
        : "+f"((d)[0]), "+f"((d)[1]), "+f"((d)[2]), "+f"((d)[3]) \
        : "r"((a)[0]), "r"((a)[1]), "r"((a)[2]), "r"((a)[3]), "r"(b0), "r"(b1))

// slot -> k mapping
__device__ __forceinline__ int slot_k(int s){ return (s>>3)*16 + ((s>>2)&1)*8 + (s&3); }

// ---------------- K0: zero scratch ----------------
__global__ void k_zero(){
    int i = blockIdx.x*blockDim.x + threadIdx.x;
    if (i < Nn) g_deg[i] = 0;
    if (i < Bn){ g_rowsum[i]=0.0; g_msum[i]=0.0; }
}

// ---------------- CSR build ----------------
__global__ void k_count(const int* __restrict__ dst){
    int e = blockIdx.x*blockDim.x + threadIdx.x;
    if (e < En) atomicAdd(&g_deg[dst[e]], 1);
}
__global__ void k_scan(){        // 1 block, 1024 threads, 10 elems/thread
    __shared__ int warp_sums[32];
    int t = threadIdx.x;
    int base = t*10;
    int local[10]; int s = 0;
    #pragma unroll
    for (int i=0;i<10;i++){ local[i]=s; s += g_deg[base+i]; }
    int lane = t&31, w = t>>5;
    int v = s;
    #pragma unroll
    for (int o=1;o<32;o<<=1){ int u=__shfl_up_sync(0xffffffffu,v,o); if(lane>=o) v+=u; }
    if (lane==31) warp_sums[w]=v;
    __syncthreads();
    if (w==0){
        int x = warp_sums[lane];
        #pragma unroll
        for (int o=1;o<32;o<<=1){ int u=__shfl_up_sync(0xffffffffu,x,o); if(lane>=o) x+=u; }
        warp_sums[lane]=x;
    }
    __syncthreads();
    int excl = v - s + (w>0 ? warp_sums[w-1] : 0);
    #pragma unroll
    for (int i=0;i<10;i++){ g_off[base+i]=excl+local[i]; g_pos[base+i]=excl+local[i]; }
    if (t==1023) g_off[Nn]=En;
}
__global__ void k_scatter(const int* __restrict__ dst){
    int e = blockIdx.x*blockDim.x + threadIdx.x;
    if (e < En){
        int p = atomicAdd(&g_pos[dst[e]], 1);
        g_eidx[p] = e;
    }
}

// ---------------- pack emb into tf32 fragment-pair layout ----------------
__global__ void k_bpack(const float* __restrict__ emb){
    long long id = (long long)blockIdx.x*blockDim.x + threadIdx.x;
    if (id >= (long long)Vn*128) return;
    int row = (int)(id>>7), s = (int)(id&127);
    int k = slot_k(s);
    const float* p = emb + (size_t)row*Dn;
    g_bh[(size_t)row*128 + s] = make_float2(tf32r(p[k]), tf32r(p[k+4]));
}

// ---------------- pack srn hi/lo split ----------------
__global__ void k_apack(){
    int id = blockIdx.x*blockDim.x + threadIdx.x;   // Bn*128 = 65536
    int row = id>>7, s = id&127;
    int k = slot_k(s);
    const float* p = g_srn + (size_t)row*Dn;
    float a0 = p[k], a1 = p[k+4];
    float h0 = tf32r(a0), h1 = tf32r(a1);
    g_ahi[row*128 + s] = make_float2(h0, h1);
    g_alo[row*128 + s] = make_float2(tf32r(a0-h0), tf32r(a1-h1));
}

// ---------------- K1: inverse norms of emb rows ----------------
__global__ void k_inorm(const float* __restrict__ emb){
    int row = blockIdx.x*8 + (threadIdx.x>>5);
    int lane = threadIdx.x&31;
    float ss = 0.f;
    const float* p = emb + (size_t)row*Dn;
    for (int k=lane;k<Dn;k+=32){ float x=p[k]; ss += x*x; }
    #pragma unroll
    for (int o=16;o;o>>=1) ss += __shfl_xor_sync(0xffffffffu, ss, o);
    if (lane==0) g_inorm[row] = 1.f / fmaxf(sqrtf(ss), 1e-12f);
}

// ---------------- K2: h_v = l2norm(emb[iid]) ----------------
__global__ void k_hv(const float* __restrict__ emb, const int* __restrict__ iid){
    int i = blockIdx.x*blockDim.x + threadIdx.x;
    int n = i>>8, k = i&255;
    int id = iid[n];
    g_hv[i] = emb[(size_t)id*Dn + k] * g_inorm[id];
}

// ---------------- K3: fused gather GAT ----------------
__global__ void __launch_bounds__(256) k_gat(const int* __restrict__ src, const int* __restrict__ dis,
                      const float* __restrict__ dis_emb,
                      const float* __restrict__ pi_w, const float* __restrict__ M_w){
    __shared__ float hd[Dn];
    __shared__ float se[DEGMAX];
    __shared__ int   ssrc[DEGMAX];
    int d = blockIdx.x;
    int t = threadIdx.x;
    int beg = g_off[d], end = g_off[d+1];
    int deg = end - beg; if (deg > DEGMAX) deg = DEGMAX;
    if (deg == 0){
        g_h[(size_t)d*Dn + t] = 0.f;
        return;
    }
    hd[t] = g_hv[(size_t)d*Dn + t];
    __syncthreads();
    int warp = t>>5, lane = t&31;
    for (int slot=warp; slot<deg; slot+=8){
        int e = g_eidx[beg+slot];
        int s = src[e], di = dis[e];
        const float* hs = g_hv + (size_t)s*Dn;
        const float* he = dis_emb + (size_t)di*Dn;
        float e1 = 0.f, g = 0.f;
        for (int k=lane;k<Dn;k+=32){
            float a = hs[k], b = hd[k], c = he[k];
            float p = a*b;
            e1 += p*c*pi_w[k];
            g  += p*M_w[k] + c*M_w[Dn+k];
        }
        #pragma unroll
        for (int o=16;o;o>>=1){
            e1 += __shfl_xor_sync(0xffffffffu, e1, o);
            g  += __shfl_xor_sync(0xffffffffu, g,  o);
        }
        if (lane==0){
            se[slot] = e1 * (1.f/(1.f+__expf(-g)));
            ssrc[slot] = s;
        }
    }
    __syncthreads();
    float mx = -3.4e38f;
    for (int i=0;i<deg;i++) mx = fmaxf(mx, se[i]);
    float acc = 0.f, asum = 0.f;
    for (int i=0;i<deg;i++){
        float a = __expf(se[i]-mx);
        asum += a;
        acc += a * g_hv[(size_t)ssrc[i]*Dn + t];
    }
    g_h[(size_t)d*Dn + t] = acc / asum;
}

// ---------------- K6: f = concat(h_t, last_feat) @ r_w ----------------
__global__ void k_f(const int* __restrict__ tid_, const int* __restrict__ last_idx,
                    const float* __restrict__ target_emb, const float* __restrict__ r_w){
    __shared__ float sin_[8][2*Dn];
    int b0 = blockIdx.x*8;
    int t = threadIdx.x;
    for (int idx=t; idx<8*2*Dn; idx+=256){
        int j = idx>>9, k = idx&511;
        int b = b0+j;
        float v = (k<Dn) ? target_emb[(size_t)tid_[b]*Dn + k]
                         : g_h[(size_t)last_idx[b]*Dn + (k-Dn)];
        sin_[j][k] = v;
    }
    __syncthreads();
    float acc[8] = {0,0,0,0,0,0,0,0};
    int d = t;
    for (int k=0;k<2*Dn;k++){
        float w = r_w[(size_t)k*Dn + d];
        #pragma unroll
        for (int j=0;j<8;j++) acc[j] += sin_[j][k]*w;
    }
    #pragma unroll
    for (int j=0;j<8;j++) g_f[(size_t)(b0+j)*Dn + d] = acc[j];
}

// ---------------- K7: eagg + m-scalar ----------------
__global__ void __launch_bounds__(256) k_eagg(const int* __restrict__ pid, const int* __restrict__ agg_dst,
                        const float* __restrict__ pos_emb, const float* __restrict__ q_w){
    __shared__ __align__(16) float sT[2*Dn][20];
    __shared__ int s_pid[16], s_sess[16];
    __shared__ float sred[8][16];
    int j0 = blockIdx.x*16;
    int t = threadIdx.x;
    if (t<16){ s_pid[t] = pid[j0+t]; s_sess[t] = agg_dst[j0+t]; }
    __syncthreads();
    for (int idx=t; idx<16*2*Dn; idx+=256){
        int j = idx>>9, k = idx&511;
        float v = (k<Dn) ? g_h[(size_t)(j0+j)*Dn + k]
                         : pos_emb[(size_t)s_pid[j]*Dn + (k-Dn)];
        sT[k][j] = v;
    }
    __syncthreads();

    unsigned long long acc[8];
    #pragma unroll
    for (int p=0;p<8;p++) acc[p]=0ull;
    int d = t;
    #pragma unroll 4
    for (int k=0;k<2*Dn;k++){
        float w = q_w[(size_t)k*Dn + d];
        unsigned long long wd = fpack(w,w);
        const ulonglong2* sp = (const ulonglong2*)&sT[k][0];
        #pragma unroll
        for (int q=0;q<4;q++){
            ulonglong2 pr = sp[q];
            acc[2*q+0] = ffma2(pr.x, wd, acc[2*q+0]);
            acc[2*q+1] = ffma2(pr.y, wd, acc[2*q+1]);
        }
    }
    float partial[16];
    #pragma unroll
    for (int p=0;p<8;p++){
        float t0 = tanhf(f2lo(acc[p]));
        float t1 = tanhf(f2hi(acc[p]));
        int j = 2*p;
        partial[j]   = t0 * g_f[(size_t)s_sess[j]*Dn + d];
        partial[j+1] = t1 * g_f[(size_t)s_sess[j+1]*Dn + d];
    }
    int w = t>>5, lane = t&31;
    #pragma unroll
    for (int j=0;j<16;j++){
        float p = partial[j];
        #pragma unroll
        for (int o=16;o;o>>=1) p += __shfl_xor_sync(0xffffffffu, p, o);
        if (lane==0) sred[w][j] = p;
    }
    __syncthreads();
    if (t<16){
        float s=0.f;
        #pragma unroll
        for (int ww=0;ww<8;ww++) s += sred[ww][t];
        g_mscal[j0+t] = s;
    }
}

// ---------------- K8: sr per session + l2norm ----------------
__global__ void k_sr(){
    __shared__ float sm[Sn];
    __shared__ float sred[8];
    int b = blockIdx.x, t = threadIdx.x;
    if (t<Sn) sm[t] = g_mscal[b*Sn + t];
    __syncthreads();
    float acc = 0.f;
    #pragma unroll
    for (int s=0;s<Sn;s++) acc += g_h[(size_t)(b*Sn+s)*Dn + t]*sm[s];
    float ss = acc*acc;
    #pragma unroll
    for (int o=16;o;o>>=1) ss += __shfl_xor_sync(0xffffffffu, ss, o);
    if ((t&31)==0) sred[t>>5] = ss;
    __syncthreads();
    float tot = 0.f;
    #pragma unroll
    for (int w=0;w<8;w++) tot += sred[w];
    g_srn[(size_t)b*Dn + t] = acc / fmaxf(sqrtf(tot), 1e-12f);
}

// ---------------- K9: phi head ----------------
__global__ void k_phi(const float* __restrict__ sc1_w, const float* __restrict__ sc1_b,
                      const float* __restrict__ sc2_w){
    __shared__ float ssr[8][Dn];
    __shared__ float s_p[8][2];
    int b0 = blockIdx.x*8;
    int t = threadIdx.x;
    for (int idx=t; idx<8*Dn; idx+=256){
        int j = idx>>8, k = idx&255;
        ssr[j][k] = g_srn[(size_t)(b0+j)*Dn + k];
    }
    if (t<16) s_p[t>>1][t&1] = 0.f;
    __syncthreads();
    float acc[8] = {0,0,0,0,0,0,0,0};
    int d = t;
    for (int k=0;k<Dn;k++){
        float w = sc1_w[(size_t)k*Dn + d];
        #pragma unroll
        for (int j=0;j<8;j++) acc[j] += ssr[j][k]*w;
    }
    float bb = sc1_b[d], w0 = sc2_w[d*2], w1 = sc2_w[d*2+1];
    int lane = t&31;
    #pragma unroll
    for (int j=0;j<8;j++){
        float hid = fmaxf(acc[j]+bb, 0.f);
        float p0 = hid*w0, p1 = hid*w1;
        #pragma unroll
        for (int o=16;o;o>>=1){
            p0 += __shfl_xor_sync(0xffffffffu, p0, o);
            p1 += __shfl_xor_sync(0xffffffffu, p1, o);
        }
        if (lane==0){ atomicAdd(&s_p[j][0], p0); atomicAdd(&s_p[j][1], p1); }
    }
    __syncthreads();
    if (t<8){
        float a0 = s_p[t][0], a1 = s_p[t][1];
        float m = fmaxf(a0,a1);
        float lse = m + logf(__expf(a0-m)+__expf(a1-m));
        g_logphi[(b0+t)*2+0] = a0 - lse;
        g_logphi[(b0+t)*2+1] = a1 - lse;
    }
}

// ---------------- K10: masked (in-session) logits + msum ----------------
__global__ void k_masked(const int* __restrict__ iid, const float* __restrict__ emb){
    __shared__ int iids[Sn];
    __shared__ float s_sr[Dn];
    int b = blockIdx.x, t = threadIdx.x;
    if (t<Sn) iids[t] = iid[b*Sn+t];
    if (t<Dn) s_sr[t] = g_srn[(size_t)b*Dn + t];
    __syncthreads();
    int warp = t>>5, lane = t&31;
    for (int slot=warp; slot<Sn; slot+=8){
        int v = iids[slot];
        bool dup = false;
        for (int j=0;j<slot;j++) if (iids[j]==v) { dup=true; break; }
        if (dup){
            if (lane==0) g_mask_v[b*Sn+slot] = -1;
            continue;
        }
        const float* ev = emb + (size_t)v*Dn;
        float dot = 0.f;
        for (int k=lane;k<Dn;k+=32) dot += s_sr[k]*ev[k];
        #pragma unroll
        for (int o=16;o;o>>=1) dot += __shfl_xor_sync(0xffffffffu, dot, o);
        if (lane==0){
            float l = dot * g_inorm[v] * 12.f;
            g_mask_v[b*Sn+slot] = v;
            g_mask_l[b*Sn+slot] = l;
            atomicAdd(&g_msum[b], (double)__expf(l-12.f));
        }
    }
}

// ---------------- K11: smem-free mma.sync tf32 GEMM (2-MMA split, packed operands) ----------------
// CTA 128M x 128N, 8 warps (4x2), warp tile 32x64. A = hi+lo from g_ahi/g_alo, B = g_bh (tf32).
__global__ void __launch_bounds__(256) k_gemm_mma(float* __restrict__ out){
    int tid = threadIdx.x;
    int w = tid>>5, lane = tid&31;
    int g = lane>>2, t = lane&3;
    int wm = w>>1, wn = w&1;
    int m0 = blockIdx.x*128;       // 0..3
    int v0 = blockIdx.y*128;       // 0..781

    int ar0 = m0 + wm*32 + g;      // A rows: ar0 + mi*16 + rp*8
    int nbase = v0 + wn*64 + g;    // B rows: nbase + ni*8

    // per-ni row validity + pointers (uniform across kc)
    const float2* bptr[8];
    bool bok[8];
    #pragma unroll
    for (int ni=0;ni<8;ni++){
        int nb = nbase + ni*8;
        bok[ni] = (nb < Vn);
        bptr[ni] = g_bh + (size_t)(bok[ni]?nb:0)*128 + t;
    }
    const float2* ahp[2][2];
    const float2* alp[2][2];
    #pragma unroll
    for (int mi=0;mi<2;mi++)
        #pragma unroll
        for (int rp=0;rp<2;rp++){
            int row = ar0 + mi*16 + rp*8;
            ahp[mi][rp] = g_ahi + row*128 + t;
            alp[mi][rp] = g_alo + row*128 + t;
        }

    float acc[2][8][4];
    #pragma unroll
    for (int mi=0;mi<2;mi++)
        #pragma unroll
        for (int ni=0;ni<8;ni++)
            #pragma unroll
            for (int q=0;q<4;q++) acc[mi][ni][q]=0.f;

    #pragma unroll 2
    for (int kc=0; kc<16; kc++){
        int sb = kc*8;
        #pragma unroll
        for (int k8=0; k8<2; k8++){
            int so = sb + k8*4;
            unsigned Ahi[2][4], Alo[2][4];
            #pragma unroll
            for (int mi=0;mi<2;mi++){
                float2 h0 = __ldg(ahp[mi][0] + so);
                float2 h1 = __ldg(ahp[mi][1] + so);
                float2 l0 = __ldg(alp[mi][0] + so);
                float2 l1 = __ldg(alp[mi][1] + so);
                Ahi[mi][0]=__float_as_uint(h0.x); Ahi[mi][1]=__float_as_uint(h1.x);
                Ahi[mi][2]=__float_as_uint(h0.y); Ahi[mi][3]=__float_as_uint(h1.y);
                Alo[mi][0]=__float_as_uint(l0.x); Alo[mi][1]=__float_as_uint(l1.x);
                Alo[mi][2]=__float_as_uint(l0.y); Alo[mi][3]=__float_as_uint(l1.y);
            }
            #pragma unroll
            for (int ni=0;ni<8;ni++){
                float2 b = bok[ni] ? __ldg(bptr[ni] + so) : make_float2(0.f,0.f);
                unsigned b0=__float_as_uint(b.x), b1=__float_as_uint(b.y);
                #pragma unroll
                for (int mi=0;mi<2;mi++){
                    MMA_TF32(acc[mi][ni], Ahi[mi], b0, b1);
                    MMA_TF32(acc[mi][ni], Alo[mi], b0, b1);
                }
            }
        }
    }

    // epilogue: scale by 12*inorm, store, accumulate exp row sums
    float rsum[4] = {0.f,0.f,0.f,0.f};
    #pragma unroll
    for (int mi=0;mi<2;mi++){
        int r0 = m0 + wm*32 + mi*16 + g;
        #pragma unroll
        for (int ni=0;ni<8;ni++){
            int col = v0 + wn*64 + ni*8 + 2*t;
            if (col < Vn){
                float s0 = 12.f*g_inorm[col], s1 = 12.f*g_inorm[col+1];
                float v00 = acc[mi][ni][0]*s0, v01 = acc[mi][ni][1]*s1;
                float v10 = acc[mi][ni][2]*s0, v11 = acc[mi][ni][3]*s1;
                float2* p0 = (float2*)(out + (size_t)r0*Vn + col);
                float2* p1 = (float2*)(out + (size_t)(r0+8)*Vn + col);
                __stcs(p0, make_float2(v00, v01));
                __stcs(p1, make_float2(v10, v11));
                rsum[mi*2+0] += __expf(v00-12.f) + __expf(v01-12.f);
                rsum[mi*2+1] += __expf(v10-12.f) + __expf(v11-12.f);
            }
        }
    }
    #pragma unroll
    for (int o=1;o<4;o<<=1)
        #pragma unroll
        for (int j=0;j<4;j++) rsum[j] += __shfl_xor_sync(0xffffffffu, rsum[j], o);
    if (t==0){
        #pragma unroll
        for (int j=0;j<4;j++){
            int row = m0 + wm*32 + (j>>1)*16 + (j&1)*8 + g;
            atomicAdd(&g_rowsum[row], (double)rsum[j]);
        }
    }
}

// ---------------- K12: per-row shift for unmasked entries ----------------
__global__ void k_finalize(float* __restrict__ out){
    __shared__ float s_shift;
    int row = blockIdx.y;
    if (threadIdx.x==0){
        double sex = g_rowsum[row] - g_msum[row];
        s_shift = g_logphi[row*2+1] - (float)(12.0 + log(sex));
    }
    __syncthreads();
    float sh = s_shift;
    int i = blockIdx.x*blockDim.x + threadIdx.x;
    if (i < Vn/4){
        float4* p = (float4*)(out + (size_t)row*Vn) + i;
        float4 o = __ldcs(p);
        o.x += sh; o.y += sh; o.z += sh; o.w += sh;
        __stcs(p, o);
    }
}

// ---------------- K13: overwrite masked entries ----------------
__global__ void k_fixup(float* __restrict__ out){
    int b = blockIdx.x, s = threadIdx.x;
    if (s >= Sn) return;
    int v = g_mask_v[b*Sn+s];
    if (v < 0) return;
    float lse_in = (float)(12.0 + log(g_msum[b]));
    out[(size_t)b*Vn + v] = g_mask_l[b*Sn+s] - lse_in + g_logphi[b*2+0];
}

// ---------------- launch ----------------
extern "C" void kernel_launch(void* const* d_in, const int* in_sizes, int n_in,
                              void* d_out, int out_size){
    const int* iid      = (const int*)d_in[0];
    const int* src      = (const int*)d_in[1];
    const int* dst      = (const int*)d_in[2];
    const int* dis      = (const int*)d_in[3];
    const int* pid      = (const int*)d_in[4];
    const int* agg_dst  = (const int*)d_in[6];
    const int* tid_     = (const int*)d_in[7];
    const int* last_idx = (const int*)d_in[8];
    const float* emb        = (const float*)d_in[9];
    const float* pos_emb    = (const float*)d_in[10];
    const float* dis_emb    = (const float*)d_in[11];
    const float* target_emb = (const float*)d_in[12];
    const float* pi_w  = (const float*)d_in[13];
    const float* M_w   = (const float*)d_in[14];
    const float* q_w   = (const float*)d_in[15];
    const float* r_w   = (const float*)d_in[16];
    const float* sc1_w = (const float*)d_in[17];
    const float* sc1_b = (const float*)d_in[18];
    const float* sc2_w = (const float*)d_in[19];
    float* out = (float*)d_out;

    k_zero<<<(Nn+255)/256,256>>>();                      // 1
    k_count<<<En/256,256>>>(dst);                        // 2
    k_scan<<<1,1024>>>();                                // 3
    k_bpack<<<(int)(((long long)Vn*128+255)/256),256>>>(emb);  // 4 (profiled slot)
    k_scatter<<<En/256,256>>>(dst);                      // 5
    k_inorm<<<Vn/8,256>>>(emb);                          // 6
    k_hv<<<(Nn*Dn)/256,256>>>(emb, iid);                 // 7
    k_gat<<<Nn,256>>>(src,dis,dis_emb,pi_w,M_w);         // 8
    k_f<<<Bn/8,256>>>(tid_,last_idx,target_emb,r_w);
    k_eagg<<<Nn/16,256>>>(pid,agg_dst,pos_emb,q_w);
    k_sr<<<Bn,256>>>();
    k_apack<<<Bn*128/256,256>>>();
    k_phi<<<Bn/8,256>>>(sc1_w,sc1_b,sc2_w);
    k_masked<<<Bn,256>>>(iid, emb);
    dim3 gg(4, (Vn+127)/128);
    k_gemm_mma<<<gg, 256>>>(out);
    dim3 gf((Vn/4 + 255)/256, Bn);
    k_finalize<<<gf,256>>>(out);
    k_fixup<<<Bn,32>>>(out);
}

// round 7
// speedup vs baseline: 1.3917x; 1.1775x over previous
#include <cuda_runtime.h>
#include <cuda_bf16.h>
#include <math.h>
#include <stdint.h>

#define Vn 100000
#define Dn 256
#define Bn 512
#define Sn 20
#define Nn (Bn*Sn)      // 10240
#define En (8*Nn)       // 81920
#define DEGMAX 128

// ---------------- scratch (device globals; no allocation allowed) ----------------
__device__ float g_inorm[Vn];
__device__ float g_hv[Nn*Dn];
__device__ float g_h[Nn*Dn];
__device__ float g_f[Bn*Dn];
__device__ float g_mscal[Nn];
__device__ float g_srn[Bn*Dn];
__device__ float g_logphi[Bn*2];
__device__ double g_rowsum[Bn];
__device__ double g_msum[Bn];
__device__ int   g_mask_v[Bn*Sn];
__device__ float g_mask_l[Bn*Sn];
// CSR
__device__ int g_deg[Nn];
__device__ int g_off[Nn+1];
__device__ int g_pos[Nn];
__device__ int g_eidx[En];
// packed GEMM operands: per row, 64 slots; slot s = c*4+t (chunk c of K=16, quad-thread t)
// uint4 = { bf16x2(k0,k0+1)_hi, bf16x2(k0+8,k0+9)_hi, bf16x2(k0,k0+1)_lo, bf16x2(k0+8,k0+9)_lo }
// where k0 = c*16 + 2t
__device__ uint4 g_bp[(size_t)Vn*64];   // 102.4 MB
__device__ uint4 g_ap[Bn*64];           // 0.5 MB

// ---------------- helpers ----------------
__device__ __forceinline__ unsigned long long ffma2(unsigned long long a, unsigned long long b, unsigned long long c){
    unsigned long long d;
    asm("fma.rn.f32x2 %0, %1, %2, %3;" : "=l"(d) : "l"(a), "l"(b), "l"(c));
    return d;
}
__device__ __forceinline__ float f2lo(unsigned long long u){ return __int_as_float((int)(unsigned)(u & 0xFFFFFFFFull)); }
__device__ __forceinline__ float f2hi(unsigned long long u){ return __int_as_float((int)(unsigned)(u >> 32)); }
__device__ __forceinline__ unsigned long long fpack(float lo, float hi){
    unsigned long long u;
    asm("mov.b64 %0, {%1, %2};" : "=l"(u) : "r"(__float_as_int(lo)), "r"(__float_as_int(hi)));
    return u;
}

// bf16 helpers
__device__ __forceinline__ unsigned short bfr(float x){   // raw bf16 bits, RN
    __nv_bfloat16 h = __float2bfloat16(x);
    return *(unsigned short*)&h;
}
__device__ __forceinline__ float bff(unsigned short u){
    __nv_bfloat16 h = *(__nv_bfloat16*)&u;
    return __bfloat162float(h);
}

// mma.sync m16n8k16 bf16: D = A*B + D
#define MMA_BF16(d, a0, a1, a2, a3, b0, b1) \
    asm volatile("mma.sync.aligned.m16n8k16.row.col.f32.bf16.bf16.f32 " \
        "{%0,%1,%2,%3}, {%4,%5,%6,%7}, {%8,%9}, {%0,%1,%2,%3};" \
        : "+f"((d)[0]), "+f"((d)[1]), "+f"((d)[2]), "+f"((d)[3]) \
        : "r"(a0), "r"(a1), "r"(a2), "r"(a3), "r"(b0), "r"(b1))

// ---------------- K0: zero scratch ----------------
__global__ void k_zero(){
    int i = blockIdx.x*blockDim.x + threadIdx.x;
    if (i < Nn) g_deg[i] = 0;
    if (i < Bn){ g_rowsum[i]=0.0; g_msum[i]=0.0; }
}

// ---------------- CSR build ----------------
__global__ void k_count(const int* __restrict__ dst){
    int e = blockIdx.x*blockDim.x + threadIdx.x;
    if (e < En) atomicAdd(&g_deg[dst[e]], 1);
}
__global__ void k_scan(){        // 1 block, 1024 threads, 10 elems/thread
    __shared__ int warp_sums[32];
    int t = threadIdx.x;
    int base = t*10;
    int local[10]; int s = 0;
    #pragma unroll
    for (int i=0;i<10;i++){ local[i]=s; s += g_deg[base+i]; }
    int lane = t&31, w = t>>5;
    int v = s;
    #pragma unroll
    for (int o=1;o<32;o<<=1){ int u=__shfl_up_sync(0xffffffffu,v,o); if(lane>=o) v+=u; }
    if (lane==31) warp_sums[w]=v;
    __syncthreads();
    if (w==0){
        int x = warp_sums[lane];
        #pragma unroll
        for (int o=1;o<32;o<<=1){ int u=__shfl_up_sync(0xffffffffu,x,o); if(lane>=o) x+=u; }
        warp_sums[lane]=x;
    }
    __syncthreads();
    int excl = v - s + (w>0 ? warp_sums[w-1] : 0);
    #pragma unroll
    for (int i=0;i<10;i++){ g_off[base+i]=excl+local[i]; g_pos[base+i]=excl+local[i]; }
    if (t==1023) g_off[Nn]=En;
}
__global__ void k_scatter(const int* __restrict__ dst){
    int e = blockIdx.x*blockDim.x + threadIdx.x;
    if (e < En){
        int p = atomicAdd(&g_pos[dst[e]], 1);
        g_eidx[p] = e;
    }
}

// ---------------- pack emb into bf16 hi/lo fragment layout ----------------
__global__ void k_bpack(const float* __restrict__ emb){
    long long id = (long long)blockIdx.x*blockDim.x + threadIdx.x;
    if (id >= (long long)Vn*64) return;
    int row = (int)(id>>6), s = (int)(id&63);
    int c = s>>2, t = s&3;
    int k0 = c*16 + 2*t;
    const float* p = emb + (size_t)row*Dn;
    float v0=p[k0], v1=p[k0+1], v2=p[k0+8], v3=p[k0+9];
    unsigned short h0=bfr(v0), h1=bfr(v1), h2=bfr(v2), h3=bfr(v3);
    unsigned short l0=bfr(v0-bff(h0)), l1=bfr(v1-bff(h1)), l2=bfr(v2-bff(h2)), l3=bfr(v3-bff(h3));
    uint4 o;
    o.x = ((unsigned)h1<<16) | h0;
    o.y = ((unsigned)h3<<16) | h2;
    o.z = ((unsigned)l1<<16) | l0;
    o.w = ((unsigned)l3<<16) | l2;
    g_bp[(size_t)row*64 + s] = o;
}

// ---------------- pack srn hi/lo ----------------
__global__ void k_apack(){
    int id = blockIdx.x*blockDim.x + threadIdx.x;   // Bn*64 = 32768
    int row = id>>6, s = id&63;
    int c = s>>2, t = s&3;
    int k0 = c*16 + 2*t;
    const float* p = g_srn + (size_t)row*Dn;
    float v0=p[k0], v1=p[k0+1], v2=p[k0+8], v3=p[k0+9];
    unsigned short h0=bfr(v0), h1=bfr(v1), h2=bfr(v2), h3=bfr(v3);
    unsigned short l0=bfr(v0-bff(h0)), l1=bfr(v1-bff(h1)), l2=bfr(v2-bff(h2)), l3=bfr(v3-bff(h3));
    uint4 o;
    o.x = ((unsigned)h1<<16) | h0;
    o.y = ((unsigned)h3<<16) | h2;
    o.z = ((unsigned)l1<<16) | l0;
    o.w = ((unsigned)l3<<16) | l2;
    g_ap[row*64 + s] = o;
}

// ---------------- K1: inverse norms of emb rows ----------------
__global__ void k_inorm(const float* __restrict__ emb){
    int row = blockIdx.x*8 + (threadIdx.x>>5);
    int lane = threadIdx.x&31;
    float ss = 0.f;
    const float* p = emb + (size_t)row*Dn;
    for (int k=lane;k<Dn;k+=32){ float x=p[k]; ss += x*x; }
    #pragma unroll
    for (int o=16;o;o>>=1) ss += __shfl_xor_sync(0xffffffffu, ss, o);
    if (lane==0) g_inorm[row] = 1.f / fmaxf(sqrtf(ss), 1e-12f);
}

// ---------------- K2: h_v = l2norm(emb[iid]) ----------------
__global__ void k_hv(const float* __restrict__ emb, const int* __restrict__ iid){
    int i = blockIdx.x*blockDim.x + threadIdx.x;
    int n = i>>8, k = i&255;
    int id = iid[n];
    g_hv[i] = emb[(size_t)id*Dn + k] * g_inorm[id];
}

// ---------------- K3: fused gather GAT ----------------
__global__ void __launch_bounds__(256) k_gat(const int* __restrict__ src, const int* __restrict__ dis,
                      const float* __restrict__ dis_emb,
                      const float* __restrict__ pi_w, const float* __restrict__ M_w){
    __shared__ float hd[Dn];
    __shared__ float se[DEGMAX];
    __shared__ int   ssrc[DEGMAX];
    int d = blockIdx.x;
    int t = threadIdx.x;
    int beg = g_off[d], end = g_off[d+1];
    int deg = end - beg; if (deg > DEGMAX) deg = DEGMAX;
    if (deg == 0){
        g_h[(size_t)d*Dn + t] = 0.f;
        return;
    }
    hd[t] = g_hv[(size_t)d*Dn + t];
    __syncthreads();
    int warp = t>>5, lane = t&31;
    for (int slot=warp; slot<deg; slot+=8){
        int e = g_eidx[beg+slot];
        int s = src[e], di = dis[e];
        const float* hs = g_hv + (size_t)s*Dn;
        const float* he = dis_emb + (size_t)di*Dn;
        float e1 = 0.f, g = 0.f;
        for (int k=lane;k<Dn;k+=32){
            float a = hs[k], b = hd[k], c = he[k];
            float p = a*b;
            e1 += p*c*pi_w[k];
            g  += p*M_w[k] + c*M_w[Dn+k];
        }
        #pragma unroll
        for (int o=16;o;o>>=1){
            e1 += __shfl_xor_sync(0xffffffffu, e1, o);
            g  += __shfl_xor_sync(0xffffffffu, g,  o);
        }
        if (lane==0){
            se[slot] = e1 * (1.f/(1.f+__expf(-g)));
            ssrc[slot] = s;
        }
    }
    __syncthreads();
    float mx = -3.4e38f;
    for (int i=0;i<deg;i++) mx = fmaxf(mx, se[i]);
    float acc = 0.f, asum = 0.f;
    for (int i=0;i<deg;i++){
        float a = __expf(se[i]-mx);
        asum += a;
        acc += a * g_hv[(size_t)ssrc[i]*Dn + t];
    }
    g_h[(size_t)d*Dn + t] = acc / asum;
}

// ---------------- K6: f = concat(h_t, last_feat) @ r_w ----------------
__global__ void k_f(const int* __restrict__ tid_, const int* __restrict__ last_idx,
                    const float* __restrict__ target_emb, const float* __restrict__ r_w){
    __shared__ float sin_[8][2*Dn];
    int b0 = blockIdx.x*8;
    int t = threadIdx.x;
    for (int idx=t; idx<8*2*Dn; idx+=256){
        int j = idx>>9, k = idx&511;
        int b = b0+j;
        float v = (k<Dn) ? target_emb[(size_t)tid_[b]*Dn + k]
                         : g_h[(size_t)last_idx[b]*Dn + (k-Dn)];
        sin_[j][k] = v;
    }
    __syncthreads();
    float acc[8] = {0,0,0,0,0,0,0,0};
    int d = t;
    for (int k=0;k<2*Dn;k++){
        float w = r_w[(size_t)k*Dn + d];
        #pragma unroll
        for (int j=0;j<8;j++) acc[j] += sin_[j][k]*w;
    }
    #pragma unroll
    for (int j=0;j<8;j++) g_f[(size_t)(b0+j)*Dn + d] = acc[j];
}

// ---------------- K7: eagg + m-scalar ----------------
__global__ void __launch_bounds__(256) k_eagg(const int* __restrict__ pid, const int* __restrict__ agg_dst,
                        const float* __restrict__ pos_emb, const float* __restrict__ q_w){
    __shared__ __align__(16) float sT[2*Dn][20];
    __shared__ int s_pid[16], s_sess[16];
    __shared__ float sred[8][16];
    int j0 = blockIdx.x*16;
    int t = threadIdx.x;
    if (t<16){ s_pid[t] = pid[j0+t]; s_sess[t] = agg_dst[j0+t]; }
    __syncthreads();
    for (int idx=t; idx<16*2*Dn; idx+=256){
        int j = idx>>9, k = idx&511;
        float v = (k<Dn) ? g_h[(size_t)(j0+j)*Dn + k]
                         : pos_emb[(size_t)s_pid[j]*Dn + (k-Dn)];
        sT[k][j] = v;
    }
    __syncthreads();

    unsigned long long acc[8];
    #pragma unroll
    for (int p=0;p<8;p++) acc[p]=0ull;
    int d = t;
    #pragma unroll 4
    for (int k=0;k<2*Dn;k++){
        float w = q_w[(size_t)k*Dn + d];
        unsigned long long wd = fpack(w,w);
        const ulonglong2* sp = (const ulonglong2*)&sT[k][0];
        #pragma unroll
        for (int q=0;q<4;q++){
            ulonglong2 pr = sp[q];
            acc[2*q+0] = ffma2(pr.x, wd, acc[2*q+0]);
            acc[2*q+1] = ffma2(pr.y, wd, acc[2*q+1]);
        }
    }
    float partial[16];
    #pragma unroll
    for (int p=0;p<8;p++){
        float t0 = tanhf(f2lo(acc[p]));
        float t1 = tanhf(f2hi(acc[p]));
        int j = 2*p;
        partial[j]   = t0 * g_f[(size_t)s_sess[j]*Dn + d];
        partial[j+1] = t1 * g_f[(size_t)s_sess[j+1]*Dn + d];
    }
    int w = t>>5, lane = t&31;
    #pragma unroll
    for (int j=0;j<16;j++){
        float p = partial[j];
        #pragma unroll
        for (int o=16;o;o>>=1) p += __shfl_xor_sync(0xffffffffu, p, o);
        if (lane==0) sred[w][j] = p;
    }
    __syncthreads();
    if (t<16){
        float s=0.f;
        #pragma unroll
        for (int ww=0;ww<8;ww++) s += sred[ww][t];
        g_mscal[j0+t] = s;
    }
}

// ---------------- K8: sr per session + l2norm ----------------
__global__ void k_sr(){
    __shared__ float sm[Sn];
    __shared__ float sred[8];
    int b = blockIdx.x, t = threadIdx.x;
    if (t<Sn) sm[t] = g_mscal[b*Sn + t];
    __syncthreads();
    float acc = 0.f;
    #pragma unroll
    for (int s=0;s<Sn;s++) acc += g_h[(size_t)(b*Sn+s)*Dn + t]*sm[s];
    float ss = acc*acc;
    #pragma unroll
    for (int o=16;o;o>>=1) ss += __shfl_xor_sync(0xffffffffu, ss, o);
    if ((t&31)==0) sred[t>>5] = ss;
    __syncthreads();
    float tot = 0.f;
    #pragma unroll
    for (int w=0;w<8;w++) tot += sred[w];
    g_srn[(size_t)b*Dn + t] = acc / fmaxf(sqrtf(tot), 1e-12f);
}

// ---------------- K9: phi head ----------------
__global__ void k_phi(const float* __restrict__ sc1_w, const float* __restrict__ sc1_b,
                      const float* __restrict__ sc2_w){
    __shared__ float ssr[8][Dn];
    __shared__ float s_p[8][2];
    int b0 = blockIdx.x*8;
    int t = threadIdx.x;
    for (int idx=t; idx<8*Dn; idx+=256){
        int j = idx>>8, k = idx&255;
        ssr[j][k] = g_srn[(size_t)(b0+j)*Dn + k];
    }
    if (t<16) s_p[t>>1][t&1] = 0.f;
    __syncthreads();
    float acc[8] = {0,0,0,0,0,0,0,0};
    int d = t;
    for (int k=0;k<Dn;k++){
        float w = sc1_w[(size_t)k*Dn + d];
        #pragma unroll
        for (int j=0;j<8;j++) acc[j] += ssr[j][k]*w;
    }
    float bb = sc1_b[d], w0 = sc2_w[d*2], w1 = sc2_w[d*2+1];
    int lane = t&31;
    #pragma unroll
    for (int j=0;j<8;j++){
        float hid = fmaxf(acc[j]+bb, 0.f);
        float p0 = hid*w0, p1 = hid*w1;
        #pragma unroll
        for (int o=16;o;o>>=1){
            p0 += __shfl_xor_sync(0xffffffffu, p0, o);
            p1 += __shfl_xor_sync(0xffffffffu, p1, o);
        }
        if (lane==0){ atomicAdd(&s_p[j][0], p0); atomicAdd(&s_p[j][1], p1); }
    }
    __syncthreads();
    if (t<8){
        float a0 = s_p[t][0], a1 = s_p[t][1];
        float m = fmaxf(a0,a1);
        float lse = m + logf(__expf(a0-m)+__expf(a1-m));
        g_logphi[(b0+t)*2+0] = a0 - lse;
        g_logphi[(b0+t)*2+1] = a1 - lse;
    }
}

// ---------------- K10: masked (in-session) logits + msum ----------------
__global__ void k_masked(const int* __restrict__ iid, const float* __restrict__ emb){
    __shared__ int iids[Sn];
    __shared__ float s_sr[Dn];
    int b = blockIdx.x, t = threadIdx.x;
    if (t<Sn) iids[t] = iid[b*Sn+t];
    if (t<Dn) s_sr[t] = g_srn[(size_t)b*Dn + t];
    __syncthreads();
    int warp = t>>5, lane = t&31;
    for (int slot=warp; slot<Sn; slot+=8){
        int v = iids[slot];
        bool dup = false;
        for (int j=0;j<slot;j++) if (iids[j]==v) { dup=true; break; }
        if (dup){
            if (lane==0) g_mask_v[b*Sn+slot] = -1;
            continue;
        }
        const float* ev = emb + (size_t)v*Dn;
        float dot = 0.f;
        for (int k=lane;k<Dn;k+=32) dot += s_sr[k]*ev[k];
        #pragma unroll
        for (int o=16;o;o>>=1) dot += __shfl_xor_sync(0xffffffffu, dot, o);
        if (lane==0){
            float l = dot * g_inorm[v] * 12.f;
            g_mask_v[b*Sn+slot] = v;
            g_mask_l[b*Sn+slot] = l;
            atomicAdd(&g_msum[b], (double)__expf(l-12.f));
        }
    }
}

// ---------------- K11: smem-free mma.sync bf16 3-term GEMM ----------------
// CTA 128M x 128N, 8 warps (4x2), warp tile 32x64, K chunks of 16.
__global__ void __launch_bounds__(256,2) k_gemm_mma(float* __restrict__ out){
    int tid = threadIdx.x;
    int w = tid>>5, lane = tid&31;
    int g = lane>>2, t = lane&3;
    int wm = w>>1, wn = w&1;
    int m0 = blockIdx.x*128;       // 0..3
    int v0 = blockIdx.y*128;       // 0..781

    int ar0 = m0 + wm*32 + g;      // A rows: ar0 + mi*16 + rp*8
    int nbase = v0 + wn*64 + g;    // B rows: nbase + ni*8

    const uint4* bptr[8];
    bool bok[8];
    #pragma unroll
    for (int ni=0;ni<8;ni++){
        int nb = nbase + ni*8;
        bok[ni] = (nb < Vn);
        bptr[ni] = g_bp + (size_t)(bok[ni]?nb:0)*64 + t;
    }
    const uint4* aptr[2][2];
    #pragma unroll
    for (int mi=0;mi<2;mi++)
        #pragma unroll
        for (int rp=0;rp<2;rp++){
            int row = ar0 + mi*16 + rp*8;
            aptr[mi][rp] = g_ap + row*64 + t;
        }

    float acc[2][8][4];
    #pragma unroll
    for (int mi=0;mi<2;mi++)
        #pragma unroll
        for (int ni=0;ni<8;ni++)
            #pragma unroll
            for (int q=0;q<4;q++) acc[mi][ni][q]=0.f;

    const uint4 z4 = make_uint4(0,0,0,0);
    #pragma unroll 2
    for (int c=0; c<16; c++){
        int so = c*4;
        // A fragments: a0 = row g k-lo, a1 = row g+8 k-lo, a2 = row g k-hi, a3 = row g+8 k-hi
        uint4 A0[2], A1[2];
        #pragma unroll
        for (int mi=0;mi<2;mi++){
            A0[mi] = __ldg(aptr[mi][0] + so);   // row g
            A1[mi] = __ldg(aptr[mi][1] + so);   // row g+8
        }
        #pragma unroll
        for (int ni=0;ni<8;ni++){
            uint4 b = bok[ni] ? __ldg(bptr[ni] + so) : z4;
            #pragma unroll
            for (int mi=0;mi<2;mi++){
                // hi*hi
                MMA_BF16(acc[mi][ni], A0[mi].x, A1[mi].x, A0[mi].y, A1[mi].y, b.x, b.y);
                // hi*lo
                MMA_BF16(acc[mi][ni], A0[mi].x, A1[mi].x, A0[mi].y, A1[mi].y, b.z, b.w);
                // lo*hi
                MMA_BF16(acc[mi][ni], A0[mi].z, A1[mi].z, A0[mi].w, A1[mi].w, b.x, b.y);
            }
        }
    }

    // epilogue: scale by 12*inorm, store, accumulate exp row sums
    float rsum[4] = {0.f,0.f,0.f,0.f};
    #pragma unroll
    for (int mi=0;mi<2;mi++){
        int r0 = m0 + wm*32 + mi*16 + g;
        #pragma unroll
        for (int ni=0;ni<8;ni++){
            int col = v0 + wn*64 + ni*8 + 2*t;
            if (col < Vn){
                float s0 = 12.f*g_inorm[col], s1 = 12.f*g_inorm[col+1];
                float v00 = acc[mi][ni][0]*s0, v01 = acc[mi][ni][1]*s1;
                float v10 = acc[mi][ni][2]*s0, v11 = acc[mi][ni][3]*s1;
                float2* p0 = (float2*)(out + (size_t)r0*Vn + col);
                float2* p1 = (float2*)(out + (size_t)(r0+8)*Vn + col);
                __stcs(p0, make_float2(v00, v01));
                __stcs(p1, make_float2(v10, v11));
                rsum[mi*2+0] += __expf(v00-12.f) + __expf(v01-12.f);
                rsum[mi*2+1] += __expf(v10-12.f) + __expf(v11-12.f);
            }
        }
    }
    #pragma unroll
    for (int o=1;o<4;o<<=1)
        #pragma unroll
        for (int j=0;j<4;j++) rsum[j] += __shfl_xor_sync(0xffffffffu, rsum[j], o);
    if (t==0){
        #pragma unroll
        for (int j=0;j<4;j++){
            int row = m0 + wm*32 + (j>>1)*16 + (j&1)*8 + g;
            atomicAdd(&g_rowsum[row], (double)rsum[j]);
        }
    }
}

// ---------------- K12: per-row shift for unmasked entries ----------------
__global__ void k_finalize(float* __restrict__ out){
    __shared__ float s_shift;
    int row = blockIdx.y;
    if (threadIdx.x==0){
        double sex = g_rowsum[row] - g_msum[row];
        s_shift = g_logphi[row*2+1] - (float)(12.0 + log(sex));
    }
    __syncthreads();
    float sh = s_shift;
    int i = blockIdx.x*blockDim.x + threadIdx.x;
    if (i < Vn/4){
        float4* p = (float4*)(out + (size_t)row*Vn) + i;
        float4 o = __ldcs(p);
        o.x += sh; o.y += sh; o.z += sh; o.w += sh;
        __stcs(p, o);
    }
}

// ---------------- K13: overwrite masked entries ----------------
__global__ void k_fixup(float* __restrict__ out){
    int b = blockIdx.x, s = threadIdx.x;
    if (s >= Sn) return;
    int v = g_mask_v[b*Sn+s];
    if (v < 0) return;
    float lse_in = (float)(12.0 + log(g_msum[b]));
    out[(size_t)b*Vn + v] = g_mask_l[b*Sn+s] - lse_in + g_logphi[b*2+0];
}

// ---------------- launch ----------------
extern "C" void kernel_launch(void* const* d_in, const int* in_sizes, int n_in,
                              void* d_out, int out_size){
    const int* iid      = (const int*)d_in[0];
    const int* src      = (const int*)d_in[1];
    const int* dst      = (const int*)d_in[2];
    const int* dis      = (const int*)d_in[3];
    const int* pid      = (const int*)d_in[4];
    const int* agg_dst  = (const int*)d_in[6];
    const int* tid_     = (const int*)d_in[7];
    const int* last_idx = (const int*)d_in[8];
    const float* emb        = (const float*)d_in[9];
    const float* pos_emb    = (const float*)d_in[10];
    const float* dis_emb    = (const float*)d_in[11];
    const float* target_emb = (const float*)d_in[12];
    const float* pi_w  = (const float*)d_in[13];
    const float* M_w   = (const float*)d_in[14];
    const float* q_w   = (const float*)d_in[15];
    const float* r_w   = (const float*)d_in[16];
    const float* sc1_w = (const float*)d_in[17];
    const float* sc1_b = (const float*)d_in[18];
    const float* sc2_w = (const float*)d_in[19];
    float* out = (float*)d_out;

    k_zero<<<(Nn+255)/256,256>>>();                      // 1
    k_count<<<En/256,256>>>(dst);                        // 2
    k_scan<<<1,1024>>>();                                // 3
    k_bpack<<<(int)(((long long)Vn*64+255)/256),256>>>(emb);  // 4 (profiled slot)
    k_scatter<<<En/256,256>>>(dst);                      // 5
    k_inorm<<<Vn/8,256>>>(emb);                          // 6
    k_hv<<<(Nn*Dn)/256,256>>>(emb, iid);                 // 7
    k_gat<<<Nn,256>>>(src,dis,dis_emb,pi_w,M_w);         // 8
    k_f<<<Bn/8,256>>>(tid_,last_idx,target_emb,r_w);
    k_eagg<<<Nn/16,256>>>(pid,agg_dst,pos_emb,q_w);
    k_sr<<<Bn,256>>>();
    k_apack<<<Bn*64/256,256>>>();
    k_phi<<<Bn/8,256>>>(sc1_w,sc1_b,sc2_w);
    k_masked<<<Bn,256>>>(iid, emb);
    dim3 gg(4, (Vn+127)/128);
    k_gemm_mma<<<gg, 256>>>(out);
    dim3 gf((Vn/4 + 255)/256, Bn);
    k_finalize<<<gf,256>>>(out);
    k_fixup<<<Bn,32>>>(out);
}

// round 8
// speedup vs baseline: 1.6737x; 1.2026x over previous
#include <cuda_runtime.h>
#include <cuda_bf16.h>
#include <cuda_fp16.h>
#include <math.h>
#include <stdint.h>

#define Vn 100000
#define Dn 256
#define Bn 512
#define Sn 20
#define Nn (Bn*Sn)      // 10240
#define En (8*Nn)       // 81920
#define DEGMAX 128

// ---------------- scratch (device globals; no allocation allowed) ----------------
__device__ float g_inorm[Vn];
__device__ float g_hv[Nn*Dn];
__device__ float g_h[Nn*Dn];
__device__ float g_f[Bn*Dn];
__device__ float g_mscal[Nn];
__device__ float g_srn[Bn*Dn];
__device__ float g_logphi[Bn*2];
__device__ double g_rowsum[Bn];
__device__ double g_msum[Bn];
__device__ int   g_mask_v[Bn*Sn];
__device__ float g_mask_l[Bn*Sn];
// CSR
__device__ int g_deg[Nn];
__device__ int g_off[Nn+1];
__device__ int g_pos[Nn];
__device__ int g_eidx[En];
// packed GEMM operands: per row, 64 slots; slot s = c*4+t (chunk c of K=16, quad-thread t), k0 = c*16+2t
// B: uint2 = { f16x2(k0,k0+1), f16x2(k0+8,k0+9) }            (single-term fp16)
// A: uint4 = { hi(k0,k0+1), hi(k0+8,k0+9), lo(k0,k0+1), lo(k0+8,k0+9) }   (fp16 hi/lo split)
__device__ uint2 g_bp[(size_t)Vn*64];   // 51.2 MB
__device__ uint4 g_ap[Bn*64];           // 0.5 MB

// ---------------- helpers ----------------
__device__ __forceinline__ unsigned long long ffma2(unsigned long long a, unsigned long long b, unsigned long long c){
    unsigned long long d;
    asm("fma.rn.f32x2 %0, %1, %2, %3;" : "=l"(d) : "l"(a), "l"(b), "l"(c));
    return d;
}
__device__ __forceinline__ float f2lo(unsigned long long u){ return __int_as_float((int)(unsigned)(u & 0xFFFFFFFFull)); }
__device__ __forceinline__ float f2hi(unsigned long long u){ return __int_as_float((int)(unsigned)(u >> 32)); }
__device__ __forceinline__ unsigned long long fpack(float lo, float hi){
    unsigned long long u;
    asm("mov.b64 %0, {%1, %2};" : "=l"(u) : "r"(__float_as_int(lo)), "r"(__float_as_int(hi)));
    return u;
}

// fp16 helpers
__device__ __forceinline__ unsigned short hfr(float x){
    __half h = __float2half_rn(x);
    return *(unsigned short*)&h;
}
__device__ __forceinline__ float hff(unsigned short u){
    __half h = *(__half*)&u;
    return __half2float(h);
}

// mma.sync m16n8k16 f16: D = A*B + D (fp32 accum)
#define MMA_F16(d, a0, a1, a2, a3, b0, b1) \
    asm volatile("mma.sync.aligned.m16n8k16.row.col.f32.f16.f16.f32 " \
        "{%0,%1,%2,%3}, {%4,%5,%6,%7}, {%8,%9}, {%0,%1,%2,%3};" \
        : "+f"((d)[0]), "+f"((d)[1]), "+f"((d)[2]), "+f"((d)[3]) \
        : "r"(a0), "r"(a1), "r"(a2), "r"(a3), "r"(b0), "r"(b1))

// ---------------- K0: zero scratch ----------------
__global__ void k_zero(){
    int i = blockIdx.x*blockDim.x + threadIdx.x;
    if (i < Nn) g_deg[i] = 0;
    if (i < Bn){ g_rowsum[i]=0.0; g_msum[i]=0.0; }
}

// ---------------- CSR build ----------------
__global__ void k_count(const int* __restrict__ dst){
    int e = blockIdx.x*blockDim.x + threadIdx.x;
    if (e < En) atomicAdd(&g_deg[dst[e]], 1);
}
__global__ void k_scan(){        // 1 block, 1024 threads, 10 elems/thread
    __shared__ int warp_sums[32];
    int t = threadIdx.x;
    int base = t*10;
    int local[10]; int s = 0;
    #pragma unroll
    for (int i=0;i<10;i++){ local[i]=s; s += g_deg[base+i]; }
    int lane = t&31, w = t>>5;
    int v = s;
    #pragma unroll
    for (int o=1;o<32;o<<=1){ int u=__shfl_up_sync(0xffffffffu,v,o); if(lane>=o) v+=u; }
    if (lane==31) warp_sums[w]=v;
    __syncthreads();
    if (w==0){
        int x = warp_sums[lane];
        #pragma unroll
        for (int o=1;o<32;o<<=1){ int u=__shfl_up_sync(0xffffffffu,x,o); if(lane>=o) x+=u; }
        warp_sums[lane]=x;
    }
    __syncthreads();
    int excl = v - s + (w>0 ? warp_sums[w-1] : 0);
    #pragma unroll
    for (int i=0;i<10;i++){ g_off[base+i]=excl+local[i]; g_pos[base+i]=excl+local[i]; }
    if (t==1023) g_off[Nn]=En;
}
__global__ void k_scatter(const int* __restrict__ dst){
    int e = blockIdx.x*blockDim.x + threadIdx.x;
    if (e < En){
        int p = atomicAdd(&g_pos[dst[e]], 1);
        g_eidx[p] = e;
    }
}

// ---------------- pack emb into fp16 fragment layout ----------------
__global__ void k_bpack(const float* __restrict__ emb){
    long long id = (long long)blockIdx.x*blockDim.x + threadIdx.x;
    if (id >= (long long)Vn*64) return;
    int row = (int)(id>>6), s = (int)(id&63);
    int c = s>>2, t = s&3;
    int k0 = c*16 + 2*t;
    const float* p = emb + (size_t)row*Dn;
    unsigned short h0=hfr(p[k0]), h1=hfr(p[k0+1]), h2=hfr(p[k0+8]), h3=hfr(p[k0+9]);
    uint2 o;
    o.x = ((unsigned)h1<<16) | h0;
    o.y = ((unsigned)h3<<16) | h2;
    g_bp[(size_t)row*64 + s] = o;
}

// ---------------- pack srn fp16 hi/lo ----------------
__global__ void k_apack(){
    int id = blockIdx.x*blockDim.x + threadIdx.x;   // Bn*64 = 32768
    int row = id>>6, s = id&63;
    int c = s>>2, t = s&3;
    int k0 = c*16 + 2*t;
    const float* p = g_srn + (size_t)row*Dn;
    float v0=p[k0], v1=p[k0+1], v2=p[k0+8], v3=p[k0+9];
    unsigned short h0=hfr(v0), h1=hfr(v1), h2=hfr(v2), h3=hfr(v3);
    unsigned short l0=hfr(v0-hff(h0)), l1=hfr(v1-hff(h1)), l2=hfr(v2-hff(h2)), l3=hfr(v3-hff(h3));
    uint4 o;
    o.x = ((unsigned)h1<<16) | h0;
    o.y = ((unsigned)h3<<16) | h2;
    o.z = ((unsigned)l1<<16) | l0;
    o.w = ((unsigned)l3<<16) | l2;
    g_ap[row*64 + s] = o;
}

// ---------------- K1: inverse norms of emb rows ----------------
__global__ void k_inorm(const float* __restrict__ emb){
    int row = blockIdx.x*8 + (threadIdx.x>>5);
    int lane = threadIdx.x&31;
    float ss = 0.f;
    const float* p = emb + (size_t)row*Dn;
    for (int k=lane;k<Dn;k+=32){ float x=p[k]; ss += x*x; }
    #pragma unroll
    for (int o=16;o;o>>=1) ss += __shfl_xor_sync(0xffffffffu, ss, o);
    if (lane==0) g_inorm[row] = 1.f / fmaxf(sqrtf(ss), 1e-12f);
}

// ---------------- K2: h_v = l2norm(emb[iid]) ----------------
__global__ void k_hv(const float* __restrict__ emb, const int* __restrict__ iid){
    int i = blockIdx.x*blockDim.x + threadIdx.x;
    int n = i>>8, k = i&255;
    int id = iid[n];
    g_hv[i] = emb[(size_t)id*Dn + k] * g_inorm[id];
}

// ---------------- K3: fused gather GAT ----------------
__global__ void __launch_bounds__(256) k_gat(const int* __restrict__ src, const int* __restrict__ dis,
                      const float* __restrict__ dis_emb,
                      const float* __restrict__ pi_w, const float* __restrict__ M_w){
    __shared__ float hd[Dn];
    __shared__ float se[DEGMAX];
    __shared__ int   ssrc[DEGMAX];
    int d = blockIdx.x;
    int t = threadIdx.x;
    int beg = g_off[d], end = g_off[d+1];
    int deg = end - beg; if (deg > DEGMAX) deg = DEGMAX;
    if (deg == 0){
        g_h[(size_t)d*Dn + t] = 0.f;
        return;
    }
    hd[t] = g_hv[(size_t)d*Dn + t];
    __syncthreads();
    int warp = t>>5, lane = t&31;
    for (int slot=warp; slot<deg; slot+=8){
        int e = g_eidx[beg+slot];
        int s = src[e], di = dis[e];
        const float* hs = g_hv + (size_t)s*Dn;
        const float* he = dis_emb + (size_t)di*Dn;
        float e1 = 0.f, g = 0.f;
        for (int k=lane;k<Dn;k+=32){
            float a = hs[k], b = hd[k], c = he[k];
            float p = a*b;
            e1 += p*c*pi_w[k];
            g  += p*M_w[k] + c*M_w[Dn+k];
        }
        #pragma unroll
        for (int o=16;o;o>>=1){
            e1 += __shfl_xor_sync(0xffffffffu, e1, o);
            g  += __shfl_xor_sync(0xffffffffu, g,  o);
        }
        if (lane==0){
            se[slot] = e1 * (1.f/(1.f+__expf(-g)));
            ssrc[slot] = s;
        }
    }
    __syncthreads();
    float mx = -3.4e38f;
    for (int i=0;i<deg;i++) mx = fmaxf(mx, se[i]);
    float acc = 0.f, asum = 0.f;
    for (int i=0;i<deg;i++){
        float a = __expf(se[i]-mx);
        asum += a;
        acc += a * g_hv[(size_t)ssrc[i]*Dn + t];
    }
    g_h[(size_t)d*Dn + t] = acc / asum;
}

// ---------------- K6: f = concat(h_t, last_feat) @ r_w ----------------
__global__ void k_f(const int* __restrict__ tid_, const int* __restrict__ last_idx,
                    const float* __restrict__ target_emb, const float* __restrict__ r_w){
    __shared__ float sin_[8][2*Dn];
    int b0 = blockIdx.x*8;
    int t = threadIdx.x;
    for (int idx=t; idx<8*2*Dn; idx+=256){
        int j = idx>>9, k = idx&511;
        int b = b0+j;
        float v = (k<Dn) ? target_emb[(size_t)tid_[b]*Dn + k]
                         : g_h[(size_t)last_idx[b]*Dn + (k-Dn)];
        sin_[j][k] = v;
    }
    __syncthreads();
    float acc[8] = {0,0,0,0,0,0,0,0};
    int d = t;
    for (int k=0;k<2*Dn;k++){
        float w = r_w[(size_t)k*Dn + d];
        #pragma unroll
        for (int j=0;j<8;j++) acc[j] += sin_[j][k]*w;
    }
    #pragma unroll
    for (int j=0;j<8;j++) g_f[(size_t)(b0+j)*Dn + d] = acc[j];
}

// ---------------- K7: eagg + m-scalar ----------------
__global__ void __launch_bounds__(256) k_eagg(const int* __restrict__ pid, const int* __restrict__ agg_dst,
                        const float* __restrict__ pos_emb, const float* __restrict__ q_w){
    __shared__ __align__(16) float sT[2*Dn][20];
    __shared__ int s_pid[16], s_sess[16];
    __shared__ float sred[8][16];
    int j0 = blockIdx.x*16;
    int t = threadIdx.x;
    if (t<16){ s_pid[t] = pid[j0+t]; s_sess[t] = agg_dst[j0+t]; }
    __syncthreads();
    for (int idx=t; idx<16*2*Dn; idx+=256){
        int j = idx>>9, k = idx&511;
        float v = (k<Dn) ? g_h[(size_t)(j0+j)*Dn + k]
                         : pos_emb[(size_t)s_pid[j]*Dn + (k-Dn)];
        sT[k][j] = v;
    }
    __syncthreads();

    unsigned long long acc[8];
    #pragma unroll
    for (int p=0;p<8;p++) acc[p]=0ull;
    int d = t;
    #pragma unroll 4
    for (int k=0;k<2*Dn;k++){
        float w = q_w[(size_t)k*Dn + d];
        unsigned long long wd = fpack(w,w);
        const ulonglong2* sp = (const ulonglong2*)&sT[k][0];
        #pragma unroll
        for (int q=0;q<4;q++){
            ulonglong2 pr = sp[q];
            acc[2*q+0] = ffma2(pr.x, wd, acc[2*q+0]);
            acc[2*q+1] = ffma2(pr.y, wd, acc[2*q+1]);
        }
    }
    float partial[16];
    #pragma unroll
    for (int p=0;p<8;p++){
        float t0 = tanhf(f2lo(acc[p]));
        float t1 = tanhf(f2hi(acc[p]));
        int j = 2*p;
        partial[j]   = t0 * g_f[(size_t)s_sess[j]*Dn + d];
        partial[j+1] = t1 * g_f[(size_t)s_sess[j+1]*Dn + d];
    }
    int w = t>>5, lane = t&31;
    #pragma unroll
    for (int j=0;j<16;j++){
        float p = partial[j];
        #pragma unroll
        for (int o=16;o;o>>=1) p += __shfl_xor_sync(0xffffffffu, p, o);
        if (lane==0) sred[w][j] = p;
    }
    __syncthreads();
    if (t<16){
        float s=0.f;
        #pragma unroll
        for (int ww=0;ww<8;ww++) s += sred[ww][t];
        g_mscal[j0+t] = s;
    }
}

// ---------------- K8: sr per session + l2norm ----------------
__global__ void k_sr(){
    __shared__ float sm[Sn];
    __shared__ float sred[8];
    int b = blockIdx.x, t = threadIdx.x;
    if (t<Sn) sm[t] = g_mscal[b*Sn + t];
    __syncthreads();
    float acc = 0.f;
    #pragma unroll
    for (int s=0;s<Sn;s++) acc += g_h[(size_t)(b*Sn+s)*Dn + t]*sm[s];
    float ss = acc*acc;
    #pragma unroll
    for (int o=16;o;o>>=1) ss += __shfl_xor_sync(0xffffffffu, ss, o);
    if ((t&31)==0) sred[t>>5] = ss;
    __syncthreads();
    float tot = 0.f;
    #pragma unroll
    for (int w=0;w<8;w++) tot += sred[w];
    g_srn[(size_t)b*Dn + t] = acc / fmaxf(sqrtf(tot), 1e-12f);
}

// ---------------- K9: phi head ----------------
__global__ void k_phi(const float* __restrict__ sc1_w, const float* __restrict__ sc1_b,
                      const float* __restrict__ sc2_w){
    __shared__ float ssr[8][Dn];
    __shared__ float s_p[8][2];
    int b0 = blockIdx.x*8;
    int t = threadIdx.x;
    for (int idx=t; idx<8*Dn; idx+=256){
        int j = idx>>8, k = idx&255;
        ssr[j][k] = g_srn[(size_t)(b0+j)*Dn + k];
    }
    if (t<16) s_p[t>>1][t&1] = 0.f;
    __syncthreads();
    float acc[8] = {0,0,0,0,0,0,0,0};
    int d = t;
    for (int k=0;k<Dn;k++){
        float w = sc1_w[(size_t)k*Dn + d];
        #pragma unroll
        for (int j=0;j<8;j++) acc[j] += ssr[j][k]*w;
    }
    float bb = sc1_b[d], w0 = sc2_w[d*2], w1 = sc2_w[d*2+1];
    int lane = t&31;
    #pragma unroll
    for (int j=0;j<8;j++){
        float hid = fmaxf(acc[j]+bb, 0.f);
        float p0 = hid*w0, p1 = hid*w1;
        #pragma unroll
        for (int o=16;o;o>>=1){
            p0 += __shfl_xor_sync(0xffffffffu, p0, o);
            p1 += __shfl_xor_sync(0xffffffffu, p1, o);
        }
        if (lane==0){ atomicAdd(&s_p[j][0], p0); atomicAdd(&s_p[j][1], p1); }
    }
    __syncthreads();
    if (t<8){
        float a0 = s_p[t][0], a1 = s_p[t][1];
        float m = fmaxf(a0,a1);
        float lse = m + logf(__expf(a0-m)+__expf(a1-m));
        g_logphi[(b0+t)*2+0] = a0 - lse;
        g_logphi[(b0+t)*2+1] = a1 - lse;
    }
}

// ---------------- K10: masked (in-session) logits + msum ----------------
__global__ void k_masked(const int* __restrict__ iid, const float* __restrict__ emb){
    __shared__ int iids[Sn];
    __shared__ float s_sr[Dn];
    int b = blockIdx.x, t = threadIdx.x;
    if (t<Sn) iids[t] = iid[b*Sn+t];
    if (t<Dn) s_sr[t] = g_srn[(size_t)b*Dn + t];
    __syncthreads();
    int warp = t>>5, lane = t&31;
    for (int slot=warp; slot<Sn; slot+=8){
        int v = iids[slot];
        bool dup = false;
        for (int j=0;j<slot;j++) if (iids[j]==v) { dup=true; break; }
        if (dup){
            if (lane==0) g_mask_v[b*Sn+slot] = -1;
            continue;
        }
        const float* ev = emb + (size_t)v*Dn;
        float dot = 0.f;
        for (int k=lane;k<Dn;k+=32) dot += s_sr[k]*ev[k];
        #pragma unroll
        for (int o=16;o;o>>=1) dot += __shfl_xor_sync(0xffffffffu, dot, o);
        if (lane==0){
            float l = dot * g_inorm[v] * 12.f;
            g_mask_v[b*Sn+slot] = v;
            g_mask_l[b*Sn+slot] = l;
            atomicAdd(&g_msum[b], (double)__expf(l-12.f));
        }
    }
}

// ---------------- K11: smem-free mma.sync fp16 2-term GEMM ----------------
// CTA 128M x 128N, 8 warps (4x2), warp tile 32x64, K chunks of 16.
// A = (ah + al) fp16 split (exact), B = fp16 single term.
__global__ void __launch_bounds__(256,2) k_gemm_mma(float* __restrict__ out){
    int tid = threadIdx.x;
    int w = tid>>5, lane = tid&31;
    int g = lane>>2, t = lane&3;
    int wm = w>>1, wn = w&1;
    int m0 = blockIdx.x*128;       // 0..3
    int v0 = blockIdx.y*128;       // 0..781

    int ar0 = m0 + wm*32 + g;      // A rows: ar0 + mi*16 + rp*8
    int nbase = v0 + wn*64 + g;    // B rows: nbase + ni*8

    const uint2* bptr[8];
    bool bok[8];
    #pragma unroll
    for (int ni=0;ni<8;ni++){
        int nb = nbase + ni*8;
        bok[ni] = (nb < Vn);
        bptr[ni] = g_bp + (size_t)(bok[ni]?nb:0)*64 + t;
    }
    const uint4* aptr[2][2];
    #pragma unroll
    for (int mi=0;mi<2;mi++)
        #pragma unroll
        for (int rp=0;rp<2;rp++){
            int row = ar0 + mi*16 + rp*8;
            aptr[mi][rp] = g_ap + row*64 + t;
        }

    float acc[2][8][4];
    #pragma unroll
    for (int mi=0;mi<2;mi++)
        #pragma unroll
        for (int ni=0;ni<8;ni++)
            #pragma unroll
            for (int q=0;q<4;q++) acc[mi][ni][q]=0.f;

    const uint2 z2 = make_uint2(0,0);
    #pragma unroll 2
    for (int c=0; c<16; c++){
        int so = c*4;
        uint4 A0[2], A1[2];
        #pragma unroll
        for (int mi=0;mi<2;mi++){
            A0[mi] = __ldg(aptr[mi][0] + so);   // row g
            A1[mi] = __ldg(aptr[mi][1] + so);   // row g+8
        }
        #pragma unroll
        for (int ni=0;ni<8;ni++){
            uint2 b = bok[ni] ? __ldg(bptr[ni] + so) : z2;
            #pragma unroll
            for (int mi=0;mi<2;mi++){
                // hi * b
                MMA_F16(acc[mi][ni], A0[mi].x, A1[mi].x, A0[mi].y, A1[mi].y, b.x, b.y);
                // lo * b
                MMA_F16(acc[mi][ni], A0[mi].z, A1[mi].z, A0[mi].w, A1[mi].w, b.x, b.y);
            }
        }
    }

    // epilogue: scale by 12*inorm, store, accumulate exp row sums
    float rsum[4] = {0.f,0.f,0.f,0.f};
    #pragma unroll
    for (int mi=0;mi<2;mi++){
        int r0 = m0 + wm*32 + mi*16 + g;
        #pragma unroll
        for (int ni=0;ni<8;ni++){
            int col = v0 + wn*64 + ni*8 + 2*t;
            if (col < Vn){
                float s0 = 12.f*g_inorm[col], s1 = 12.f*g_inorm[col+1];
                float v00 = acc[mi][ni][0]*s0, v01 = acc[mi][ni][1]*s1;
                float v10 = acc[mi][ni][2]*s0, v11 = acc[mi][ni][3]*s1;
                float2* p0 = (float2*)(out + (size_t)r0*Vn + col);
                float2* p1 = (float2*)(out + (size_t)(r0+8)*Vn + col);
                __stcs(p0, make_float2(v00, v01));
                __stcs(p1, make_float2(v10, v11));
                rsum[mi*2+0] += __expf(v00-12.f) + __expf(v01-12.f);
                rsum[mi*2+1] += __expf(v10-12.f) + __expf(v11-12.f);
            }
        }
    }
    #pragma unroll
    for (int o=1;o<4;o<<=1)
        #pragma unroll
        for (int j=0;j<4;j++) rsum[j] += __shfl_xor_sync(0xffffffffu, rsum[j], o);
    if (t==0){
        #pragma unroll
        for (int j=0;j<4;j++){
            int row = m0 + wm*32 + (j>>1)*16 + (j&1)*8 + g;
            atomicAdd(&g_rowsum[row], (double)rsum[j]);
        }
    }
}

// ---------------- K12: per-row shift for unmasked entries ----------------
__global__ void k_finalize(float* __restrict__ out){
    __shared__ float s_shift;
    int row = blockIdx.y;
    if (threadIdx.x==0){
        double sex = g_rowsum[row] - g_msum[row];
        s_shift = g_logphi[row*2+1] - (float)(12.0 + log(sex));
    }
    __syncthreads();
    float sh = s_shift;
    int i = blockIdx.x*blockDim.x + threadIdx.x;
    if (i < Vn/4){
        float4* p = (float4*)(out + (size_t)row*Vn) + i;
        float4 o = __ldcs(p);
        o.x += sh; o.y += sh; o.z += sh; o.w += sh;
        __stcs(p, o);
    }
}

// ---------------- K13: overwrite masked entries ----------------
__global__ void k_fixup(float* __restrict__ out){
    int b = blockIdx.x, s = threadIdx.x;
    if (s >= Sn) return;
    int v = g_mask_v[b*Sn+s];
    if (v < 0) return;
    float lse_in = (float)(12.0 + log(g_msum[b]));
    out[(size_t)b*Vn + v] = g_mask_l[b*Sn+s] - lse_in + g_logphi[b*2+0];
}

// ---------------- launch ----------------
extern "C" void kernel_launch(void* const* d_in, const int* in_sizes, int n_in,
                              void* d_out, int out_size){
    const int* iid      = (const int*)d_in[0];
    const int* src      = (const int*)d_in[1];
    const int* dst      = (const int*)d_in[2];
    const int* dis      = (const int*)d_in[3];
    const int* pid      = (const int*)d_in[4];
    const int* agg_dst  = (const int*)d_in[6];
    const int* tid_     = (const int*)d_in[7];
    const int* last_idx = (const int*)d_in[8];
    const float* emb        = (const float*)d_in[9];
    const float* pos_emb    = (const float*)d_in[10];
    const float* dis_emb    = (const float*)d_in[11];
    const float* target_emb = (const float*)d_in[12];
    const float* pi_w  = (const float*)d_in[13];
    const float* M_w   = (const float*)d_in[14];
    const float* q_w   = (const float*)d_in[15];
    const float* r_w   = (const float*)d_in[16];
    const float* sc1_w = (const float*)d_in[17];
    const float* sc1_b = (const float*)d_in[18];
    const float* sc2_w = (const float*)d_in[19];
    float* out = (float*)d_out;

    k_zero<<<(Nn+255)/256,256>>>();                      // 1
    k_count<<<En/256,256>>>(dst);                        // 2
    k_scan<<<1,1024>>>();                                // 3
    k_bpack<<<(int)(((long long)Vn*64+255)/256),256>>>(emb);  // 4 (profiled slot)
    k_scatter<<<En/256,256>>>(dst);                      // 5
    k_inorm<<<Vn/8,256>>>(emb);                          // 6
    k_hv<<<(Nn*Dn)/256,256>>>(emb, iid);                 // 7
    k_gat<<<Nn,256>>>(src,dis,dis_emb,pi_w,M_w);         // 8
    k_f<<<Bn/8,256>>>(tid_,last_idx,target_emb,r_w);
    k_eagg<<<Nn/16,256>>>(pid,agg_dst,pos_emb,q_w);
    k_sr<<<Bn,256>>>();
    k_apack<<<Bn*64/256,256>>>();
    k_phi<<<Bn/8,256>>>(sc1_w,sc1_b,sc2_w);
    k_masked<<<Bn,256>>>(iid, emb);
    dim3 gg(4, (Vn+127)/128);
    k_gemm_mma<<<gg, 256>>>(out);
    dim3 gf((Vn/4 + 255)/256, Bn);
    k_finalize<<<gf,256>>>(out);
    k_fixup<<<Bn,32>>>(out);
}

// round 9
// speedup vs baseline: 1.7355x; 1.0369x over previous
#include <cuda_runtime.h>
#include <cuda_bf16.h>
#include <cuda_fp16.h>
#include <math.h>
#include <stdint.h>

#define Vn 100000
#define Dn 256
#define Bn 512
#define Sn 20
#define Nn (Bn*Sn)      // 10240
#define En (8*Nn)       // 81920
#define DEGMAX 128

// ---------------- scratch (device globals; no allocation allowed) ----------------
__device__ float g_inorm[Vn];
__device__ float g_hv[Nn*Dn];
__device__ float g_h[Nn*Dn];
__device__ float g_f[Bn*Dn];
__device__ float g_mscal[Nn];
__device__ float g_srn[Bn*Dn];
__device__ float g_logphi[Bn*2];
__device__ double g_rowsum[Bn];
__device__ double g_msum[Bn];
__device__ int   g_mask_v[Bn*Sn];
__device__ float g_mask_l[Bn*Sn];
// CSR
__device__ int g_deg[Nn];
__device__ int g_off[Nn+1];
__device__ int g_pos[Nn];
__device__ int g_eidx[En];
// packed GEMM operands: per row, 64 slots; slot s = c*4+t (chunk c of K=16, quad-thread t), k0 = c*16+2t
// uint2 = { f16x2(k0,k0+1), f16x2(k0+8,k0+9) }   single-term fp16 for both A and B
__device__ uint2 g_bp[(size_t)Vn*64];   // 51.2 MB
__device__ uint2 g_ap[Bn*64];           // 0.25 MB

// ---------------- helpers ----------------
__device__ __forceinline__ unsigned long long ffma2(unsigned long long a, unsigned long long b, unsigned long long c){
    unsigned long long d;
    asm("fma.rn.f32x2 %0, %1, %2, %3;" : "=l"(d) : "l"(a), "l"(b), "l"(c));
    return d;
}
__device__ __forceinline__ float f2lo(unsigned long long u){ return __int_as_float((int)(unsigned)(u & 0xFFFFFFFFull)); }
__device__ __forceinline__ float f2hi(unsigned long long u){ return __int_as_float((int)(unsigned)(u >> 32)); }
__device__ __forceinline__ unsigned long long fpack(float lo, float hi){
    unsigned long long u;
    asm("mov.b64 %0, {%1, %2};" : "=l"(u) : "r"(__float_as_int(lo)), "r"(__float_as_int(hi)));
    return u;
}

// fp16 helpers
__device__ __forceinline__ unsigned short hfr(float x){
    __half h = __float2half_rn(x);
    return *(unsigned short*)&h;
}

// mma.sync m16n8k16 f16: D = A*B + D (fp32 accum)
#define MMA_F16(d, a0, a1, a2, a3, b0, b1) \
    asm volatile("mma.sync.aligned.m16n8k16.row.col.f32.f16.f16.f32 " \
        "{%0,%1,%2,%3}, {%4,%5,%6,%7}, {%8,%9}, {%0,%1,%2,%3};" \
        : "+f"((d)[0]), "+f"((d)[1]), "+f"((d)[2]), "+f"((d)[3]) \
        : "r"(a0), "r"(a1), "r"(a2), "r"(a3), "r"(b0), "r"(b1))

// ---------------- K0: zero scratch ----------------
__global__ void k_zero(){
    int i = blockIdx.x*blockDim.x + threadIdx.x;
    if (i < Nn) g_deg[i] = 0;
    if (i < Bn){ g_rowsum[i]=0.0; g_msum[i]=0.0; }
}

// ---------------- CSR build ----------------
__global__ void k_count(const int* __restrict__ dst){
    int e = blockIdx.x*blockDim.x + threadIdx.x;
    if (e < En) atomicAdd(&g_deg[dst[e]], 1);
}
__global__ void k_scan(){        // 1 block, 1024 threads, 10 elems/thread
    __shared__ int warp_sums[32];
    int t = threadIdx.x;
    int base = t*10;
    int local[10]; int s = 0;
    #pragma unroll
    for (int i=0;i<10;i++){ local[i]=s; s += g_deg[base+i]; }
    int lane = t&31, w = t>>5;
    int v = s;
    #pragma unroll
    for (int o=1;o<32;o<<=1){ int u=__shfl_up_sync(0xffffffffu,v,o); if(lane>=o) v+=u; }
    if (lane==31) warp_sums[w]=v;
    __syncthreads();
    if (w==0){
        int x = warp_sums[lane];
        #pragma unroll
        for (int o=1;o<32;o<<=1){ int u=__shfl_up_sync(0xffffffffu,x,o); if(lane>=o) x+=u; }
        warp_sums[lane]=x;
    }
    __syncthreads();
    int excl = v - s + (w>0 ? warp_sums[w-1] : 0);
    #pragma unroll
    for (int i=0;i<10;i++){ g_off[base+i]=excl+local[i]; g_pos[base+i]=excl+local[i]; }
    if (t==1023) g_off[Nn]=En;
}
__global__ void k_scatter(const int* __restrict__ dst){
    int e = blockIdx.x*blockDim.x + threadIdx.x;
    if (e < En){
        int p = atomicAdd(&g_pos[dst[e]], 1);
        g_eidx[p] = e;
    }
}

// ---------------- pack emb into fp16 fragment layout ----------------
__global__ void k_bpack(const float* __restrict__ emb){
    long long id = (long long)blockIdx.x*blockDim.x + threadIdx.x;
    if (id >= (long long)Vn*64) return;
    int row = (int)(id>>6), s = (int)(id&63);
    int c = s>>2, t = s&3;
    int k0 = c*16 + 2*t;
    const float* p = emb + (size_t)row*Dn;
    unsigned short h0=hfr(p[k0]), h1=hfr(p[k0+1]), h2=hfr(p[k0+8]), h3=hfr(p[k0+9]);
    uint2 o;
    o.x = ((unsigned)h1<<16) | h0;
    o.y = ((unsigned)h3<<16) | h2;
    g_bp[(size_t)row*64 + s] = o;
}

// ---------------- pack srn fp16 ----------------
__global__ void k_apack(){
    int id = blockIdx.x*blockDim.x + threadIdx.x;   // Bn*64 = 32768
    int row = id>>6, s = id&63;
    int c = s>>2, t = s&3;
    int k0 = c*16 + 2*t;
    const float* p = g_srn + (size_t)row*Dn;
    unsigned short h0=hfr(p[k0]), h1=hfr(p[k0+1]), h2=hfr(p[k0+8]), h3=hfr(p[k0+9]);
    uint2 o;
    o.x = ((unsigned)h1<<16) | h0;
    o.y = ((unsigned)h3<<16) | h2;
    g_ap[row*64 + s] = o;
}

// ---------------- K1: inverse norms of emb rows ----------------
__global__ void k_inorm(const float* __restrict__ emb){
    int row = blockIdx.x*8 + (threadIdx.x>>5);
    int lane = threadIdx.x&31;
    float ss = 0.f;
    const float* p = emb + (size_t)row*Dn;
    for (int k=lane;k<Dn;k+=32){ float x=p[k]; ss += x*x; }
    #pragma unroll
    for (int o=16;o;o>>=1) ss += __shfl_xor_sync(0xffffffffu, ss, o);
    if (lane==0) g_inorm[row] = 1.f / fmaxf(sqrtf(ss), 1e-12f);
}

// ---------------- K2: h_v = l2norm(emb[iid]) ----------------
__global__ void k_hv(const float* __restrict__ emb, const int* __restrict__ iid){
    int i = blockIdx.x*blockDim.x + threadIdx.x;
    int n = i>>8, k = i&255;
    int id = iid[n];
    g_hv[i] = emb[(size_t)id*Dn + k] * g_inorm[id];
}

// ---------------- K3: fused gather GAT ----------------
__global__ void __launch_bounds__(256) k_gat(const int* __restrict__ src, const int* __restrict__ dis,
                      const float* __restrict__ dis_emb,
                      const float* __restrict__ pi_w, const float* __restrict__ M_w){
    __shared__ float hd[Dn];
    __shared__ float se[DEGMAX];
    __shared__ int   ssrc[DEGMAX];
    int d = blockIdx.x;
    int t = threadIdx.x;
    int beg = g_off[d], end = g_off[d+1];
    int deg = end - beg; if (deg > DEGMAX) deg = DEGMAX;
    if (deg == 0){
        g_h[(size_t)d*Dn + t] = 0.f;
        return;
    }
    hd[t] = g_hv[(size_t)d*Dn + t];
    __syncthreads();
    int warp = t>>5, lane = t&31;
    for (int slot=warp; slot<deg; slot+=8){
        int e = g_eidx[beg+slot];
        int s = src[e], di = dis[e];
        const float* hs = g_hv + (size_t)s*Dn;
        const float* he = dis_emb + (size_t)di*Dn;
        float e1 = 0.f, g = 0.f;
        for (int k=lane;k<Dn;k+=32){
            float a = hs[k], b = hd[k], c = he[k];
            float p = a*b;
            e1 += p*c*pi_w[k];
            g  += p*M_w[k] + c*M_w[Dn+k];
        }
        #pragma unroll
        for (int o=16;o;o>>=1){
            e1 += __shfl_xor_sync(0xffffffffu, e1, o);
            g  += __shfl_xor_sync(0xffffffffu, g,  o);
        }
        if (lane==0){
            se[slot] = e1 * (1.f/(1.f+__expf(-g)));
            ssrc[slot] = s;
        }
    }
    __syncthreads();
    float mx = -3.4e38f;
    for (int i=0;i<deg;i++) mx = fmaxf(mx, se[i]);
    float acc = 0.f, asum = 0.f;
    for (int i=0;i<deg;i++){
        float a = __expf(se[i]-mx);
        asum += a;
        acc += a * g_hv[(size_t)ssrc[i]*Dn + t];
    }
    g_h[(size_t)d*Dn + t] = acc / asum;
}

// ---------------- K6: f = concat(h_t, last_feat) @ r_w ----------------
__global__ void k_f(const int* __restrict__ tid_, const int* __restrict__ last_idx,
                    const float* __restrict__ target_emb, const float* __restrict__ r_w){
    __shared__ float sin_[8][2*Dn];
    int b0 = blockIdx.x*8;
    int t = threadIdx.x;
    for (int idx=t; idx<8*2*Dn; idx+=256){
        int j = idx>>9, k = idx&511;
        int b = b0+j;
        float v = (k<Dn) ? target_emb[(size_t)tid_[b]*Dn + k]
                         : g_h[(size_t)last_idx[b]*Dn + (k-Dn)];
        sin_[j][k] = v;
    }
    __syncthreads();
    float acc[8] = {0,0,0,0,0,0,0,0};
    int d = t;
    for (int k=0;k<2*Dn;k++){
        float w = r_w[(size_t)k*Dn + d];
        #pragma unroll
        for (int j=0;j<8;j++) acc[j] += sin_[j][k]*w;
    }
    #pragma unroll
    for (int j=0;j<8;j++) g_f[(size_t)(b0+j)*Dn + d] = acc[j];
}

// ---------------- K7: eagg + m-scalar ----------------
__global__ void __launch_bounds__(256) k_eagg(const int* __restrict__ pid, const int* __restrict__ agg_dst,
                        const float* __restrict__ pos_emb, const float* __restrict__ q_w){
    __shared__ __align__(16) float sT[2*Dn][20];
    __shared__ int s_pid[16], s_sess[16];
    __shared__ float sred[8][16];
    int j0 = blockIdx.x*16;
    int t = threadIdx.x;
    if (t<16){ s_pid[t] = pid[j0+t]; s_sess[t] = agg_dst[j0+t]; }
    __syncthreads();
    for (int idx=t; idx<16*2*Dn; idx+=256){
        int j = idx>>9, k = idx&511;
        float v = (k<Dn) ? g_h[(size_t)(j0+j)*Dn + k]
                         : pos_emb[(size_t)s_pid[j]*Dn + (k-Dn)];
        sT[k][j] = v;
    }
    __syncthreads();

    unsigned long long acc[8];
    #pragma unroll
    for (int p=0;p<8;p++) acc[p]=0ull;
    int d = t;
    #pragma unroll 4
    for (int k=0;k<2*Dn;k++){
        float w = q_w[(size_t)k*Dn + d];
        unsigned long long wd = fpack(w,w);
        const ulonglong2* sp = (const ulonglong2*)&sT[k][0];
        #pragma unroll
        for (int q=0;q<4;q++){
            ulonglong2 pr = sp[q];
            acc[2*q+0] = ffma2(pr.x, wd, acc[2*q+0]);
            acc[2*q+1] = ffma2(pr.y, wd, acc[2*q+1]);
        }
    }
    float partial[16];
    #pragma unroll
    for (int p=0;p<8;p++){
        float t0 = tanhf(f2lo(acc[p]));
        float t1 = tanhf(f2hi(acc[p]));
        int j = 2*p;
        partial[j]   = t0 * g_f[(size_t)s_sess[j]*Dn + d];
        partial[j+1] = t1 * g_f[(size_t)s_sess[j+1]*Dn + d];
    }
    int w = t>>5, lane = t&31;
    #pragma unroll
    for (int j=0;j<16;j++){
        float p = partial[j];
        #pragma unroll
        for (int o=16;o;o>>=1) p += __shfl_xor_sync(0xffffffffu, p, o);
        if (lane==0) sred[w][j] = p;
    }
    __syncthreads();
    if (t<16){
        float s=0.f;
        #pragma unroll
        for (int ww=0;ww<8;ww++) s += sred[ww][t];
        g_mscal[j0+t] = s;
    }
}

// ---------------- K8: sr per session + l2norm ----------------
__global__ void k_sr(){
    __shared__ float sm[Sn];
    __shared__ float sred[8];
    int b = blockIdx.x, t = threadIdx.x;
    if (t<Sn) sm[t] = g_mscal[b*Sn + t];
    __syncthreads();
    float acc = 0.f;
    #pragma unroll
    for (int s=0;s<Sn;s++) acc += g_h[(size_t)(b*Sn+s)*Dn + t]*sm[s];
    float ss = acc*acc;
    #pragma unroll
    for (int o=16;o;o>>=1) ss += __shfl_xor_sync(0xffffffffu, ss, o);
    if ((t&31)==0) sred[t>>5] = ss;
    __syncthreads();
    float tot = 0.f;
    #pragma unroll
    for (int w=0;w<8;w++) tot += sred[w];
    g_srn[(size_t)b*Dn + t] = acc / fmaxf(sqrtf(tot), 1e-12f);
}

// ---------------- K9: phi head ----------------
__global__ void k_phi(const float* __restrict__ sc1_w, const float* __restrict__ sc1_b,
                      const float* __restrict__ sc2_w){
    __shared__ float ssr[8][Dn];
    __shared__ float s_p[8][2];
    int b0 = blockIdx.x*8;
    int t = threadIdx.x;
    for (int idx=t; idx<8*Dn; idx+=256){
        int j = idx>>8, k = idx&255;
        ssr[j][k] = g_srn[(size_t)(b0+j)*Dn + k];
    }
    if (t<16) s_p[t>>1][t&1] = 0.f;
    __syncthreads();
    float acc[8] = {0,0,0,0,0,0,0,0};
    int d = t;
    for (int k=0;k<Dn;k++){
        float w = sc1_w[(size_t)k*Dn + d];
        #pragma unroll
        for (int j=0;j<8;j++) acc[j] += ssr[j][k]*w;
    }
    float bb = sc1_b[d], w0 = sc2_w[d*2], w1 = sc2_w[d*2+1];
    int lane = t&31;
    #pragma unroll
    for (int j=0;j<8;j++){
        float hid = fmaxf(acc[j]+bb, 0.f);
        float p0 = hid*w0, p1 = hid*w1;
        #pragma unroll
        for (int o=16;o;o>>=1){
            p0 += __shfl_xor_sync(0xffffffffu, p0, o);
            p1 += __shfl_xor_sync(0xffffffffu, p1, o);
        }
        if (lane==0){ atomicAdd(&s_p[j][0], p0); atomicAdd(&s_p[j][1], p1); }
    }
    __syncthreads();
    if (t<8){
        float a0 = s_p[t][0], a1 = s_p[t][1];
        float m = fmaxf(a0,a1);
        float lse = m + logf(__expf(a0-m)+__expf(a1-m));
        g_logphi[(b0+t)*2+0] = a0 - lse;
        g_logphi[(b0+t)*2+1] = a1 - lse;
    }
}

// ---------------- K10: masked (in-session) logits + msum ----------------
__global__ void k_masked(const int* __restrict__ iid, const float* __restrict__ emb){
    __shared__ int iids[Sn];
    __shared__ float s_sr[Dn];
    int b = blockIdx.x, t = threadIdx.x;
    if (t<Sn) iids[t] = iid[b*Sn+t];
    if (t<Dn) s_sr[t] = g_srn[(size_t)b*Dn + t];
    __syncthreads();
    int warp = t>>5, lane = t&31;
    for (int slot=warp; slot<Sn; slot+=8){
        int v = iids[slot];
        bool dup = false;
        for (int j=0;j<slot;j++) if (iids[j]==v) { dup=true; break; }
        if (dup){
            if (lane==0) g_mask_v[b*Sn+slot] = -1;
            continue;
        }
        const float* ev = emb + (size_t)v*Dn;
        float dot = 0.f;
        for (int k=lane;k<Dn;k+=32) dot += s_sr[k]*ev[k];
        #pragma unroll
        for (int o=16;o;o>>=1) dot += __shfl_xor_sync(0xffffffffu, dot, o);
        if (lane==0){
            float l = dot * g_inorm[v] * 12.f;
            g_mask_v[b*Sn+slot] = v;
            g_mask_l[b*Sn+slot] = l;
            atomicAdd(&g_msum[b], (double)__expf(l-12.f));
        }
    }
}

// ---------------- K11: smem-free mma.sync fp16 single-term GEMM ----------------
// CTA 128M x 128N, 8 warps (4x2), warp tile 32x64, K chunks of 16.
__global__ void __launch_bounds__(256,2) k_gemm_mma(float* __restrict__ out){
    int tid = threadIdx.x;
    int w = tid>>5, lane = tid&31;
    int g = lane>>2, t = lane&3;
    int wm = w>>1, wn = w&1;
    int m0 = blockIdx.x*128;       // 0..3
    int v0 = blockIdx.y*128;       // 0..781

    int ar0 = m0 + wm*32 + g;      // A rows: ar0 + mi*16 + rp*8
    int nbase = v0 + wn*64 + g;    // B rows: nbase + ni*8

    const uint2* bptr[8];
    bool bok[8];
    #pragma unroll
    for (int ni=0;ni<8;ni++){
        int nb = nbase + ni*8;
        bok[ni] = (nb < Vn);
        bptr[ni] = g_bp + (size_t)(bok[ni]?nb:0)*64 + t;
    }
    const uint2* aptr[2][2];
    #pragma unroll
    for (int mi=0;mi<2;mi++)
        #pragma unroll
        for (int rp=0;rp<2;rp++){
            int row = ar0 + mi*16 + rp*8;
            aptr[mi][rp] = g_ap + row*64 + t;
        }

    float acc[2][8][4];
    #pragma unroll
    for (int mi=0;mi<2;mi++)
        #pragma unroll
        for (int ni=0;ni<8;ni++)
            #pragma unroll
            for (int q=0;q<4;q++) acc[mi][ni][q]=0.f;

    const uint2 z2 = make_uint2(0,0);
    #pragma unroll 2
    for (int c=0; c<16; c++){
        int so = c*4;
        uint2 A0[2], A1[2];
        #pragma unroll
        for (int mi=0;mi<2;mi++){
            A0[mi] = __ldg(aptr[mi][0] + so);   // row g
            A1[mi] = __ldg(aptr[mi][1] + so);   // row g+8
        }
        #pragma unroll
        for (int ni=0;ni<8;ni++){
            uint2 b = bok[ni] ? __ldg(bptr[ni] + so) : z2;
            #pragma unroll
            for (int mi=0;mi<2;mi++){
                MMA_F16(acc[mi][ni], A0[mi].x, A1[mi].x, A0[mi].y, A1[mi].y, b.x, b.y);
            }
        }
    }

    // epilogue: scale by 12*inorm, store, accumulate exp row sums
    float rsum[4] = {0.f,0.f,0.f,0.f};
    #pragma unroll
    for (int mi=0;mi<2;mi++){
        int r0 = m0 + wm*32 + mi*16 + g;
        #pragma unroll
        for (int ni=0;ni<8;ni++){
            int col = v0 + wn*64 + ni*8 + 2*t;
            if (col < Vn){
                float s0 = 12.f*g_inorm[col], s1 = 12.f*g_inorm[col+1];
                float v00 = acc[mi][ni][0]*s0, v01 = acc[mi][ni][1]*s1;
                float v10 = acc[mi][ni][2]*s0, v11 = acc[mi][ni][3]*s1;
                float2* p0 = (float2*)(out + (size_t)r0*Vn + col);
                float2* p1 = (float2*)(out + (size_t)(r0+8)*Vn + col);
                __stcs(p0, make_float2(v00, v01));
                __stcs(p1, make_float2(v10, v11));
                rsum[mi*2+0] += __expf(v00-12.f) + __expf(v01-12.f);
                rsum[mi*2+1] += __expf(v10-12.f) + __expf(v11-12.f);
            }
        }
    }
    #pragma unroll
    for (int o=1;o<4;o<<=1)
        #pragma unroll
        for (int j=0;j<4;j++) rsum[j] += __shfl_xor_sync(0xffffffffu, rsum[j], o);
    if (t==0){
        #pragma unroll
        for (int j=0;j<4;j++){
            int row = m0 + wm*32 + (j>>1)*16 + (j&1)*8 + g;
            atomicAdd(&g_rowsum[row], (double)rsum[j]);
        }
    }
}

// ---------------- K12: per-row shift for unmasked entries ----------------
__global__ void k_finalize(float* __restrict__ out){
    __shared__ float s_shift;
    int row = blockIdx.y;
    if (threadIdx.x==0){
        double sex = g_rowsum[row] - g_msum[row];
        s_shift = g_logphi[row*2+1] - (float)(12.0 + log(sex));
    }
    __syncthreads();
    float sh = s_shift;
    int i = blockIdx.x*blockDim.x + threadIdx.x;
    if (i < Vn/4){
        float4* p = (float4*)(out + (size_t)row*Vn) + i;
        float4 o = __ldcs(p);
        o.x += sh; o.y += sh; o.z += sh; o.w += sh;
        __stcs(p, o);
    }
}

// ---------------- K13: overwrite masked entries ----------------
__global__ void k_fixup(float* __restrict__ out){
    int b = blockIdx.x, s = threadIdx.x;
    if (s >= Sn) return;
    int v = g_mask_v[b*Sn+s];
    if (v < 0) return;
    float lse_in = (float)(12.0 + log(g_msum[b]));
    out[(size_t)b*Vn + v] = g_mask_l[b*Sn+s] - lse_in + g_logphi[b*2+0];
}

// ---------------- launch ----------------
extern "C" void kernel_launch(void* const* d_in, const int* in_sizes, int n_in,
                              void* d_out, int out_size){
    const int* iid      = (const int*)d_in[0];
    const int* src      = (const int*)d_in[1];
    const int* dst      = (const int*)d_in[2];
    const int* dis      = (const int*)d_in[3];
    const int* pid      = (const int*)d_in[4];
    const int* agg_dst  = (const int*)d_in[6];
    const int* tid_     = (const int*)d_in[7];
    const int* last_idx = (const int*)d_in[8];
    const float* emb        = (const float*)d_in[9];
    const float* pos_emb    = (const float*)d_in[10];
    const float* dis_emb    = (const float*)d_in[11];
    const float* target_emb = (const float*)d_in[12];
    const float* pi_w  = (const float*)d_in[13];
    const float* M_w   = (const float*)d_in[14];
    const float* q_w   = (const float*)d_in[15];
    const float* r_w   = (const float*)d_in[16];
    const float* sc1_w = (const float*)d_in[17];
    const float* sc1_b = (const float*)d_in[18];
    const float* sc2_w = (const float*)d_in[19];
    float* out = (float*)d_out;

    k_zero<<<(Nn+255)/256,256>>>();                      // 1
    k_count<<<En/256,256>>>(dst);                        // 2
    k_scan<<<1,1024>>>();                                // 3
    k_bpack<<<(int)(((long long)Vn*64+255)/256),256>>>(emb);  // 4 (profiled slot)
    k_scatter<<<En/256,256>>>(dst);                      // 5
    k_inorm<<<Vn/8,256>>>(emb);                          // 6
    k_hv<<<(Nn*Dn)/256,256>>>(emb, iid);                 // 7
    k_gat<<<Nn,256>>>(src,dis,dis_emb,pi_w,M_w);         // 8
    k_f<<<Bn/8,256>>>(tid_,last_idx,target_emb,r_w);
    k_eagg<<<Nn/16,256>>>(pid,agg_dst,pos_emb,q_w);
    k_sr<<<Bn,256>>>();
    k_apack<<<Bn*64/256,256>>>();
    k_phi<<<Bn/8,256>>>(sc1_w,sc1_b,sc2_w);
    k_masked<<<Bn,256>>>(iid, emb);
    dim3 gg(4, (Vn+127)/128);
    k_gemm_mma<<<gg, 256>>>(out);
    dim3 gf((Vn/4 + 255)/256, Bn);
    k_finalize<<<gf,256>>>(out);
    k_fixup<<<Bn,32>>>(out);
}

// round 10
// speedup vs baseline: 1.8856x; 1.0865x over previous
#include <cuda_runtime.h>
#include <cuda_bf16.h>
#include <cuda_fp16.h>
#include <math.h>
#include <stdint.h>

#define Vn 100000
#define Dn 256
#define Bn 512
#define Sn 20
#define Nn (Bn*Sn)      // 10240
#define En (8*Nn)       // 81920
#define DEGMAX 128

// ---------------- scratch (device globals; no allocation allowed) ----------------
__device__ float g_inorm[Vn];
__device__ float g_hv[Nn*Dn];
__device__ float g_h[Nn*Dn];
__device__ float g_f[Bn*Dn];
__device__ float g_mscal[Nn];
__device__ float g_srn[Bn*Dn];
__device__ float g_logphi[Bn*2];
__device__ double g_rowsum[Bn];
__device__ double g_msum[Bn];
__device__ int   g_mask_v[Bn*Sn];
__device__ float g_mask_l[Bn*Sn];
// CSR
__device__ int g_deg[Nn];
__device__ int g_off[Nn+1];
__device__ int g_pos[Nn];
__device__ int g_eidx[En];
// packed GEMM operands: per row, 64 slots; slot s = c*4+t (chunk c of K=16, quad-thread t), k0 = c*16+2t
// uint2 = { f16x2(k0,k0+1), f16x2(k0+8,k0+9) }   single-term fp16 for both A and B
__device__ uint2 g_bp[(size_t)Vn*64];   // 51.2 MB
__device__ uint2 g_ap[Bn*64];           // 0.25 MB

// ---------------- helpers ----------------
__device__ __forceinline__ unsigned long long ffma2(unsigned long long a, unsigned long long b, unsigned long long c){
    unsigned long long d;
    asm("fma.rn.f32x2 %0, %1, %2, %3;" : "=l"(d) : "l"(a), "l"(b), "l"(c));
    return d;
}
__device__ __forceinline__ float f2lo(unsigned long long u){ return __int_as_float((int)(unsigned)(u & 0xFFFFFFFFull)); }
__device__ __forceinline__ float f2hi(unsigned long long u){ return __int_as_float((int)(unsigned)(u >> 32)); }
__device__ __forceinline__ unsigned long long fpack(float lo, float hi){
    unsigned long long u;
    asm("mov.b64 %0, {%1, %2};" : "=l"(u) : "r"(__float_as_int(lo)), "r"(__float_as_int(hi)));
    return u;
}
__device__ __forceinline__ unsigned short hfr(float x){
    __half h = __float2half_rn(x);
    return *(unsigned short*)&h;
}
__device__ __forceinline__ unsigned smem_u32(const void* p){
    unsigned a;
    asm("{ .reg .u64 t; cvta.to.shared.u64 t, %1; cvt.u32.u64 %0, t; }" : "=r"(a) : "l"(p));
    return a;
}

// mma.sync m16n8k16 f16: D = A*B + D (fp32 accum)
#define MMA_F16(d, a0, a1, a2, a3, b0, b1) \
    asm volatile("mma.sync.aligned.m16n8k16.row.col.f32.f16.f16.f32 " \
        "{%0,%1,%2,%3}, {%4,%5,%6,%7}, {%8,%9}, {%0,%1,%2,%3};" \
        : "+f"((d)[0]), "+f"((d)[1]), "+f"((d)[2]), "+f"((d)[3]) \
        : "r"(a0), "r"(a1), "r"(a2), "r"(a3), "r"(b0), "r"(b1))

// cp.async 16B with zero-fill when src_bytes < 16
__device__ __forceinline__ void cp16(unsigned dst, const void* src, int src_bytes){
    asm volatile("cp.async.cg.shared.global [%0], [%1], 16, %2;"
        :: "r"(dst), "l"(src), "r"(src_bytes) : "memory");
}
#define CP_COMMIT() asm volatile("cp.async.commit_group;" ::: "memory")
#define CP_WAIT2()  asm volatile("cp.async.wait_group 2;" ::: "memory")

// ---------------- K0: zero scratch ----------------
__global__ void k_zero(){
    int i = blockIdx.x*blockDim.x + threadIdx.x;
    if (i < Nn) g_deg[i] = 0;
    if (i < Bn){ g_rowsum[i]=0.0; g_msum[i]=0.0; }
}

// ---------------- CSR build ----------------
__global__ void k_count(const int* __restrict__ dst){
    int e = blockIdx.x*blockDim.x + threadIdx.x;
    if (e < En) atomicAdd(&g_deg[dst[e]], 1);
}
__global__ void k_scan(){        // 1 block, 1024 threads, 10 elems/thread
    __shared__ int warp_sums[32];
    int t = threadIdx.x;
    int base = t*10;
    int local[10]; int s = 0;
    #pragma unroll
    for (int i=0;i<10;i++){ local[i]=s; s += g_deg[base+i]; }
    int lane = t&31, w = t>>5;
    int v = s;
    #pragma unroll
    for (int o=1;o<32;o<<=1){ int u=__shfl_up_sync(0xffffffffu,v,o); if(lane>=o) v+=u; }
    if (lane==31) warp_sums[w]=v;
    __syncthreads();
    if (w==0){
        int x = warp_sums[lane];
        #pragma unroll
        for (int o=1;o<32;o<<=1){ int u=__shfl_up_sync(0xffffffffu,x,o); if(lane>=o) x+=u; }
        warp_sums[lane]=x;
    }
    __syncthreads();
    int excl = v - s + (w>0 ? warp_sums[w-1] : 0);
    #pragma unroll
    for (int i=0;i<10;i++){ g_off[base+i]=excl+local[i]; g_pos[base+i]=excl+local[i]; }
    if (t==1023) g_off[Nn]=En;
}
__global__ void k_scatter(const int* __restrict__ dst){
    int e = blockIdx.x*blockDim.x + threadIdx.x;
    if (e < En){
        int p = atomicAdd(&g_pos[dst[e]], 1);
        g_eidx[p] = e;
    }
}

// ---------------- pack emb into fp16 fragment layout ----------------
__global__ void k_bpack(const float* __restrict__ emb){
    long long id = (long long)blockIdx.x*blockDim.x + threadIdx.x;
    if (id >= (long long)Vn*64) return;
    int row = (int)(id>>6), s = (int)(id&63);
    int c = s>>2, t = s&3;
    int k0 = c*16 + 2*t;
    const float* p = emb + (size_t)row*Dn;
    unsigned short h0=hfr(p[k0]), h1=hfr(p[k0+1]), h2=hfr(p[k0+8]), h3=hfr(p[k0+9]);
    uint2 o;
    o.x = ((unsigned)h1<<16) | h0;
    o.y = ((unsigned)h3<<16) | h2;
    g_bp[(size_t)row*64 + s] = o;
}

// ---------------- pack srn fp16 ----------------
__global__ void k_apack(){
    int id = blockIdx.x*blockDim.x + threadIdx.x;   // Bn*64 = 32768
    int row = id>>6, s = id&63;
    int c = s>>2, t = s&3;
    int k0 = c*16 + 2*t;
    const float* p = g_srn + (size_t)row*Dn;
    unsigned short h0=hfr(p[k0]), h1=hfr(p[k0+1]), h2=hfr(p[k0+8]), h3=hfr(p[k0+9]);
    uint2 o;
    o.x = ((unsigned)h1<<16) | h0;
    o.y = ((unsigned)h3<<16) | h2;
    g_ap[row*64 + s] = o;
}

// ---------------- K1: inverse norms of emb rows ----------------
__global__ void k_inorm(const float* __restrict__ emb){
    int row = blockIdx.x*8 + (threadIdx.x>>5);
    int lane = threadIdx.x&31;
    float ss = 0.f;
    const float* p = emb + (size_t)row*Dn;
    for (int k=lane;k<Dn;k+=32){ float x=p[k]; ss += x*x; }
    #pragma unroll
    for (int o=16;o;o>>=1) ss += __shfl_xor_sync(0xffffffffu, ss, o);
    if (lane==0) g_inorm[row] = 1.f / fmaxf(sqrtf(ss), 1e-12f);
}

// ---------------- K2: h_v = l2norm(emb[iid]) ----------------
__global__ void k_hv(const float* __restrict__ emb, const int* __restrict__ iid){
    int i = blockIdx.x*blockDim.x + threadIdx.x;
    int n = i>>8, k = i&255;
    int id = iid[n];
    g_hv[i] = emb[(size_t)id*Dn + k] * g_inorm[id];
}

// ---------------- K3: fused gather GAT ----------------
__global__ void __launch_bounds__(256) k_gat(const int* __restrict__ src, const int* __restrict__ dis,
                      const float* __restrict__ dis_emb,
                      const float* __restrict__ pi_w, const float* __restrict__ M_w){
    __shared__ float hd[Dn];
    __shared__ float se[DEGMAX];
    __shared__ int   ssrc[DEGMAX];
    int d = blockIdx.x;
    int t = threadIdx.x;
    int beg = g_off[d], end = g_off[d+1];
    int deg = end - beg; if (deg > DEGMAX) deg = DEGMAX;
    if (deg == 0){
        g_h[(size_t)d*Dn + t] = 0.f;
        return;
    }
    hd[t] = g_hv[(size_t)d*Dn + t];
    __syncthreads();
    int warp = t>>5, lane = t&31;
    for (int slot=warp; slot<deg; slot+=8){
        int e = g_eidx[beg+slot];
        int s = src[e], di = dis[e];
        const float* hs = g_hv + (size_t)s*Dn;
        const float* he = dis_emb + (size_t)di*Dn;
        float e1 = 0.f, g = 0.f;
        for (int k=lane;k<Dn;k+=32){
            float a = hs[k], b = hd[k], c = he[k];
            float p = a*b;
            e1 += p*c*pi_w[k];
            g  += p*M_w[k] + c*M_w[Dn+k];
        }
        #pragma unroll
        for (int o=16;o;o>>=1){
            e1 += __shfl_xor_sync(0xffffffffu, e1, o);
            g  += __shfl_xor_sync(0xffffffffu, g,  o);
        }
        if (lane==0){
            se[slot] = e1 * (1.f/(1.f+__expf(-g)));
            ssrc[slot] = s;
        }
    }
    __syncthreads();
    float mx = -3.4e38f;
    for (int i=0;i<deg;i++) mx = fmaxf(mx, se[i]);
    float acc = 0.f, asum = 0.f;
    for (int i=0;i<deg;i++){
        float a = __expf(se[i]-mx);
        asum += a;
        acc += a * g_hv[(size_t)ssrc[i]*Dn + t];
    }
    g_h[(size_t)d*Dn + t] = acc / asum;
}

// ---------------- K6: f = concat(h_t, last_feat) @ r_w ----------------
__global__ void k_f(const int* __restrict__ tid_, const int* __restrict__ last_idx,
                    const float* __restrict__ target_emb, const float* __restrict__ r_w){
    __shared__ float sin_[8][2*Dn];
    int b0 = blockIdx.x*8;
    int t = threadIdx.x;
    for (int idx=t; idx<8*2*Dn; idx+=256){
        int j = idx>>9, k = idx&511;
        int b = b0+j;
        float v = (k<Dn) ? target_emb[(size_t)tid_[b]*Dn + k]
                         : g_h[(size_t)last_idx[b]*Dn + (k-Dn)];
        sin_[j][k] = v;
    }
    __syncthreads();
    float acc[8] = {0,0,0,0,0,0,0,0};
    int d = t;
    for (int k=0;k<2*Dn;k++){
        float w = r_w[(size_t)k*Dn + d];
        #pragma unroll
        for (int j=0;j<8;j++) acc[j] += sin_[j][k]*w;
    }
    #pragma unroll
    for (int j=0;j<8;j++) g_f[(size_t)(b0+j)*Dn + d] = acc[j];
}

// ---------------- K7: eagg + m-scalar ----------------
__global__ void __launch_bounds__(256) k_eagg(const int* __restrict__ pid, const int* __restrict__ agg_dst,
                        const float* __restrict__ pos_emb, const float* __restrict__ q_w){
    __shared__ __align__(16) float sT[2*Dn][20];
    __shared__ int s_pid[16], s_sess[16];
    __shared__ float sred[8][16];
    int j0 = blockIdx.x*16;
    int t = threadIdx.x;
    if (t<16){ s_pid[t] = pid[j0+t]; s_sess[t] = agg_dst[j0+t]; }
    __syncthreads();
    for (int idx=t; idx<16*2*Dn; idx+=256){
        int j = idx>>9, k = idx&511;
        float v = (k<Dn) ? g_h[(size_t)(j0+j)*Dn + k]
                         : pos_emb[(size_t)s_pid[j]*Dn + (k-Dn)];
        sT[k][j] = v;
    }
    __syncthreads();

    unsigned long long acc[8];
    #pragma unroll
    for (int p=0;p<8;p++) acc[p]=0ull;
    int d = t;
    #pragma unroll 4
    for (int k=0;k<2*Dn;k++){
        float w = q_w[(size_t)k*Dn + d];
        unsigned long long wd = fpack(w,w);
        const ulonglong2* sp = (const ulonglong2*)&sT[k][0];
        #pragma unroll
        for (int q=0;q<4;q++){
            ulonglong2 pr = sp[q];
            acc[2*q+0] = ffma2(pr.x, wd, acc[2*q+0]);
            acc[2*q+1] = ffma2(pr.y, wd, acc[2*q+1]);
        }
    }
    float partial[16];
    #pragma unroll
    for (int p=0;p<8;p++){
        float t0 = tanhf(f2lo(acc[p]));
        float t1 = tanhf(f2hi(acc[p]));
        int j = 2*p;
        partial[j]   = t0 * g_f[(size_t)s_sess[j]*Dn + d];
        partial[j+1] = t1 * g_f[(size_t)s_sess[j+1]*Dn + d];
    }
    int w = t>>5, lane = t&31;
    #pragma unroll
    for (int j=0;j<16;j++){
        float p = partial[j];
        #pragma unroll
        for (int o=16;o;o>>=1) p += __shfl_xor_sync(0xffffffffu, p, o);
        if (lane==0) sred[w][j] = p;
    }
    __syncthreads();
    if (t<16){
        float s=0.f;
        #pragma unroll
        for (int ww=0;ww<8;ww++) s += sred[ww][t];
        g_mscal[j0+t] = s;
    }
}

// ---------------- K8: sr per session + l2norm ----------------
__global__ void k_sr(){
    __shared__ float sm[Sn];
    __shared__ float sred[8];
    int b = blockIdx.x, t = threadIdx.x;
    if (t<Sn) sm[t] = g_mscal[b*Sn + t];
    __syncthreads();
    float acc = 0.f;
    #pragma unroll
    for (int s=0;s<Sn;s++) acc += g_h[(size_t)(b*Sn+s)*Dn + t]*sm[s];
    float ss = acc*acc;
    #pragma unroll
    for (int o=16;o;o>>=1) ss += __shfl_xor_sync(0xffffffffu, ss, o);
    if ((t&31)==0) sred[t>>5] = ss;
    __syncthreads();
    float tot = 0.f;
    #pragma unroll
    for (int w=0;w<8;w++) tot += sred[w];
    g_srn[(size_t)b*Dn + t] = acc / fmaxf(sqrtf(tot), 1e-12f);
}

// ---------------- K9: phi head ----------------
__global__ void k_phi(const float* __restrict__ sc1_w, const float* __restrict__ sc1_b,
                      const float* __restrict__ sc2_w){
    __shared__ float ssr[8][Dn];
    __shared__ float s_p[8][2];
    int b0 = blockIdx.x*8;
    int t = threadIdx.x;
    for (int idx=t; idx<8*Dn; idx+=256){
        int j = idx>>8, k = idx&255;
        ssr[j][k] = g_srn[(size_t)(b0+j)*Dn + k];
    }
    if (t<16) s_p[t>>1][t&1] = 0.f;
    __syncthreads();
    float acc[8] = {0,0,0,0,0,0,0,0};
    int d = t;
    for (int k=0;k<Dn;k++){
        float w = sc1_w[(size_t)k*Dn + d];
        #pragma unroll
        for (int j=0;j<8;j++) acc[j] += ssr[j][k]*w;
    }
    float bb = sc1_b[d], w0 = sc2_w[d*2], w1 = sc2_w[d*2+1];
    int lane = t&31;
    #pragma unroll
    for (int j=0;j<8;j++){
        float hid = fmaxf(acc[j]+bb, 0.f);
        float p0 = hid*w0, p1 = hid*w1;
        #pragma unroll
        for (int o=16;o;o>>=1){
            p0 += __shfl_xor_sync(0xffffffffu, p0, o);
            p1 += __shfl_xor_sync(0xffffffffu, p1, o);
        }
        if (lane==0){ atomicAdd(&s_p[j][0], p0); atomicAdd(&s_p[j][1], p1); }
    }
    __syncthreads();
    if (t<8){
        float a0 = s_p[t][0], a1 = s_p[t][1];
        float m = fmaxf(a0,a1);
        float lse = m + logf(__expf(a0-m)+__expf(a1-m));
        g_logphi[(b0+t)*2+0] = a0 - lse;
        g_logphi[(b0+t)*2+1] = a1 - lse;
    }
}

// ---------------- K10: masked (in-session) logits + msum ----------------
__global__ void k_masked(const int* __restrict__ iid, const float* __restrict__ emb){
    __shared__ int iids[Sn];
    __shared__ float s_sr[Dn];
    int b = blockIdx.x, t = threadIdx.x;
    if (t<Sn) iids[t] = iid[b*Sn+t];
    if (t<Dn) s_sr[t] = g_srn[(size_t)b*Dn + t];
    __syncthreads();
    int warp = t>>5, lane = t&31;
    for (int slot=warp; slot<Sn; slot+=8){
        int v = iids[slot];
        bool dup = false;
        for (int j=0;j<slot;j++) if (iids[j]==v) { dup=true; break; }
        if (dup){
            if (lane==0) g_mask_v[b*Sn+slot] = -1;
            continue;
        }
        const float* ev = emb + (size_t)v*Dn;
        float dot = 0.f;
        for (int k=lane;k<Dn;k+=32) dot += s_sr[k]*ev[k];
        #pragma unroll
        for (int o=16;o;o>>=1) dot += __shfl_xor_sync(0xffffffffu, dot, o);
        if (lane==0){
            float l = dot * g_inorm[v] * 12.f;
            g_mask_v[b*Sn+slot] = v;
            g_mask_l[b*Sn+slot] = l;
            atomicAdd(&g_msum[b], (double)__expf(l-12.f));
        }
    }
}

// ---------------- K11: cp.async-pipelined smem-staged fp16 GEMM ----------------
// CTA 128M x 128N, 8 warps (4x2), warp tile 32x64, 16 K-chunks, 4-stage ring.
#define NSTAGE 4
__global__ void __launch_bounds__(256,2) k_gemm_mma(float* __restrict__ out){
    // stage layout: [stage][row 0..127][slot 0..3] uint2  (32 B per row per stage)
    __shared__ __align__(16) uint2 sA[NSTAGE][128][4];
    __shared__ __align__(16) uint2 sB[NSTAGE][128][4];
    int tid = threadIdx.x;
    int w = tid>>5, lane = tid&31;
    int g = lane>>2, t = lane&3;
    int wm = w>>1, wn = w&1;
    int m0 = blockIdx.x*128;       // 0..3
    int v0 = blockIdx.y*128;       // 0..781

    unsigned sAu = smem_u32(&sA[0][0][0]);
    unsigned sBu = smem_u32(&sB[0][0][0]);

    // staging indices: each thread copies one 16B half-row of A and of B per chunk
    int srow = tid>>1, shalf = tid&1;
    int svrow = v0 + srow;
    int bbytes = (svrow < Vn) ? 16 : 0;
    const uint2* asrc0 = g_ap + (m0+srow)*64 + shalf*2;
    const uint2* bsrc0 = g_bp + (size_t)((svrow<Vn)?svrow:0)*64 + shalf*2;
    unsigned adst0 = sAu + (unsigned)((srow*4 + shalf*2)*8);
    unsigned bdst0 = sBu + (unsigned)((srow*4 + shalf*2)*8);

    float acc[2][8][4];
    #pragma unroll
    for (int mi=0;mi<2;mi++)
        #pragma unroll
        for (int ni=0;ni<8;ni++)
            #pragma unroll
            for (int q=0;q<4;q++) acc[mi][ni][q]=0.f;

    // prologue: stages 0..NSTAGE-2 <- chunks 0..NSTAGE-2
    #pragma unroll
    for (int s=0;s<NSTAGE-1;s++){
        cp16(adst0 + (unsigned)(s*4096), asrc0 + s*4, 16);
        cp16(bdst0 + (unsigned)(s*4096), bsrc0 + s*4, bbytes);
        CP_COMMIT();
    }

    for (int c=0; c<16; c++){
        CP_WAIT2();
        __syncthreads();
        int st = c & (NSTAGE-1);
        // fragment loads from smem (conflict-free per half-warp phase)
        uint2 A0[2], A1[2], Bf[8];
        #pragma unroll
        for (int mi=0;mi<2;mi++){
            A0[mi] = sA[st][wm*32 + mi*16 + g][t];
            A1[mi] = sA[st][wm*32 + mi*16 + 8 + g][t];
        }
        #pragma unroll
        for (int ni=0;ni<8;ni++)
            Bf[ni] = sB[st][wn*64 + ni*8 + g][t];
        #pragma unroll
        for (int ni=0;ni<8;ni++){
            #pragma unroll
            for (int mi=0;mi<2;mi++){
                MMA_F16(acc[mi][ni], A0[mi].x, A1[mi].x, A0[mi].y, A1[mi].y, Bf[ni].x, Bf[ni].y);
            }
        }
        __syncthreads();
        int cn = c + NSTAGE - 1;
        if (cn < 16){
            int sn = cn & (NSTAGE-1);
            cp16(adst0 + (unsigned)(sn*4096), asrc0 + cn*4, 16);
            cp16(bdst0 + (unsigned)(sn*4096), bsrc0 + cn*4, bbytes);
        }
        CP_COMMIT();
    }

    // epilogue: scale by 12*inorm, store, accumulate exp row sums
    float rsum[4] = {0.f,0.f,0.f,0.f};
    #pragma unroll
    for (int mi=0;mi<2;mi++){
        int r0 = m0 + wm*32 + mi*16 + g;
        #pragma unroll
        for (int ni=0;ni<8;ni++){
            int col = v0 + wn*64 + ni*8 + 2*t;
            if (col < Vn){
                float s0 = 12.f*g_inorm[col], s1 = 12.f*g_inorm[col+1];
                float v00 = acc[mi][ni][0]*s0, v01 = acc[mi][ni][1]*s1;
                float v10 = acc[mi][ni][2]*s0, v11 = acc[mi][ni][3]*s1;
                float2* p0 = (float2*)(out + (size_t)r0*Vn + col);
                float2* p1 = (float2*)(out + (size_t)(r0+8)*Vn + col);
                __stcs(p0, make_float2(v00, v01));
                __stcs(p1, make_float2(v10, v11));
                rsum[mi*2+0] += __expf(v00-12.f) + __expf(v01-12.f);
                rsum[mi*2+1] += __expf(v10-12.f) + __expf(v11-12.f);
            }
        }
    }
    #pragma unroll
    for (int o=1;o<4;o<<=1)
        #pragma unroll
        for (int j=0;j<4;j++) rsum[j] += __shfl_xor_sync(0xffffffffu, rsum[j], o);
    if (t==0){
        #pragma unroll
        for (int j=0;j<4;j++){
            int row = m0 + wm*32 + (j>>1)*16 + (j&1)*8 + g;
            atomicAdd(&g_rowsum[row], (double)rsum[j]);
        }
    }
}

// ---------------- K12: per-row shift for unmasked entries ----------------
__global__ void k_finalize(float* __restrict__ out){
    __shared__ float s_shift;
    int row = blockIdx.y;
    if (threadIdx.x==0){
        double sex = g_rowsum[row] - g_msum[row];
        s_shift = g_logphi[row*2+1] - (float)(12.0 + log(sex));
    }
    __syncthreads();
    float sh = s_shift;
    int i = blockIdx.x*blockDim.x + threadIdx.x;
    if (i < Vn/4){
        float4* p = (float4*)(out + (size_t)row*Vn) + i;
        float4 o = __ldcs(p);
        o.x += sh; o.y += sh; o.z += sh; o.w += sh;
        __stcs(p, o);
    }
}

// ---------------- K13: overwrite masked entries ----------------
__global__ void k_fixup(float* __restrict__ out){
    int b = blockIdx.x, s = threadIdx.x;
    if (s >= Sn) return;
    int v = g_mask_v[b*Sn+s];
    if (v < 0) return;
    float lse_in = (float)(12.0 + log(g_msum[b]));
    out[(size_t)b*Vn + v] = g_mask_l[b*Sn+s] - lse_in + g_logphi[b*2+0];
}

// ---------------- launch ----------------
extern "C" void kernel_launch(void* const* d_in, const int* in_sizes, int n_in,
                              void* d_out, int out_size){
    const int* iid      = (const int*)d_in[0];
    const int* src      = (const int*)d_in[1];
    const int* dst      = (const int*)d_in[2];
    const int* dis      = (const int*)d_in[3];
    const int* pid      = (const int*)d_in[4];
    const int* agg_dst  = (const int*)d_in[6];
    const int* tid_     = (const int*)d_in[7];
    const int* last_idx = (const int*)d_in[8];
    const float* emb        = (const float*)d_in[9];
    const float* pos_emb    = (const float*)d_in[10];
    const float* dis_emb    = (const float*)d_in[11];
    const float* target_emb = (const float*)d_in[12];
    const float* pi_w  = (const float*)d_in[13];
    const float* M_w   = (const float*)d_in[14];
    const float* q_w   = (const float*)d_in[15];
    const float* r_w   = (const float*)d_in[16];
    const float* sc1_w = (const float*)d_in[17];
    const float* sc1_b = (const float*)d_in[18];
    const float* sc2_w = (const float*)d_in[19];
    float* out = (float*)d_out;

    k_zero<<<(Nn+255)/256,256>>>();                      // 1
    k_count<<<En/256,256>>>(dst);                        // 2
    k_scan<<<1,1024>>>();                                // 3
    k_bpack<<<(int)(((long long)Vn*64+255)/256),256>>>(emb);  // 4 (profiled slot)
    k_scatter<<<En/256,256>>>(dst);                      // 5
    k_inorm<<<Vn/8,256>>>(emb);                          // 6
    k_hv<<<(Nn*Dn)/256,256>>>(emb, iid);                 // 7
    k_gat<<<Nn,256>>>(src,dis,dis_emb,pi_w,M_w);         // 8
    k_f<<<Bn/8,256>>>(tid_,last_idx,target_emb,r_w);
    k_eagg<<<Nn/16,256>>>(pid,agg_dst,pos_emb,q_w);
    k_sr<<<Bn,256>>>();
    k_apack<<<Bn*64/256,256>>>();
    k_phi<<<Bn/8,256>>>(sc1_w,sc1_b,sc2_w);
    k_masked<<<Bn,256>>>(iid, emb);
    dim3 gg(4, (Vn+127)/128);
    k_gemm_mma<<<gg, 256>>>(out);
    dim3 gf((Vn/4 + 255)/256, Bn);
    k_finalize<<<gf,256>>>(out);
    k_fixup<<<Bn,32>>>(out);
}

// round 11
// speedup vs baseline: 1.8979x; 1.0065x over previous
#include <cuda_runtime.h>
#include <cuda_bf16.h>
#include <cuda_fp16.h>
#include <math.h>
#include <stdint.h>

#define Vn 100000
#define Dn 256
#define Bn 512
#define Sn 20
#define Nn (Bn*Sn)      // 10240
#define En (8*Nn)       // 81920
#define DEGMAX 128
#define SHIFT 4.0f

// ---------------- scratch (device globals; no allocation allowed) ----------------
__device__ float g_inorm[Vn];
__device__ float g_hv[Nn*Dn];
__device__ float g_h[Nn*Dn];
__device__ float g_f[Bn*Dn];
__device__ float g_mscal[Nn];
__device__ float g_srn[Bn*Dn];
__device__ float g_logphi[Bn*2];
__device__ double g_rowsum[Bn];
__device__ double g_msum[Bn];
__device__ int   g_mask_v[Bn*Sn];
__device__ float g_mask_l[Bn*Sn];
// CSR
__device__ int g_deg[Nn];
__device__ int g_off[Nn+1];
__device__ int g_pos[Nn];
__device__ int g_eidx[En];
// packed GEMM operands: per row, 64 slots; slot s = c*4+t (chunk c of K=16, quad-thread t), k0 = c*16+2t
// uint2 = { f16x2(k0,k0+1), f16x2(k0+8,k0+9) }   single-term fp16 for both A and B
__device__ uint2 g_bp[(size_t)Vn*64];   // 51.2 MB
__device__ uint2 g_ap[Bn*64];           // 0.25 MB

// ---------------- helpers ----------------
__device__ __forceinline__ unsigned long long ffma2(unsigned long long a, unsigned long long b, unsigned long long c){
    unsigned long long d;
    asm("fma.rn.f32x2 %0, %1, %2, %3;" : "=l"(d) : "l"(a), "l"(b), "l"(c));
    return d;
}
__device__ __forceinline__ float f2lo(unsigned long long u){ return __int_as_float((int)(unsigned)(u & 0xFFFFFFFFull)); }
__device__ __forceinline__ float f2hi(unsigned long long u){ return __int_as_float((int)(unsigned)(u >> 32)); }
__device__ __forceinline__ unsigned long long fpack(float lo, float hi){
    unsigned long long u;
    asm("mov.b64 %0, {%1, %2};" : "=l"(u) : "r"(__float_as_int(lo)), "r"(__float_as_int(hi)));
    return u;
}
__device__ __forceinline__ unsigned short hfr(float x){
    __half h = __float2half_rn(x);
    return *(unsigned short*)&h;
}
__device__ __forceinline__ unsigned smem_u32(const void* p){
    unsigned a;
    asm("{ .reg .u64 t; cvta.to.shared.u64 t, %1; cvt.u32.u64 %0, t; }" : "=r"(a) : "l"(p));
    return a;
}
// sum of exp2 of two fp32 exponents via f16x2 MUFU (one MUFU per pair)
__device__ __forceinline__ float exp2_pair_sum(float y0, float y1){
    unsigned p, e;
    asm("cvt.rn.f16x2.f32 %0, %1, %2;" : "=r"(p) : "f"(y1), "f"(y0));
    asm("ex2.approx.f16x2 %0, %1;" : "=r"(e) : "r"(p));
    __half2 he = *reinterpret_cast<__half2*>(&e);
    float2 fe = __half22float2(he);
    return fe.x + fe.y;
}

// mma.sync m16n8k16 f16: D = A*B + D (fp32 accum)
#define MMA_F16(d, a0, a1, a2, a3, b0, b1) \
    asm volatile("mma.sync.aligned.m16n8k16.row.col.f32.f16.f16.f32 " \
        "{%0,%1,%2,%3}, {%4,%5,%6,%7}, {%8,%9}, {%0,%1,%2,%3};" \
        : "+f"((d)[0]), "+f"((d)[1]), "+f"((d)[2]), "+f"((d)[3]) \
        : "r"(a0), "r"(a1), "r"(a2), "r"(a3), "r"(b0), "r"(b1))

// cp.async 16B with zero-fill when src_bytes < 16
__device__ __forceinline__ void cp16(unsigned dst, const void* src, int src_bytes){
    asm volatile("cp.async.cg.shared.global [%0], [%1], 16, %2;"
        :: "r"(dst), "l"(src), "r"(src_bytes) : "memory");
}
#define CP_COMMIT() asm volatile("cp.async.commit_group;" ::: "memory")
#define CP_WAIT2()  asm volatile("cp.async.wait_group 2;" ::: "memory")

// ---------------- K0: zero scratch ----------------
__global__ void k_zero(){
    int i = blockIdx.x*blockDim.x + threadIdx.x;
    if (i < Nn) g_deg[i] = 0;
    if (i < Bn){ g_rowsum[i]=0.0; g_msum[i]=0.0; }
}

// ---------------- CSR build ----------------
__global__ void k_count(const int* __restrict__ dst){
    int e = blockIdx.x*blockDim.x + threadIdx.x;
    if (e < En) atomicAdd(&g_deg[dst[e]], 1);
}
__global__ void k_scan(){        // 1 block, 1024 threads, 10 elems/thread
    __shared__ int warp_sums[32];
    int t = threadIdx.x;
    int base = t*10;
    int local[10]; int s = 0;
    #pragma unroll
    for (int i=0;i<10;i++){ local[i]=s; s += g_deg[base+i]; }
    int lane = t&31, w = t>>5;
    int v = s;
    #pragma unroll
    for (int o=1;o<32;o<<=1){ int u=__shfl_up_sync(0xffffffffu,v,o); if(lane>=o) v+=u; }
    if (lane==31) warp_sums[w]=v;
    __syncthreads();
    if (w==0){
        int x = warp_sums[lane];
        #pragma unroll
        for (int o=1;o<32;o<<=1){ int u=__shfl_up_sync(0xffffffffu,x,o); if(lane>=o) x+=u; }
        warp_sums[lane]=x;
    }
    __syncthreads();
    int excl = v - s + (w>0 ? warp_sums[w-1] : 0);
    #pragma unroll
    for (int i=0;i<10;i++){ g_off[base+i]=excl+local[i]; g_pos[base+i]=excl+local[i]; }
    if (t==1023) g_off[Nn]=En;
}
__global__ void k_scatter(const int* __restrict__ dst){
    int e = blockIdx.x*blockDim.x + threadIdx.x;
    if (e < En){
        int p = atomicAdd(&g_pos[dst[e]], 1);
        g_eidx[p] = e;
    }
}

// ---------------- pack emb into fp16 fragment layout ----------------
__global__ void k_bpack(const float* __restrict__ emb){
    long long id = (long long)blockIdx.x*blockDim.x + threadIdx.x;
    if (id >= (long long)Vn*64) return;
    int row = (int)(id>>6), s = (int)(id&63);
    int c = s>>2, t = s&3;
    int k0 = c*16 + 2*t;
    const float* p = emb + (size_t)row*Dn;
    unsigned short h0=hfr(p[k0]), h1=hfr(p[k0+1]), h2=hfr(p[k0+8]), h3=hfr(p[k0+9]);
    uint2 o;
    o.x = ((unsigned)h1<<16) | h0;
    o.y = ((unsigned)h3<<16) | h2;
    g_bp[(size_t)row*64 + s] = o;
}

// ---------------- pack srn fp16 ----------------
__global__ void k_apack(){
    int id = blockIdx.x*blockDim.x + threadIdx.x;   // Bn*64 = 32768
    int row = id>>6, s = id&63;
    int c = s>>2, t = s&3;
    int k0 = c*16 + 2*t;
    const float* p = g_srn + (size_t)row*Dn;
    unsigned short h0=hfr(p[k0]), h1=hfr(p[k0+1]), h2=hfr(p[k0+8]), h3=hfr(p[k0+9]);
    uint2 o;
    o.x = ((unsigned)h1<<16) | h0;
    o.y = ((unsigned)h3<<16) | h2;
    g_ap[row*64 + s] = o;
}

// ---------------- K1: inverse norms of emb rows ----------------
__global__ void k_inorm(const float* __restrict__ emb){
    int row = blockIdx.x*8 + (threadIdx.x>>5);
    int lane = threadIdx.x&31;
    float ss = 0.f;
    const float* p = emb + (size_t)row*Dn;
    for (int k=lane;k<Dn;k+=32){ float x=p[k]; ss += x*x; }
    #pragma unroll
    for (int o=16;o;o>>=1) ss += __shfl_xor_sync(0xffffffffu, ss, o);
    if (lane==0) g_inorm[row] = 1.f / fmaxf(sqrtf(ss), 1e-12f);
}

// ---------------- K2: h_v = l2norm(emb[iid]) ----------------
__global__ void k_hv(const float* __restrict__ emb, const int* __restrict__ iid){
    int i = blockIdx.x*blockDim.x + threadIdx.x;
    int n = i>>8, k = i&255;
    int id = iid[n];
    g_hv[i] = emb[(size_t)id*Dn + k] * g_inorm[id];
}

// ---------------- K3: fused gather GAT ----------------
__global__ void __launch_bounds__(256) k_gat(const int* __restrict__ src, const int* __restrict__ dis,
                      const float* __restrict__ dis_emb,
                      const float* __restrict__ pi_w, const float* __restrict__ M_w){
    __shared__ float hd[Dn];
    __shared__ float se[DEGMAX];
    __shared__ int   ssrc[DEGMAX];
    int d = blockIdx.x;
    int t = threadIdx.x;
    int beg = g_off[d], end = g_off[d+1];
    int deg = end - beg; if (deg > DEGMAX) deg = DEGMAX;
    if (deg == 0){
        g_h[(size_t)d*Dn + t] = 0.f;
        return;
    }
    hd[t] = g_hv[(size_t)d*Dn + t];
    __syncthreads();
    int warp = t>>5, lane = t&31;
    for (int slot=warp; slot<deg; slot+=8){
        int e = g_eidx[beg+slot];
        int s = src[e], di = dis[e];
        const float* hs = g_hv + (size_t)s*Dn;
        const float* he = dis_emb + (size_t)di*Dn;
        float e1 = 0.f, g = 0.f;
        for (int k=lane;k<Dn;k+=32){
            float a = hs[k], b = hd[k], c = he[k];
            float p = a*b;
            e1 += p*c*pi_w[k];
            g  += p*M_w[k] + c*M_w[Dn+k];
        }
        #pragma unroll
        for (int o=16;o;o>>=1){
            e1 += __shfl_xor_sync(0xffffffffu, e1, o);
            g  += __shfl_xor_sync(0xffffffffu, g,  o);
        }
        if (lane==0){
            se[slot] = e1 * (1.f/(1.f+__expf(-g)));
            ssrc[slot] = s;
        }
    }
    __syncthreads();
    float mx = -3.4e38f;
    for (int i=0;i<deg;i++) mx = fmaxf(mx, se[i]);
    float acc = 0.f, asum = 0.f;
    for (int i=0;i<deg;i++){
        float a = __expf(se[i]-mx);
        asum += a;
        acc += a * g_hv[(size_t)ssrc[i]*Dn + t];
    }
    g_h[(size_t)d*Dn + t] = acc / asum;
}

// ---------------- K6: f = concat(h_t, last_feat) @ r_w ----------------
__global__ void k_f(const int* __restrict__ tid_, const int* __restrict__ last_idx,
                    const float* __restrict__ target_emb, const float* __restrict__ r_w){
    __shared__ float sin_[8][2*Dn];
    int b0 = blockIdx.x*8;
    int t = threadIdx.x;
    for (int idx=t; idx<8*2*Dn; idx+=256){
        int j = idx>>9, k = idx&511;
        int b = b0+j;
        float v = (k<Dn) ? target_emb[(size_t)tid_[b]*Dn + k]
                         : g_h[(size_t)last_idx[b]*Dn + (k-Dn)];
        sin_[j][k] = v;
    }
    __syncthreads();
    float acc[8] = {0,0,0,0,0,0,0,0};
    int d = t;
    for (int k=0;k<2*Dn;k++){
        float w = r_w[(size_t)k*Dn + d];
        #pragma unroll
        for (int j=0;j<8;j++) acc[j] += sin_[j][k]*w;
    }
    #pragma unroll
    for (int j=0;j<8;j++) g_f[(size_t)(b0+j)*Dn + d] = acc[j];
}

// ---------------- K7: eagg + m-scalar ----------------
__global__ void __launch_bounds__(256) k_eagg(const int* __restrict__ pid, const int* __restrict__ agg_dst,
                        const float* __restrict__ pos_emb, const float* __restrict__ q_w){
    __shared__ __align__(16) float sT[2*Dn][20];
    __shared__ int s_pid[16], s_sess[16];
    __shared__ float sred[8][16];
    int j0 = blockIdx.x*16;
    int t = threadIdx.x;
    if (t<16){ s_pid[t] = pid[j0+t]; s_sess[t] = agg_dst[j0+t]; }
    __syncthreads();
    for (int idx=t; idx<16*2*Dn; idx+=256){
        int j = idx>>9, k = idx&511;
        float v = (k<Dn) ? g_h[(size_t)(j0+j)*Dn + k]
                         : pos_emb[(size_t)s_pid[j]*Dn + (k-Dn)];
        sT[k][j] = v;
    }
    __syncthreads();

    unsigned long long acc[8];
    #pragma unroll
    for (int p=0;p<8;p++) acc[p]=0ull;
    int d = t;
    #pragma unroll 4
    for (int k=0;k<2*Dn;k++){
        float w = q_w[(size_t)k*Dn + d];
        unsigned long long wd = fpack(w,w);
        const ulonglong2* sp = (const ulonglong2*)&sT[k][0];
        #pragma unroll
        for (int q=0;q<4;q++){
            ulonglong2 pr = sp[q];
            acc[2*q+0] = ffma2(pr.x, wd, acc[2*q+0]);
            acc[2*q+1] = ffma2(pr.y, wd, acc[2*q+1]);
        }
    }
    float partial[16];
    #pragma unroll
    for (int p=0;p<8;p++){
        float t0 = tanhf(f2lo(acc[p]));
        float t1 = tanhf(f2hi(acc[p]));
        int j = 2*p;
        partial[j]   = t0 * g_f[(size_t)s_sess[j]*Dn + d];
        partial[j+1] = t1 * g_f[(size_t)s_sess[j+1]*Dn + d];
    }
    int w = t>>5, lane = t&31;
    #pragma unroll
    for (int j=0;j<16;j++){
        float p = partial[j];
        #pragma unroll
        for (int o=16;o;o>>=1) p += __shfl_xor_sync(0xffffffffu, p, o);
        if (lane==0) sred[w][j] = p;
    }
    __syncthreads();
    if (t<16){
        float s=0.f;
        #pragma unroll
        for (int ww=0;ww<8;ww++) s += sred[ww][t];
        g_mscal[j0+t] = s;
    }
}

// ---------------- K8: sr per session + l2norm ----------------
__global__ void k_sr(){
    __shared__ float sm[Sn];
    __shared__ float sred[8];
    int b = blockIdx.x, t = threadIdx.x;
    if (t<Sn) sm[t] = g_mscal[b*Sn + t];
    __syncthreads();
    float acc = 0.f;
    #pragma unroll
    for (int s=0;s<Sn;s++) acc += g_h[(size_t)(b*Sn+s)*Dn + t]*sm[s];
    float ss = acc*acc;
    #pragma unroll
    for (int o=16;o;o>>=1) ss += __shfl_xor_sync(0xffffffffu, ss, o);
    if ((t&31)==0) sred[t>>5] = ss;
    __syncthreads();
    float tot = 0.f;
    #pragma unroll
    for (int w=0;w<8;w++) tot += sred[w];
    g_srn[(size_t)b*Dn + t] = acc / fmaxf(sqrtf(tot), 1e-12f);
}

// ---------------- K9: phi head ----------------
__global__ void k_phi(const float* __restrict__ sc1_w, const float* __restrict__ sc1_b,
                      const float* __restrict__ sc2_w){
    __shared__ float ssr[8][Dn];
    __shared__ float s_p[8][2];
    int b0 = blockIdx.x*8;
    int t = threadIdx.x;
    for (int idx=t; idx<8*Dn; idx+=256){
        int j = idx>>8, k = idx&255;
        ssr[j][k] = g_srn[(size_t)(b0+j)*Dn + k];
    }
    if (t<16) s_p[t>>1][t&1] = 0.f;
    __syncthreads();
    float acc[8] = {0,0,0,0,0,0,0,0};
    int d = t;
    for (int k=0;k<Dn;k++){
        float w = sc1_w[(size_t)k*Dn + d];
        #pragma unroll
        for (int j=0;j<8;j++) acc[j] += ssr[j][k]*w;
    }
    float bb = sc1_b[d], w0 = sc2_w[d*2], w1 = sc2_w[d*2+1];
    int lane = t&31;
    #pragma unroll
    for (int j=0;j<8;j++){
        float hid = fmaxf(acc[j]+bb, 0.f);
        float p0 = hid*w0, p1 = hid*w1;
        #pragma unroll
        for (int o=16;o;o>>=1){
            p0 += __shfl_xor_sync(0xffffffffu, p0, o);
            p1 += __shfl_xor_sync(0xffffffffu, p1, o);
        }
        if (lane==0){ atomicAdd(&s_p[j][0], p0); atomicAdd(&s_p[j][1], p1); }
    }
    __syncthreads();
    if (t<8){
        float a0 = s_p[t][0], a1 = s_p[t][1];
        float m = fmaxf(a0,a1);
        float lse = m + logf(__expf(a0-m)+__expf(a1-m));
        g_logphi[(b0+t)*2+0] = a0 - lse;
        g_logphi[(b0+t)*2+1] = a1 - lse;
    }
}

// ---------------- K10: masked (in-session) logits + msum ----------------
__global__ void k_masked(const int* __restrict__ iid, const float* __restrict__ emb){
    __shared__ int iids[Sn];
    __shared__ float s_sr[Dn];
    int b = blockIdx.x, t = threadIdx.x;
    if (t<Sn) iids[t] = iid[b*Sn+t];
    if (t<Dn) s_sr[t] = g_srn[(size_t)b*Dn + t];
    __syncthreads();
    int warp = t>>5, lane = t&31;
    for (int slot=warp; slot<Sn; slot+=8){
        int v = iids[slot];
        bool dup = false;
        for (int j=0;j<slot;j++) if (iids[j]==v) { dup=true; break; }
        if (dup){
            if (lane==0) g_mask_v[b*Sn+slot] = -1;
            continue;
        }
        const float* ev = emb + (size_t)v*Dn;
        float dot = 0.f;
        for (int k=lane;k<Dn;k+=32) dot += s_sr[k]*ev[k];
        #pragma unroll
        for (int o=16;o;o>>=1) dot += __shfl_xor_sync(0xffffffffu, dot, o);
        if (lane==0){
            float l = dot * g_inorm[v] * 12.f;
            g_mask_v[b*Sn+slot] = v;
            g_mask_l[b*Sn+slot] = l;
            atomicAdd(&g_msum[b], (double)__expf(l-SHIFT));
        }
    }
}

// ---------------- K11: cp.async-pipelined smem-staged fp16 GEMM, f16x2 exp epilogue ----------------
// CTA 128M x 128N, 8 warps (4x2), warp tile 32x64, 16 K-chunks, 4-stage ring.
#define NSTAGE 4
__global__ void __launch_bounds__(256,2) k_gemm_mma(float* __restrict__ out){
    __shared__ __align__(16) uint2 sA[NSTAGE][128][4];
    __shared__ __align__(16) uint2 sB[NSTAGE][128][4];
    int tid = threadIdx.x;
    int w = tid>>5, lane = tid&31;
    int g = lane>>2, t = lane&3;
    int wm = w>>1, wn = w&1;
    int m0 = blockIdx.x*128;       // 0..3
    int v0 = blockIdx.y*128;       // 0..781

    unsigned sAu = smem_u32(&sA[0][0][0]);
    unsigned sBu = smem_u32(&sB[0][0][0]);

    int srow = tid>>1, shalf = tid&1;
    int svrow = v0 + srow;
    int bbytes = (svrow < Vn) ? 16 : 0;
    const uint2* asrc0 = g_ap + (m0+srow)*64 + shalf*2;
    const uint2* bsrc0 = g_bp + (size_t)((svrow<Vn)?svrow:0)*64 + shalf*2;
    unsigned adst0 = sAu + (unsigned)((srow*4 + shalf*2)*8);
    unsigned bdst0 = sBu + (unsigned)((srow*4 + shalf*2)*8);

    float acc[2][8][4];
    #pragma unroll
    for (int mi=0;mi<2;mi++)
        #pragma unroll
        for (int ni=0;ni<8;ni++)
            #pragma unroll
            for (int q=0;q<4;q++) acc[mi][ni][q]=0.f;

    #pragma unroll
    for (int s=0;s<NSTAGE-1;s++){
        cp16(adst0 + (unsigned)(s*4096), asrc0 + s*4, 16);
        cp16(bdst0 + (unsigned)(s*4096), bsrc0 + s*4, bbytes);
        CP_COMMIT();
    }

    for (int c=0; c<16; c++){
        CP_WAIT2();
        __syncthreads();
        int st = c & (NSTAGE-1);
        uint2 A0[2], A1[2], Bf[8];
        #pragma unroll
        for (int mi=0;mi<2;mi++){
            A0[mi] = sA[st][wm*32 + mi*16 + g][t];
            A1[mi] = sA[st][wm*32 + mi*16 + 8 + g][t];
        }
        #pragma unroll
        for (int ni=0;ni<8;ni++)
            Bf[ni] = sB[st][wn*64 + ni*8 + g][t];
        #pragma unroll
        for (int ni=0;ni<8;ni++){
            #pragma unroll
            for (int mi=0;mi<2;mi++){
                MMA_F16(acc[mi][ni], A0[mi].x, A1[mi].x, A0[mi].y, A1[mi].y, Bf[ni].x, Bf[ni].y);
            }
        }
        __syncthreads();
        int cn = c + NSTAGE - 1;
        if (cn < 16){
            int sn = cn & (NSTAGE-1);
            cp16(adst0 + (unsigned)(sn*4096), asrc0 + cn*4, 16);
            cp16(bdst0 + (unsigned)(sn*4096), bsrc0 + cn*4, bbytes);
        }
        CP_COMMIT();
    }

    // epilogue: scale by 12*inorm, store, exp2-pair row sums (shift = SHIFT)
    const float L2E = 1.44269504f;
    float rsum[4] = {0.f,0.f,0.f,0.f};
    #pragma unroll
    for (int mi=0;mi<2;mi++){
        int r0 = m0 + wm*32 + mi*16 + g;
        #pragma unroll
        for (int ni=0;ni<8;ni++){
            int col = v0 + wn*64 + ni*8 + 2*t;
            if (col < Vn){
                float s0 = 12.f*g_inorm[col], s1 = 12.f*g_inorm[col+1];
                float v00 = acc[mi][ni][0]*s0, v01 = acc[mi][ni][1]*s1;
                float v10 = acc[mi][ni][2]*s0, v11 = acc[mi][ni][3]*s1;
                float2* p0 = (float2*)(out + (size_t)r0*Vn + col);
                float2* p1 = (float2*)(out + (size_t)(r0+8)*Vn + col);
                __stcs(p0, make_float2(v00, v01));
                __stcs(p1, make_float2(v10, v11));
                rsum[mi*2+0] += exp2_pair_sum((v00-SHIFT)*L2E, (v01-SHIFT)*L2E);
                rsum[mi*2+1] += exp2_pair_sum((v10-SHIFT)*L2E, (v11-SHIFT)*L2E);
            }
        }
    }
    #pragma unroll
    for (int o=1;o<4;o<<=1)
        #pragma unroll
        for (int j=0;j<4;j++) rsum[j] += __shfl_xor_sync(0xffffffffu, rsum[j], o);
    if (t==0){
        #pragma unroll
        for (int j=0;j<4;j++){
            int row = m0 + wm*32 + (j>>1)*16 + (j&1)*8 + g;
            atomicAdd(&g_rowsum[row], (double)rsum[j]);
        }
    }
}

// ---------------- K12: per-row shift for unmasked entries ----------------
__global__ void k_finalize(float* __restrict__ out){
    __shared__ float s_shift;
    int row = blockIdx.y;
    if (threadIdx.x==0){
        double sex = g_rowsum[row] - g_msum[row];
        s_shift = g_logphi[row*2+1] - (float)((double)SHIFT + log(sex));
    }
    __syncthreads();
    float sh = s_shift;
    int i = blockIdx.x*blockDim.x + threadIdx.x;
    if (i < Vn/4){
        float4* p = (float4*)(out + (size_t)row*Vn) + i;
        float4 o = __ldcs(p);
        o.x += sh; o.y += sh; o.z += sh; o.w += sh;
        __stcs(p, o);
    }
}

// ---------------- K13: overwrite masked entries ----------------
__global__ void k_fixup(float* __restrict__ out){
    int b = blockIdx.x, s = threadIdx.x;
    if (s >= Sn) return;
    int v = g_mask_v[b*Sn+s];
    if (v < 0) return;
    float lse_in = (float)((double)SHIFT + log(g_msum[b]));
    out[(size_t)b*Vn + v] = g_mask_l[b*Sn+s] - lse_in + g_logphi[b*2+0];
}

// ---------------- launch ----------------
extern "C" void kernel_launch(void* const* d_in, const int* in_sizes, int n_in,
                              void* d_out, int out_size){
    const int* iid      = (const int*)d_in[0];
    const int* src      = (const int*)d_in[1];
    const int* dst      = (const int*)d_in[2];
    const int* dis      = (const int*)d_in[3];
    const int* pid      = (const int*)d_in[4];
    const int* agg_dst  = (const int*)d_in[6];
    const int* tid_     = (const int*)d_in[7];
    const int* last_idx = (const int*)d_in[8];
    const float* emb        = (const float*)d_in[9];
    const float* pos_emb    = (const float*)d_in[10];
    const float* dis_emb    = (const float*)d_in[11];
    const float* target_emb = (const float*)d_in[12];
    const float* pi_w  = (const float*)d_in[13];
    const float* M_w   = (const float*)d_in[14];
    const float* q_w   = (const float*)d_in[15];
    const float* r_w   = (const float*)d_in[16];
    const float* sc1_w = (const float*)d_in[17];
    const float* sc1_b = (const float*)d_in[18];
    const float* sc2_w = (const float*)d_in[19];
    float* out = (float*)d_out;

    k_zero<<<(Nn+255)/256,256>>>();                      // 1
    k_count<<<En/256,256>>>(dst);                        // 2
    k_scan<<<1,1024>>>();                                // 3
    k_bpack<<<(int)(((long long)Vn*64+255)/256),256>>>(emb);  // 4 (profiled slot)
    k_scatter<<<En/256,256>>>(dst);                      // 5
    k_inorm<<<Vn/8,256>>>(emb);                          // 6
    k_hv<<<(Nn*Dn)/256,256>>>(emb, iid);                 // 7
    k_gat<<<Nn,256>>>(src,dis,dis_emb,pi_w,M_w);         // 8
    k_f<<<Bn/8,256>>>(tid_,last_idx,target_emb,r_w);
    k_eagg<<<Nn/16,256>>>(pid,agg_dst,pos_emb,q_w);
    k_sr<<<Bn,256>>>();
    k_apack<<<Bn*64/256,256>>>();
    k_phi<<<Bn/8,256>>>(sc1_w,sc1_b,sc2_w);
    k_masked<<<Bn,256>>>(iid, emb);
    dim3 gg(4, (Vn+127)/128);
    k_gemm_mma<<<gg, 256>>>(out);
    dim3 gf((Vn/4 + 255)/256, Bn);
    k_finalize<<<gf,256>>>(out);
    k_fixup<<<Bn,32>>>(out);
}

// round 12
// speedup vs baseline: 2.0780x; 1.0949x over previous
#include <cuda_runtime.h>
#include <cuda_bf16.h>
#include <cuda_fp16.h>
#include <math.h>
#include <stdint.h>

#define Vn 100000
#define Dn 256
#define Bn 512
#define Sn 20
#define Nn (Bn*Sn)      // 10240
#define En (8*Nn)       // 81920
#define DEGMAX 128
#define SHIFT 4.0f

// ---------------- scratch (device globals; no allocation allowed) ----------------
__device__ float g_inorm[Vn];
__device__ float g_hv[Nn*Dn];
__device__ float g_h[Nn*Dn];
__device__ float g_f[Bn*Dn];
__device__ float g_mscal[Nn];
__device__ float g_srn[Bn*Dn];
__device__ float g_logphi[Bn*2];
__device__ double g_rowsum[Bn];
__device__ double g_msum[Bn];
__device__ int   g_mask_v[Bn*Sn];
__device__ float g_mask_l[Bn*Sn];
// CSR
__device__ int g_deg[Nn];
__device__ int g_off[Nn+1];
__device__ int g_pos[Nn];
__device__ int g_eidx[En];
// packed big-GEMM operands (fp16 single-term): slot s=c*4+t, k0=c*16+2t
__device__ uint2 g_bp[(size_t)Vn*64];   // 51.2 MB
__device__ uint2 g_ap[Bn*64];           // 0.25 MB
// eagg path: bf16 hi/lo packed h and q_w^T, posq table
__device__ uint4 g_hp[Nn*64];           // 10.5 MB
__device__ uint4 g_qp[Dn*64];           // 0.26 MB
__device__ float g_posq[Sn*Dn];

// ---------------- helpers ----------------
__device__ __forceinline__ unsigned short hfr(float x){
    __half h = __float2half_rn(x);
    return *(unsigned short*)&h;
}
__device__ __forceinline__ unsigned short bfr(float x){
    __nv_bfloat16 h = __float2bfloat16(x);
    return *(unsigned short*)&h;
}
__device__ __forceinline__ float bff(unsigned short u){
    __nv_bfloat16 h = *(__nv_bfloat16*)&u;
    return __bfloat162float(h);
}
__device__ __forceinline__ unsigned smem_u32(const void* p){
    unsigned a;
    asm("{ .reg .u64 t; cvta.to.shared.u64 t, %1; cvt.u32.u64 %0, t; }" : "=r"(a) : "l"(p));
    return a;
}
__device__ __forceinline__ float tanha(float x){
    float y; asm("tanh.approx.f32 %0, %1;" : "=f"(y) : "f"(x)); return y;
}
// sum of exp2 of two fp32 exponents via f16x2 MUFU
__device__ __forceinline__ float exp2_pair_sum(float y0, float y1){
    unsigned p, e;
    asm("cvt.rn.f16x2.f32 %0, %1, %2;" : "=r"(p) : "f"(y1), "f"(y0));
    asm("ex2.approx.f16x2 %0, %1;" : "=r"(e) : "r"(p));
    __half2 he = *reinterpret_cast<__half2*>(&e);
    float2 fe = __half22float2(he);
    return fe.x + fe.y;
}

// mma.sync m16n8k16 f16 / bf16: D = A*B + D (fp32 accum)
#define MMA_F16(d, a0, a1, a2, a3, b0, b1) \
    asm volatile("mma.sync.aligned.m16n8k16.row.col.f32.f16.f16.f32 " \
        "{%0,%1,%2,%3}, {%4,%5,%6,%7}, {%8,%9}, {%0,%1,%2,%3};" \
        : "+f"((d)[0]), "+f"((d)[1]), "+f"((d)[2]), "+f"((d)[3]) \
        : "r"(a0), "r"(a1), "r"(a2), "r"(a3), "r"(b0), "r"(b1))
#define MMA_BF16(d, a0, a1, a2, a3, b0, b1) \
    asm volatile("mma.sync.aligned.m16n8k16.row.col.f32.bf16.bf16.f32 " \
        "{%0,%1,%2,%3}, {%4,%5,%6,%7}, {%8,%9}, {%0,%1,%2,%3};" \
        : "+f"((d)[0]), "+f"((d)[1]), "+f"((d)[2]), "+f"((d)[3]) \
        : "r"(a0), "r"(a1), "r"(a2), "r"(a3), "r"(b0), "r"(b1))

__device__ __forceinline__ void cp16(unsigned dst, const void* src, int src_bytes){
    asm volatile("cp.async.cg.shared.global [%0], [%1], 16, %2;"
        :: "r"(dst), "l"(src), "r"(src_bytes) : "memory");
}
#define CP_COMMIT() asm volatile("cp.async.commit_group;" ::: "memory")
#define CP_WAIT2()  asm volatile("cp.async.wait_group 2;" ::: "memory")

// ---------------- K0: zero scratch ----------------
__global__ void k_zero(){
    int i = blockIdx.x*blockDim.x + threadIdx.x;
    if (i < Nn){ g_deg[i] = 0; g_mscal[i] = 0.f; }
    if (i < Bn){ g_rowsum[i]=0.0; g_msum[i]=0.0; }
}

// ---------------- CSR build ----------------
__global__ void k_count(const int* __restrict__ dst){
    int e = blockIdx.x*blockDim.x + threadIdx.x;
    if (e < En) atomicAdd(&g_deg[dst[e]], 1);
}
__global__ void k_scan(){
    __shared__ int warp_sums[32];
    int t = threadIdx.x;
    int base = t*10;
    int local[10]; int s = 0;
    #pragma unroll
    for (int i=0;i<10;i++){ local[i]=s; s += g_deg[base+i]; }
    int lane = t&31, w = t>>5;
    int v = s;
    #pragma unroll
    for (int o=1;o<32;o<<=1){ int u=__shfl_up_sync(0xffffffffu,v,o); if(lane>=o) v+=u; }
    if (lane==31) warp_sums[w]=v;
    __syncthreads();
    if (w==0){
        int x = warp_sums[lane];
        #pragma unroll
        for (int o=1;o<32;o<<=1){ int u=__shfl_up_sync(0xffffffffu,x,o); if(lane>=o) x+=u; }
        warp_sums[lane]=x;
    }
    __syncthreads();
    int excl = v - s + (w>0 ? warp_sums[w-1] : 0);
    #pragma unroll
    for (int i=0;i<10;i++){ g_off[base+i]=excl+local[i]; g_pos[base+i]=excl+local[i]; }
    if (t==1023) g_off[Nn]=En;
}
__global__ void k_scatter(const int* __restrict__ dst){
    int e = blockIdx.x*blockDim.x + threadIdx.x;
    if (e < En){
        int p = atomicAdd(&g_pos[dst[e]], 1);
        g_eidx[p] = e;
    }
}

// ---------------- pack emb into fp16 fragment layout ----------------
__global__ void k_bpack(const float* __restrict__ emb){
    long long id = (long long)blockIdx.x*blockDim.x + threadIdx.x;
    if (id >= (long long)Vn*64) return;
    int row = (int)(id>>6), s = (int)(id&63);
    int c = s>>2, t = s&3;
    int k0 = c*16 + 2*t;
    const float* p = emb + (size_t)row*Dn;
    unsigned short h0=hfr(p[k0]), h1=hfr(p[k0+1]), h2=hfr(p[k0+8]), h3=hfr(p[k0+9]);
    uint2 o;
    o.x = ((unsigned)h1<<16) | h0;
    o.y = ((unsigned)h3<<16) | h2;
    g_bp[(size_t)row*64 + s] = o;
}

// ---------------- pack srn fp16 ----------------
__global__ void k_apack(){
    int id = blockIdx.x*blockDim.x + threadIdx.x;
    int row = id>>6, s = id&63;
    int c = s>>2, t = s&3;
    int k0 = c*16 + 2*t;
    const float* p = g_srn + (size_t)row*Dn;
    unsigned short h0=hfr(p[k0]), h1=hfr(p[k0+1]), h2=hfr(p[k0+8]), h3=hfr(p[k0+9]);
    uint2 o;
    o.x = ((unsigned)h1<<16) | h0;
    o.y = ((unsigned)h3<<16) | h2;
    g_ap[row*64 + s] = o;
}

// ---------------- pack h into bf16 hi/lo fragment layout ----------------
__global__ void k_hpack(){
    int id = blockIdx.x*blockDim.x + threadIdx.x;   // Nn*64
    int row = id>>6, s = id&63;
    int c = s>>2, t = s&3;
    int k0 = c*16 + 2*t;
    const float* p = g_h + (size_t)row*Dn;
    float v0=p[k0], v1=p[k0+1], v2=p[k0+8], v3=p[k0+9];
    unsigned short h0=bfr(v0), h1=bfr(v1), h2=bfr(v2), h3=bfr(v3);
    unsigned short l0=bfr(v0-bff(h0)), l1=bfr(v1-bff(h1)), l2=bfr(v2-bff(h2)), l3=bfr(v3-bff(h3));
    uint4 o;
    o.x = ((unsigned)h1<<16) | h0;
    o.y = ((unsigned)h3<<16) | h2;
    o.z = ((unsigned)l1<<16) | l0;
    o.w = ((unsigned)l3<<16) | l2;
    g_hp[row*64 + s] = o;
}

// ---------------- pack q_w^T (first 256 K-rows) into bf16 hi/lo ----------------
__global__ void k_qpack(const float* __restrict__ q_w){
    int id = blockIdx.x*blockDim.x + threadIdx.x;   // Dn*64
    int n = id>>6, s = id&63;
    int c = s>>2, t = s&3;
    int k0 = c*16 + 2*t;
    float v0=q_w[(size_t)k0*Dn+n], v1=q_w[(size_t)(k0+1)*Dn+n];
    float v2=q_w[(size_t)(k0+8)*Dn+n], v3=q_w[(size_t)(k0+9)*Dn+n];
    unsigned short h0=bfr(v0), h1=bfr(v1), h2=bfr(v2), h3=bfr(v3);
    unsigned short l0=bfr(v0-bff(h0)), l1=bfr(v1-bff(h1)), l2=bfr(v2-bff(h2)), l3=bfr(v3-bff(h3));
    uint4 o;
    o.x = ((unsigned)h1<<16) | h0;
    o.y = ((unsigned)h3<<16) | h2;
    o.z = ((unsigned)l1<<16) | l0;
    o.w = ((unsigned)l3<<16) | l2;
    g_qp[n*64 + s] = o;
}

// ---------------- posq[p][d] = pos_emb[p] @ q_w[256:512, d] ----------------
__global__ void k_posq(const float* __restrict__ pos_emb, const float* __restrict__ q_w){
    int p = blockIdx.x;          // 0..19
    int d = threadIdx.x;         // 0..255
    float s = 0.f;
    const float* pe = pos_emb + (size_t)p*Dn;
    for (int k=0;k<Dn;k++)
        s += pe[k] * q_w[(size_t)(Dn+k)*Dn + d];
    g_posq[p*Dn + d] = s;
}

// ---------------- K1: inverse norms of emb rows ----------------
__global__ void k_inorm(const float* __restrict__ emb){
    int row = blockIdx.x*8 + (threadIdx.x>>5);
    int lane = threadIdx.x&31;
    float ss = 0.f;
    const float* p = emb + (size_t)row*Dn;
    for (int k=lane;k<Dn;k+=32){ float x=p[k]; ss += x*x; }
    #pragma unroll
    for (int o=16;o;o>>=1) ss += __shfl_xor_sync(0xffffffffu, ss, o);
    if (lane==0) g_inorm[row] = 1.f / fmaxf(sqrtf(ss), 1e-12f);
}

// ---------------- K2: h_v = l2norm(emb[iid]) ----------------
__global__ void k_hv(const float* __restrict__ emb, const int* __restrict__ iid){
    int i = blockIdx.x*blockDim.x + threadIdx.x;
    int n = i>>8, k = i&255;
    int id = iid[n];
    g_hv[i] = emb[(size_t)id*Dn + k] * g_inorm[id];
}

// ---------------- K3: fused gather GAT ----------------
__global__ void __launch_bounds__(256) k_gat(const int* __restrict__ src, const int* __restrict__ dis,
                      const float* __restrict__ dis_emb,
                      const float* __restrict__ pi_w, const float* __restrict__ M_w){
    __shared__ float hd[Dn];
    __shared__ float se[DEGMAX];
    __shared__ int   ssrc[DEGMAX];
    int d = blockIdx.x;
    int t = threadIdx.x;
    int beg = g_off[d], end = g_off[d+1];
    int deg = end - beg; if (deg > DEGMAX) deg = DEGMAX;
    if (deg == 0){
        g_h[(size_t)d*Dn + t] = 0.f;
        return;
    }
    hd[t] = g_hv[(size_t)d*Dn + t];
    __syncthreads();
    int warp = t>>5, lane = t&31;
    for (int slot=warp; slot<deg; slot+=8){
        int e = g_eidx[beg+slot];
        int s = src[e], di = dis[e];
        const float* hs = g_hv + (size_t)s*Dn;
        const float* he = dis_emb + (size_t)di*Dn;
        float e1 = 0.f, g = 0.f;
        for (int k=lane;k<Dn;k+=32){
            float a = hs[k], b = hd[k], c = he[k];
            float p = a*b;
            e1 += p*c*pi_w[k];
            g  += p*M_w[k] + c*M_w[Dn+k];
        }
        #pragma unroll
        for (int o=16;o;o>>=1){
            e1 += __shfl_xor_sync(0xffffffffu, e1, o);
            g  += __shfl_xor_sync(0xffffffffu, g,  o);
        }
        if (lane==0){
            se[slot] = e1 * (1.f/(1.f+__expf(-g)));
            ssrc[slot] = s;
        }
    }
    __syncthreads();
    float mx = -3.4e38f;
    for (int i=0;i<deg;i++) mx = fmaxf(mx, se[i]);
    float acc = 0.f, asum = 0.f;
    for (int i=0;i<deg;i++){
        float a = __expf(se[i]-mx);
        asum += a;
        acc += a * g_hv[(size_t)ssrc[i]*Dn + t];
    }
    g_h[(size_t)d*Dn + t] = acc / asum;
}

// ---------------- K6: f = concat(h_t, last_feat) @ r_w ----------------
__global__ void k_f(const int* __restrict__ tid_, const int* __restrict__ last_idx,
                    const float* __restrict__ target_emb, const float* __restrict__ r_w){
    __shared__ float sin_[8][2*Dn];
    int b0 = blockIdx.x*8;
    int t = threadIdx.x;
    for (int idx=t; idx<8*2*Dn; idx+=256){
        int j = idx>>9, k = idx&511;
        int b = b0+j;
        float v = (k<Dn) ? target_emb[(size_t)tid_[b]*Dn + k]
                         : g_h[(size_t)last_idx[b]*Dn + (k-Dn)];
        sin_[j][k] = v;
    }
    __syncthreads();
    float acc[8] = {0,0,0,0,0,0,0,0};
    int d = t;
    for (int k=0;k<2*Dn;k++){
        float w = r_w[(size_t)k*Dn + d];
        #pragma unroll
        for (int j=0;j<8;j++) acc[j] += sin_[j][k]*w;
    }
    #pragma unroll
    for (int j=0;j<8;j++) g_f[(size_t)(b0+j)*Dn + d] = acc[j];
}

// ---------------- K7: eagg via bf16 3-term mma: mscal += sum_d tanh(hq+posq)*f ----------------
// grid (80 M-tiles, 2 N-tiles), 256 threads, warps 4x2, warp tile 32 rows x 64 cols
__global__ void __launch_bounds__(256) k_eagg_mma(){
    int tid = threadIdx.x;
    int w = tid>>5, lane = tid&31;
    int g = lane>>2, t = lane&3;
    int wm = w>>1, wn = w&1;
    int m0 = blockIdx.x*128;     // node tile
    int n0 = blockIdx.y*128;     // dim tile

    int ar0 = m0 + wm*32 + g;
    const uint4* aptr[2][2];
    #pragma unroll
    for (int mi=0;mi<2;mi++)
        #pragma unroll
        for (int rp=0;rp<2;rp++)
            aptr[mi][rp] = g_hp + (ar0 + mi*16 + rp*8)*64 + t;
    const uint4* bptr[8];
    #pragma unroll
    for (int ni=0;ni<8;ni++)
        bptr[ni] = g_qp + (n0 + wn*64 + ni*8 + g)*64 + t;

    float acc[2][8][4];
    #pragma unroll
    for (int mi=0;mi<2;mi++)
        #pragma unroll
        for (int ni=0;ni<8;ni++)
            #pragma unroll
            for (int q=0;q<4;q++) acc[mi][ni][q]=0.f;

    #pragma unroll 2
    for (int c=0; c<16; c++){
        int so = c*4;
        uint4 A0[2], A1[2];
        #pragma unroll
        for (int mi=0;mi<2;mi++){
            A0[mi] = __ldg(aptr[mi][0] + so);
            A1[mi] = __ldg(aptr[mi][1] + so);
        }
        #pragma unroll
        for (int ni=0;ni<8;ni++){
            uint4 b = __ldg(bptr[ni] + so);
            #pragma unroll
            for (int mi=0;mi<2;mi++){
                MMA_BF16(acc[mi][ni], A0[mi].x, A1[mi].x, A0[mi].y, A1[mi].y, b.x, b.y);
                MMA_BF16(acc[mi][ni], A0[mi].x, A1[mi].x, A0[mi].y, A1[mi].y, b.z, b.w);
                MMA_BF16(acc[mi][ni], A0[mi].z, A1[mi].z, A0[mi].w, A1[mi].w, b.x, b.y);
            }
        }
    }

    // epilogue: tanh(hq + posq) * f, reduce over cols
    float rsum[2][2] = {{0.f,0.f},{0.f,0.f}};
    #pragma unroll
    for (int mi=0;mi<2;mi++){
        #pragma unroll
        for (int rp=0;rp<2;rp++){
            int r = ar0 + mi*16 + rp*8;
            int p = r % Sn, se = r / Sn;
            const float* pq = g_posq + p*Dn;
            const float* ff = g_f + (size_t)se*Dn;
            float s = 0.f;
            #pragma unroll
            for (int ni=0;ni<8;ni++){
                int col = n0 + wn*64 + ni*8 + 2*t;
                float2 q2 = *(const float2*)(pq + col);
                float2 f2 = *(const float2*)(ff + col);
                float a0 = acc[mi][ni][rp*2+0], a1 = acc[mi][ni][rp*2+1];
                s += tanha(a0 + q2.x)*f2.x + tanha(a1 + q2.y)*f2.y;
            }
            rsum[mi][rp] = s;
        }
    }
    #pragma unroll
    for (int o=1;o<4;o<<=1)
        #pragma unroll
        for (int mi=0;mi<2;mi++)
            #pragma unroll
            for (int rp=0;rp<2;rp++)
                rsum[mi][rp] += __shfl_xor_sync(0xffffffffu, rsum[mi][rp], o);
    if (t==0){
        #pragma unroll
        for (int mi=0;mi<2;mi++)
            #pragma unroll
            for (int rp=0;rp<2;rp++)
                atomicAdd(&g_mscal[ar0 + mi*16 + rp*8], rsum[mi][rp]);
    }
}

// ---------------- K8: sr per session + l2norm ----------------
__global__ void k_sr(){
    __shared__ float sm[Sn];
    __shared__ float sred[8];
    int b = blockIdx.x, t = threadIdx.x;
    if (t<Sn) sm[t] = g_mscal[b*Sn + t];
    __syncthreads();
    float acc = 0.f;
    #pragma unroll
    for (int s=0;s<Sn;s++) acc += g_h[(size_t)(b*Sn+s)*Dn + t]*sm[s];
    float ss = acc*acc;
    #pragma unroll
    for (int o=16;o;o>>=1) ss += __shfl_xor_sync(0xffffffffu, ss, o);
    if ((t&31)==0) sred[t>>5] = ss;
    __syncthreads();
    float tot = 0.f;
    #pragma unroll
    for (int w=0;w<8;w++) tot += sred[w];
    g_srn[(size_t)b*Dn + t] = acc / fmaxf(sqrtf(tot), 1e-12f);
}

// ---------------- K9: phi head ----------------
__global__ void k_phi(const float* __restrict__ sc1_w, const float* __restrict__ sc1_b,
                      const float* __restrict__ sc2_w){
    __shared__ float ssr[8][Dn];
    __shared__ float s_p[8][2];
    int b0 = blockIdx.x*8;
    int t = threadIdx.x;
    for (int idx=t; idx<8*Dn; idx+=256){
        int j = idx>>8, k = idx&255;
        ssr[j][k] = g_srn[(size_t)(b0+j)*Dn + k];
    }
    if (t<16) s_p[t>>1][t&1] = 0.f;
    __syncthreads();
    float acc[8] = {0,0,0,0,0,0,0,0};
    int d = t;
    for (int k=0;k<Dn;k++){
        float w = sc1_w[(size_t)k*Dn + d];
        #pragma unroll
        for (int j=0;j<8;j++) acc[j] += ssr[j][k]*w;
    }
    float bb = sc1_b[d], w0 = sc2_w[d*2], w1 = sc2_w[d*2+1];
    int lane = t&31;
    #pragma unroll
    for (int j=0;j<8;j++){
        float hid = fmaxf(acc[j]+bb, 0.f);
        float p0 = hid*w0, p1 = hid*w1;
        #pragma unroll
        for (int o=16;o;o>>=1){
            p0 += __shfl_xor_sync(0xffffffffu, p0, o);
            p1 += __shfl_xor_sync(0xffffffffu, p1, o);
        }
        if (lane==0){ atomicAdd(&s_p[j][0], p0); atomicAdd(&s_p[j][1], p1); }
    }
    __syncthreads();
    if (t<8){
        float a0 = s_p[t][0], a1 = s_p[t][1];
        float m = fmaxf(a0,a1);
        float lse = m + logf(__expf(a0-m)+__expf(a1-m));
        g_logphi[(b0+t)*2+0] = a0 - lse;
        g_logphi[(b0+t)*2+1] = a1 - lse;
    }
}

// ---------------- K10: masked (in-session) logits + msum ----------------
__global__ void k_masked(const int* __restrict__ iid, const float* __restrict__ emb){
    __shared__ int iids[Sn];
    __shared__ float s_sr[Dn];
    int b = blockIdx.x, t = threadIdx.x;
    if (t<Sn) iids[t] = iid[b*Sn+t];
    if (t<Dn) s_sr[t] = g_srn[(size_t)b*Dn + t];
    __syncthreads();
    int warp = t>>5, lane = t&31;
    for (int slot=warp; slot<Sn; slot+=8){
        int v = iids[slot];
        bool dup = false;
        for (int j=0;j<slot;j++) if (iids[j]==v) { dup=true; break; }
        if (dup){
            if (lane==0) g_mask_v[b*Sn+slot] = -1;
            continue;
        }
        const float* ev = emb + (size_t)v*Dn;
        float dot = 0.f;
        for (int k=lane;k<Dn;k+=32) dot += s_sr[k]*ev[k];
        #pragma unroll
        for (int o=16;o;o>>=1) dot += __shfl_xor_sync(0xffffffffu, dot, o);
        if (lane==0){
            float l = dot * g_inorm[v] * 12.f;
            g_mask_v[b*Sn+slot] = v;
            g_mask_l[b*Sn+slot] = l;
            atomicAdd(&g_msum[b], (double)__expf(l-SHIFT));
        }
    }
}

// ---------------- K11: cp.async-pipelined smem-staged fp16 GEMM ----------------
#define NSTAGE 4
__global__ void __launch_bounds__(256,2) k_gemm_mma(float* __restrict__ out){
    __shared__ __align__(16) uint2 sA[NSTAGE][128][4];
    __shared__ __align__(16) uint2 sB[NSTAGE][128][4];
    int tid = threadIdx.x;
    int w = tid>>5, lane = tid&31;
    int g = lane>>2, t = lane&3;
    int wm = w>>1, wn = w&1;
    int m0 = blockIdx.x*128;
    int v0 = blockIdx.y*128;

    unsigned sAu = smem_u32(&sA[0][0][0]);
    unsigned sBu = smem_u32(&sB[0][0][0]);

    int srow = tid>>1, shalf = tid&1;
    int svrow = v0 + srow;
    int bbytes = (svrow < Vn) ? 16 : 0;
    const uint2* asrc0 = g_ap + (m0+srow)*64 + shalf*2;
    const uint2* bsrc0 = g_bp + (size_t)((svrow<Vn)?svrow:0)*64 + shalf*2;
    unsigned adst0 = sAu + (unsigned)((srow*4 + shalf*2)*8);
    unsigned bdst0 = sBu + (unsigned)((srow*4 + shalf*2)*8);

    float acc[2][8][4];
    #pragma unroll
    for (int mi=0;mi<2;mi++)
        #pragma unroll
        for (int ni=0;ni<8;ni++)
            #pragma unroll
            for (int q=0;q<4;q++) acc[mi][ni][q]=0.f;

    #pragma unroll
    for (int s=0;s<NSTAGE-1;s++){
        cp16(adst0 + (unsigned)(s*4096), asrc0 + s*4, 16);
        cp16(bdst0 + (unsigned)(s*4096), bsrc0 + s*4, bbytes);
        CP_COMMIT();
    }

    for (int c=0; c<16; c++){
        CP_WAIT2();
        __syncthreads();
        int st = c & (NSTAGE-1);
        uint2 A0[2], A1[2], Bf[8];
        #pragma unroll
        for (int mi=0;mi<2;mi++){
            A0[mi] = sA[st][wm*32 + mi*16 + g][t];
            A1[mi] = sA[st][wm*32 + mi*16 + 8 + g][t];
        }
        #pragma unroll
        for (int ni=0;ni<8;ni++)
            Bf[ni] = sB[st][wn*64 + ni*8 + g][t];
        #pragma unroll
        for (int ni=0;ni<8;ni++){
            #pragma unroll
            for (int mi=0;mi<2;mi++){
                MMA_F16(acc[mi][ni], A0[mi].x, A1[mi].x, A0[mi].y, A1[mi].y, Bf[ni].x, Bf[ni].y);
            }
        }
        __syncthreads();
        int cn = c + NSTAGE - 1;
        if (cn < 16){
            int sn = cn & (NSTAGE-1);
            cp16(adst0 + (unsigned)(sn*4096), asrc0 + cn*4, 16);
            cp16(bdst0 + (unsigned)(sn*4096), bsrc0 + cn*4, bbytes);
        }
        CP_COMMIT();
    }

    const float L2E = 1.44269504f;
    float rsum[4] = {0.f,0.f,0.f,0.f};
    #pragma unroll
    for (int mi=0;mi<2;mi++){
        int r0 = m0 + wm*32 + mi*16 + g;
        #pragma unroll
        for (int ni=0;ni<8;ni++){
            int col = v0 + wn*64 + ni*8 + 2*t;
            if (col < Vn){
                float s0 = 12.f*g_inorm[col], s1 = 12.f*g_inorm[col+1];
                float v00 = acc[mi][ni][0]*s0, v01 = acc[mi][ni][1]*s1;
                float v10 = acc[mi][ni][2]*s0, v11 = acc[mi][ni][3]*s1;
                float2* p0 = (float2*)(out + (size_t)r0*Vn + col);
                float2* p1 = (float2*)(out + (size_t)(r0+8)*Vn + col);
                __stcs(p0, make_float2(v00, v01));
                __stcs(p1, make_float2(v10, v11));
                rsum[mi*2+0] += exp2_pair_sum((v00-SHIFT)*L2E, (v01-SHIFT)*L2E);
                rsum[mi*2+1] += exp2_pair_sum((v10-SHIFT)*L2E, (v11-SHIFT)*L2E);
            }
        }
    }
    #pragma unroll
    for (int o=1;o<4;o<<=1)
        #pragma unroll
        for (int j=0;j<4;j++) rsum[j] += __shfl_xor_sync(0xffffffffu, rsum[j], o);
    if (t==0){
        #pragma unroll
        for (int j=0;j<4;j++){
            int row = m0 + wm*32 + (j>>1)*16 + (j&1)*8 + g;
            atomicAdd(&g_rowsum[row], (double)rsum[j]);
        }
    }
}

// ---------------- K12: per-row shift for unmasked entries ----------------
__global__ void k_finalize(float* __restrict__ out){
    __shared__ float s_shift;
    int row = blockIdx.y;
    if (threadIdx.x==0){
        double sex = g_rowsum[row] - g_msum[row];
        s_shift = g_logphi[row*2+1] - (float)((double)SHIFT + log(sex));
    }
    __syncthreads();
    float sh = s_shift;
    int i = blockIdx.x*blockDim.x + threadIdx.x;
    if (i < Vn/4){
        float4* p = (float4*)(out + (size_t)row*Vn) + i;
        float4 o = __ldcs(p);
        o.x += sh; o.y += sh; o.z += sh; o.w += sh;
        __stcs(p, o);
    }
}

// ---------------- K13: overwrite masked entries ----------------
__global__ void k_fixup(float* __restrict__ out){
    int b = blockIdx.x, s = threadIdx.x;
    if (s >= Sn) return;
    int v = g_mask_v[b*Sn+s];
    if (v < 0) return;
    float lse_in = (float)((double)SHIFT + log(g_msum[b]));
    out[(size_t)b*Vn + v] = g_mask_l[b*Sn+s] - lse_in + g_logphi[b*2+0];
}

// ---------------- launch ----------------
extern "C" void kernel_launch(void* const* d_in, const int* in_sizes, int n_in,
                              void* d_out, int out_size){
    const int* iid      = (const int*)d_in[0];
    const int* src      = (const int*)d_in[1];
    const int* dst      = (const int*)d_in[2];
    const int* dis      = (const int*)d_in[3];
    const float* emb        = (const float*)d_in[9];
    const float* pos_emb    = (const float*)d_in[10];
    const float* dis_emb    = (const float*)d_in[11];
    const float* target_emb = (const float*)d_in[12];
    const float* pi_w  = (const float*)d_in[13];
    const float* M_w   = (const float*)d_in[14];
    const float* q_w   = (const float*)d_in[15];
    const float* r_w   = (const float*)d_in[16];
    const float* sc1_w = (const float*)d_in[17];
    const float* sc1_b = (const float*)d_in[18];
    const float* sc2_w = (const float*)d_in[19];
    const int* tid_     = (const int*)d_in[7];
    const int* last_idx = (const int*)d_in[8];
    float* out = (float*)d_out;

    k_zero<<<(Nn+255)/256,256>>>();                      // 1
    k_count<<<En/256,256>>>(dst);                        // 2
    k_scan<<<1,1024>>>();                                // 3
    k_bpack<<<(int)(((long long)Vn*64+255)/256),256>>>(emb);  // 4 (profiled slot)
    k_scatter<<<En/256,256>>>(dst);                      // 5
    k_inorm<<<Vn/8,256>>>(emb);                          // 6
    k_hv<<<(Nn*Dn)/256,256>>>(emb, iid);                 // 7
    k_qpack<<<Dn*64/256,256>>>(q_w);                     // 8
    k_posq<<<Sn,256>>>(pos_emb, q_w);                    // 9
    k_gat<<<Nn,256>>>(src,dis,dis_emb,pi_w,M_w);         // 10
    k_hpack<<<Nn*64/256,256>>>();                        // 11
    k_f<<<Bn/8,256>>>(tid_,last_idx,target_emb,r_w);     // 12
    dim3 ge(Nn/128, 2);
    k_eagg_mma<<<ge,256>>>();                            // 13
    k_sr<<<Bn,256>>>();
    k_apack<<<Bn*64/256,256>>>();
    k_phi<<<Bn/8,256>>>(sc1_w,sc1_b,sc2_w);
    k_masked<<<Bn,256>>>(iid, emb);
    dim3 gg(4, (Vn+127)/128);
    k_gemm_mma<<<gg, 256>>>(out);
    dim3 gf((Vn/4 + 255)/256, Bn);
    k_finalize<<<gf,256>>>(out);
    k_fixup<<<Bn,32>>>(out);
}

// round 13
// speedup vs baseline: 2.3201x; 1.1165x over previous
#include <cuda_runtime.h>
#include <cuda_bf16.h>
#include <cuda_fp16.h>
#include <math.h>
#include <stdint.h>

#define Vn 100000
#define Dn 256
#define Bn 512
#define Sn 20
#define Nn (Bn*Sn)      // 10240
#define En (8*Nn)       // 81920
#define DEGMAX 128
#define SHIFT 4.0f

// ---------------- scratch (device globals; no allocation allowed) ----------------
__device__ float g_inorm[Vn];
__device__ float g_hv[Nn*Dn];
__device__ float g_h[Nn*Dn];
__device__ float g_f[Bn*Dn];
__device__ float g_mscal[Nn];
__device__ float g_srn[Bn*Dn];
__device__ float g_logphi[Bn*2];
__device__ double g_rowsum[Bn];
__device__ double g_msum[Bn];
__device__ int   g_mask_v[Bn*Sn];
__device__ float g_mask_l[Bn*Sn];
// CSR
__device__ int g_deg[Nn];
__device__ int g_off[Nn+1];
__device__ int g_pos[Nn];
__device__ int g_eidx[En];
// packed big-GEMM operands (fp16 single-term): slot s=c*4+t, k0=c*16+2t
__device__ uint2 g_bp[(size_t)Vn*64];   // 51.2 MB
__device__ uint2 g_ap[Bn*64];           // 0.25 MB
// eagg path: bf16 hi/lo packed h and q_w^T, posq table
__device__ uint4 g_hp[Nn*64];           // 10.5 MB
__device__ uint4 g_qp[Dn*64];           // 0.26 MB
__device__ float g_posq[Sn*Dn];

// ---------------- helpers ----------------
__device__ __forceinline__ unsigned short hfr(float x){
    __half h = __float2half_rn(x);
    return *(unsigned short*)&h;
}
__device__ __forceinline__ unsigned short bfr(float x){
    __nv_bfloat16 h = __float2bfloat16(x);
    return *(unsigned short*)&h;
}
__device__ __forceinline__ float bff(unsigned short u){
    __nv_bfloat16 h = *(__nv_bfloat16*)&u;
    return __bfloat162float(h);
}
__device__ __forceinline__ unsigned smem_u32(const void* p){
    unsigned a;
    asm("{ .reg .u64 t; cvta.to.shared.u64 t, %1; cvt.u32.u64 %0, t; }" : "=r"(a) : "l"(p));
    return a;
}
__device__ __forceinline__ float tanha(float x){
    float y; asm("tanh.approx.f32 %0, %1;" : "=f"(y) : "f"(x)); return y;
}
// sum of exp2 of two fp32 exponents via f16x2 MUFU
__device__ __forceinline__ float exp2_pair_sum(float y0, float y1){
    unsigned p, e;
    asm("cvt.rn.f16x2.f32 %0, %1, %2;" : "=r"(p) : "f"(y1), "f"(y0));
    asm("ex2.approx.f16x2 %0, %1;" : "=r"(e) : "r"(p));
    __half2 he = *reinterpret_cast<__half2*>(&e);
    float2 fe = __half22float2(he);
    return fe.x + fe.y;
}

// mma.sync m16n8k16 f16 / bf16: D = A*B + D (fp32 accum)
#define MMA_F16(d, a0, a1, a2, a3, b0, b1) \
    asm volatile("mma.sync.aligned.m16n8k16.row.col.f32.f16.f16.f32 " \
        "{%0,%1,%2,%3}, {%4,%5,%6,%7}, {%8,%9}, {%0,%1,%2,%3};" \
        : "+f"((d)[0]), "+f"((d)[1]), "+f"((d)[2]), "+f"((d)[3]) \
        : "r"(a0), "r"(a1), "r"(a2), "r"(a3), "r"(b0), "r"(b1))
#define MMA_BF16(d, a0, a1, a2, a3, b0, b1) \
    asm volatile("mma.sync.aligned.m16n8k16.row.col.f32.bf16.bf16.f32 " \
        "{%0,%1,%2,%3}, {%4,%5,%6,%7}, {%8,%9}, {%0,%1,%2,%3};" \
        : "+f"((d)[0]), "+f"((d)[1]), "+f"((d)[2]), "+f"((d)[3]) \
        : "r"(a0), "r"(a1), "r"(a2), "r"(a3), "r"(b0), "r"(b1))

__device__ __forceinline__ void cp16(unsigned dst, const void* src, int src_bytes){
    asm volatile("cp.async.cg.shared.global [%0], [%1], 16, %2;"
        :: "r"(dst), "l"(src), "r"(src_bytes) : "memory");
}
#define CP_COMMIT() asm volatile("cp.async.commit_group;" ::: "memory")
#define CP_WAIT2()  asm volatile("cp.async.wait_group 2;" ::: "memory")

// ---------------- K0: zero scratch ----------------
__global__ void k_zero(){
    int i = blockIdx.x*blockDim.x + threadIdx.x;
    if (i < Nn){ g_deg[i] = 0; g_mscal[i] = 0.f; }
    if (i < Bn){ g_rowsum[i]=0.0; g_msum[i]=0.0; }
}

// ---------------- CSR build ----------------
__global__ void k_count(const int* __restrict__ dst){
    int e = blockIdx.x*blockDim.x + threadIdx.x;
    if (e < En) atomicAdd(&g_deg[dst[e]], 1);
}
__global__ void k_scan(){
    __shared__ int warp_sums[32];
    int t = threadIdx.x;
    int base = t*10;
    int local[10]; int s = 0;
    #pragma unroll
    for (int i=0;i<10;i++){ local[i]=s; s += g_deg[base+i]; }
    int lane = t&31, w = t>>5;
    int v = s;
    #pragma unroll
    for (int o=1;o<32;o<<=1){ int u=__shfl_up_sync(0xffffffffu,v,o); if(lane>=o) v+=u; }
    if (lane==31) warp_sums[w]=v;
    __syncthreads();
    if (w==0){
        int x = warp_sums[lane];
        #pragma unroll
        for (int o=1;o<32;o<<=1){ int u=__shfl_up_sync(0xffffffffu,x,o); if(lane>=o) x+=u; }
        warp_sums[lane]=x;
    }
    __syncthreads();
    int excl = v - s + (w>0 ? warp_sums[w-1] : 0);
    #pragma unroll
    for (int i=0;i<10;i++){ g_off[base+i]=excl+local[i]; g_pos[base+i]=excl+local[i]; }
    if (t==1023) g_off[Nn]=En;
}
__global__ void k_scatter(const int* __restrict__ dst){
    int e = blockIdx.x*blockDim.x + threadIdx.x;
    if (e < En){
        int p = atomicAdd(&g_pos[dst[e]], 1);
        g_eidx[p] = e;
    }
}

// ---------------- fused: emb row norms + fp16 fragment pack (one emb read) ----------------
__global__ void __launch_bounds__(256) k_bpacknorm(const float* __restrict__ emb){
    __shared__ float rows[8][Dn];
    int w = threadIdx.x>>5, lane = threadIdx.x&31;
    int row = blockIdx.x*8 + w;
    const float4* p = (const float4*)(emb + (size_t)row*Dn);
    float4 a = p[lane*2], b = p[lane*2+1];
    float ss = a.x*a.x+a.y*a.y+a.z*a.z+a.w*a.w + b.x*b.x+b.y*b.y+b.z*b.z+b.w*b.w;
    #pragma unroll
    for (int o=16;o;o>>=1) ss += __shfl_xor_sync(0xffffffffu, ss, o);
    if (lane==0) g_inorm[row] = 1.f / fmaxf(sqrtf(ss), 1e-12f);
    *(float4*)&rows[w][lane*8]   = a;
    *(float4*)&rows[w][lane*8+4] = b;
    __syncwarp();
    #pragma unroll
    for (int rep=0; rep<2; rep++){
        int s = lane + rep*32;
        int c = s>>2, t = s&3;
        int k0 = c*16 + 2*t;
        unsigned short h0=hfr(rows[w][k0]),   h1=hfr(rows[w][k0+1]);
        unsigned short h2=hfr(rows[w][k0+8]), h3=hfr(rows[w][k0+9]);
        uint2 o;
        o.x = ((unsigned)h1<<16) | h0;
        o.y = ((unsigned)h3<<16) | h2;
        g_bp[(size_t)row*64 + s] = o;
    }
}

// ---------------- pack srn fp16 ----------------
__global__ void k_apack(){
    int id = blockIdx.x*blockDim.x + threadIdx.x;
    int row = id>>6, s = id&63;
    int c = s>>2, t = s&3;
    int k0 = c*16 + 2*t;
    const float* p = g_srn + (size_t)row*Dn;
    unsigned short h0=hfr(p[k0]), h1=hfr(p[k0+1]), h2=hfr(p[k0+8]), h3=hfr(p[k0+9]);
    uint2 o;
    o.x = ((unsigned)h1<<16) | h0;
    o.y = ((unsigned)h3<<16) | h2;
    g_ap[row*64 + s] = o;
}

// ---------------- pack h into bf16 hi/lo fragment layout ----------------
__global__ void k_hpack(){
    int id = blockIdx.x*blockDim.x + threadIdx.x;   // Nn*64
    int row = id>>6, s = id&63;
    int c = s>>2, t = s&3;
    int k0 = c*16 + 2*t;
    const float* p = g_h + (size_t)row*Dn;
    float v0=p[k0], v1=p[k0+1], v2=p[k0+8], v3=p[k0+9];
    unsigned short h0=bfr(v0), h1=bfr(v1), h2=bfr(v2), h3=bfr(v3);
    unsigned short l0=bfr(v0-bff(h0)), l1=bfr(v1-bff(h1)), l2=bfr(v2-bff(h2)), l3=bfr(v3-bff(h3));
    uint4 o;
    o.x = ((unsigned)h1<<16) | h0;
    o.y = ((unsigned)h3<<16) | h2;
    o.z = ((unsigned)l1<<16) | l0;
    o.w = ((unsigned)l3<<16) | l2;
    g_hp[row*64 + s] = o;
}

// ---------------- pack q_w^T (first 256 K-rows) into bf16 hi/lo ----------------
__global__ void k_qpack(const float* __restrict__ q_w){
    int id = blockIdx.x*blockDim.x + threadIdx.x;   // Dn*64
    int n = id>>6, s = id&63;
    int c = s>>2, t = s&3;
    int k0 = c*16 + 2*t;
    float v0=q_w[(size_t)k0*Dn+n], v1=q_w[(size_t)(k0+1)*Dn+n];
    float v2=q_w[(size_t)(k0+8)*Dn+n], v3=q_w[(size_t)(k0+9)*Dn+n];
    unsigned short h0=bfr(v0), h1=bfr(v1), h2=bfr(v2), h3=bfr(v3);
    unsigned short l0=bfr(v0-bff(h0)), l1=bfr(v1-bff(h1)), l2=bfr(v2-bff(h2)), l3=bfr(v3-bff(h3));
    uint4 o;
    o.x = ((unsigned)h1<<16) | h0;
    o.y = ((unsigned)h3<<16) | h2;
    o.z = ((unsigned)l1<<16) | l0;
    o.w = ((unsigned)l3<<16) | l2;
    g_qp[n*64 + s] = o;
}

// ---------------- posq[p][d] = pos_emb[p] @ q_w[256:512, d] ----------------
__global__ void k_posq(const float* __restrict__ pos_emb, const float* __restrict__ q_w){
    int p = blockIdx.x;
    int d = threadIdx.x;
    float s = 0.f;
    const float* pe = pos_emb + (size_t)p*Dn;
    for (int k=0;k<Dn;k++)
        s += pe[k] * q_w[(size_t)(Dn+k)*Dn + d];
    g_posq[p*Dn + d] = s;
}

// ---------------- K2: h_v = l2norm(emb[iid]) ----------------
__global__ void k_hv(const float* __restrict__ emb, const int* __restrict__ iid){
    int i = blockIdx.x*blockDim.x + threadIdx.x;
    int n = i>>8, k = i&255;
    int id = iid[n];
    g_hv[i] = emb[(size_t)id*Dn + k] * g_inorm[id];
}

// ---------------- K3: fused gather GAT ----------------
__global__ void __launch_bounds__(256) k_gat(const int* __restrict__ src, const int* __restrict__ dis,
                      const float* __restrict__ dis_emb,
                      const float* __restrict__ pi_w, const float* __restrict__ M_w){
    __shared__ float hd[Dn];
    __shared__ float se[DEGMAX];
    __shared__ int   ssrc[DEGMAX];
    int d = blockIdx.x;
    int t = threadIdx.x;
    int beg = g_off[d], end = g_off[d+1];
    int deg = end - beg; if (deg > DEGMAX) deg = DEGMAX;
    if (deg == 0){
        g_h[(size_t)d*Dn + t] = 0.f;
        return;
    }
    hd[t] = g_hv[(size_t)d*Dn + t];
    __syncthreads();
    int warp = t>>5, lane = t&31;
    for (int slot=warp; slot<deg; slot+=8){
        int e = g_eidx[beg+slot];
        int s = src[e], di = dis[e];
        const float* hs = g_hv + (size_t)s*Dn;
        const float* he = dis_emb + (size_t)di*Dn;
        float e1 = 0.f, g = 0.f;
        for (int k=lane;k<Dn;k+=32){
            float a = hs[k], b = hd[k], c = he[k];
            float p = a*b;
            e1 += p*c*pi_w[k];
            g  += p*M_w[k] + c*M_w[Dn+k];
        }
        #pragma unroll
        for (int o=16;o;o>>=1){
            e1 += __shfl_xor_sync(0xffffffffu, e1, o);
            g  += __shfl_xor_sync(0xffffffffu, g,  o);
        }
        if (lane==0){
            se[slot] = e1 * (1.f/(1.f+__expf(-g)));
            ssrc[slot] = s;
        }
    }
    __syncthreads();
    float mx = -3.4e38f;
    for (int i=0;i<deg;i++) mx = fmaxf(mx, se[i]);
    float acc = 0.f, asum = 0.f;
    for (int i=0;i<deg;i++){
        float a = __expf(se[i]-mx);
        asum += a;
        acc += a * g_hv[(size_t)ssrc[i]*Dn + t];
    }
    g_h[(size_t)d*Dn + t] = acc / asum;
}

// ---------------- K6: f = concat(h_t, last_feat) @ r_w ----------------
__global__ void k_f(const int* __restrict__ tid_, const int* __restrict__ last_idx,
                    const float* __restrict__ target_emb, const float* __restrict__ r_w){
    __shared__ float sin_[8][2*Dn];
    int b0 = blockIdx.x*8;
    int t = threadIdx.x;
    for (int idx=t; idx<8*2*Dn; idx+=256){
        int j = idx>>9, k = idx&511;
        int b = b0+j;
        float v = (k<Dn) ? target_emb[(size_t)tid_[b]*Dn + k]
                         : g_h[(size_t)last_idx[b]*Dn + (k-Dn)];
        sin_[j][k] = v;
    }
    __syncthreads();
    float acc[8] = {0,0,0,0,0,0,0,0};
    int d = t;
    for (int k=0;k<2*Dn;k++){
        float w = r_w[(size_t)k*Dn + d];
        #pragma unroll
        for (int j=0;j<8;j++) acc[j] += sin_[j][k]*w;
    }
    #pragma unroll
    for (int j=0;j<8;j++) g_f[(size_t)(b0+j)*Dn + d] = acc[j];
}

// ---------------- K7: eagg via bf16 3-term mma ----------------
__global__ void __launch_bounds__(256) k_eagg_mma(){
    int tid = threadIdx.x;
    int w = tid>>5, lane = tid&31;
    int g = lane>>2, t = lane&3;
    int wm = w>>1, wn = w&1;
    int m0 = blockIdx.x*128;
    int n0 = blockIdx.y*128;

    int ar0 = m0 + wm*32 + g;
    const uint4* aptr[2][2];
    #pragma unroll
    for (int mi=0;mi<2;mi++)
        #pragma unroll
        for (int rp=0;rp<2;rp++)
            aptr[mi][rp] = g_hp + (ar0 + mi*16 + rp*8)*64 + t;
    const uint4* bptr[8];
    #pragma unroll
    for (int ni=0;ni<8;ni++)
        bptr[ni] = g_qp + (n0 + wn*64 + ni*8 + g)*64 + t;

    float acc[2][8][4];
    #pragma unroll
    for (int mi=0;mi<2;mi++)
        #pragma unroll
        for (int ni=0;ni<8;ni++)
            #pragma unroll
            for (int q=0;q<4;q++) acc[mi][ni][q]=0.f;

    #pragma unroll 2
    for (int c=0; c<16; c++){
        int so = c*4;
        uint4 A0[2], A1[2];
        #pragma unroll
        for (int mi=0;mi<2;mi++){
            A0[mi] = __ldg(aptr[mi][0] + so);
            A1[mi] = __ldg(aptr[mi][1] + so);
        }
        #pragma unroll
        for (int ni=0;ni<8;ni++){
            uint4 b = __ldg(bptr[ni] + so);
            #pragma unroll
            for (int mi=0;mi<2;mi++){
                MMA_BF16(acc[mi][ni], A0[mi].x, A1[mi].x, A0[mi].y, A1[mi].y, b.x, b.y);
                MMA_BF16(acc[mi][ni], A0[mi].x, A1[mi].x, A0[mi].y, A1[mi].y, b.z, b.w);
                MMA_BF16(acc[mi][ni], A0[mi].z, A1[mi].z, A0[mi].w, A1[mi].w, b.x, b.y);
            }
        }
    }

    float rsum[2][2] = {{0.f,0.f},{0.f,0.f}};
    #pragma unroll
    for (int mi=0;mi<2;mi++){
        #pragma unroll
        for (int rp=0;rp<2;rp++){
            int r = ar0 + mi*16 + rp*8;
            int p = r % Sn, se = r / Sn;
            const float* pq = g_posq + p*Dn;
            const float* ff = g_f + (size_t)se*Dn;
            float s = 0.f;
            #pragma unroll
            for (int ni=0;ni<8;ni++){
                int col = n0 + wn*64 + ni*8 + 2*t;
                float2 q2 = *(const float2*)(pq + col);
                float2 f2 = *(const float2*)(ff + col);
                float a0 = acc[mi][ni][rp*2+0], a1 = acc[mi][ni][rp*2+1];
                s += tanha(a0 + q2.x)*f2.x + tanha(a1 + q2.y)*f2.y;
            }
            rsum[mi][rp] = s;
        }
    }
    #pragma unroll
    for (int o=1;o<4;o<<=1)
        #pragma unroll
        for (int mi=0;mi<2;mi++)
            #pragma unroll
            for (int rp=0;rp<2;rp++)
                rsum[mi][rp] += __shfl_xor_sync(0xffffffffu, rsum[mi][rp], o);
    if (t==0){
        #pragma unroll
        for (int mi=0;mi<2;mi++)
            #pragma unroll
            for (int rp=0;rp<2;rp++)
                atomicAdd(&g_mscal[ar0 + mi*16 + rp*8], rsum[mi][rp]);
    }
}

// ---------------- K8: sr per session + l2norm ----------------
__global__ void k_sr(){
    __shared__ float sm[Sn];
    __shared__ float sred[8];
    int b = blockIdx.x, t = threadIdx.x;
    if (t<Sn) sm[t] = g_mscal[b*Sn + t];
    __syncthreads();
    float acc = 0.f;
    #pragma unroll
    for (int s=0;s<Sn;s++) acc += g_h[(size_t)(b*Sn+s)*Dn + t]*sm[s];
    float ss = acc*acc;
    #pragma unroll
    for (int o=16;o;o>>=1) ss += __shfl_xor_sync(0xffffffffu, ss, o);
    if ((t&31)==0) sred[t>>5] = ss;
    __syncthreads();
    float tot = 0.f;
    #pragma unroll
    for (int w=0;w<8;w++) tot += sred[w];
    g_srn[(size_t)b*Dn + t] = acc / fmaxf(sqrtf(tot), 1e-12f);
}

// ---------------- K9: phi head ----------------
__global__ void k_phi(const float* __restrict__ sc1_w, const float* __restrict__ sc1_b,
                      const float* __restrict__ sc2_w){
    __shared__ float ssr[8][Dn];
    __shared__ float s_p[8][2];
    int b0 = blockIdx.x*8;
    int t = threadIdx.x;
    for (int idx=t; idx<8*Dn; idx+=256){
        int j = idx>>8, k = idx&255;
        ssr[j][k] = g_srn[(size_t)(b0+j)*Dn + k];
    }
    if (t<16) s_p[t>>1][t&1] = 0.f;
    __syncthreads();
    float acc[8] = {0,0,0,0,0,0,0,0};
    int d = t;
    for (int k=0;k<Dn;k++){
        float w = sc1_w[(size_t)k*Dn + d];
        #pragma unroll
        for (int j=0;j<8;j++) acc[j] += ssr[j][k]*w;
    }
    float bb = sc1_b[d], w0 = sc2_w[d*2], w1 = sc2_w[d*2+1];
    int lane = t&31;
    #pragma unroll
    for (int j=0;j<8;j++){
        float hid = fmaxf(acc[j]+bb, 0.f);
        float p0 = hid*w0, p1 = hid*w1;
        #pragma unroll
        for (int o=16;o;o>>=1){
            p0 += __shfl_xor_sync(0xffffffffu, p0, o);
            p1 += __shfl_xor_sync(0xffffffffu, p1, o);
        }
        if (lane==0){ atomicAdd(&s_p[j][0], p0); atomicAdd(&s_p[j][1], p1); }
    }
    __syncthreads();
    if (t<8){
        float a0 = s_p[t][0], a1 = s_p[t][1];
        float m = fmaxf(a0,a1);
        float lse = m + logf(__expf(a0-m)+__expf(a1-m));
        g_logphi[(b0+t)*2+0] = a0 - lse;
        g_logphi[(b0+t)*2+1] = a1 - lse;
    }
}

// ---------------- K10: masked (in-session) logits + msum ----------------
__global__ void k_masked(const int* __restrict__ iid, const float* __restrict__ emb){
    __shared__ int iids[Sn];
    __shared__ float s_sr[Dn];
    int b = blockIdx.x, t = threadIdx.x;
    if (t<Sn) iids[t] = iid[b*Sn+t];
    if (t<Dn) s_sr[t] = g_srn[(size_t)b*Dn + t];
    __syncthreads();
    int warp = t>>5, lane = t&31;
    for (int slot=warp; slot<Sn; slot+=8){
        int v = iids[slot];
        bool dup = false;
        for (int j=0;j<slot;j++) if (iids[j]==v) { dup=true; break; }
        if (dup){
            if (lane==0) g_mask_v[b*Sn+slot] = -1;
            continue;
        }
        const float* ev = emb + (size_t)v*Dn;
        float dot = 0.f;
        for (int k=lane;k<Dn;k+=32) dot += s_sr[k]*ev[k];
        #pragma unroll
        for (int o=16;o;o>>=1) dot += __shfl_xor_sync(0xffffffffu, dot, o);
        if (lane==0){
            float l = dot * g_inorm[v] * 12.f;
            g_mask_v[b*Sn+slot] = v;
            g_mask_l[b*Sn+slot] = l;
            atomicAdd(&g_msum[b], (double)__expf(l-SHIFT));
        }
    }
}

// ---------------- K11: cp.async-pipelined fp16 GEMM (1 sync/chunk) ----------------
#define NSTAGE 4
__global__ void __launch_bounds__(256,2) k_gemm_mma(float* __restrict__ out){
    __shared__ __align__(16) uint2 sA[NSTAGE][128][4];
    __shared__ __align__(16) uint2 sB[NSTAGE][128][4];
    int tid = threadIdx.x;
    int w = tid>>5, lane = tid&31;
    int g = lane>>2, t = lane&3;
    int wm = w>>1, wn = w&1;
    int m0 = blockIdx.x*128;
    int v0 = blockIdx.y*128;

    unsigned sAu = smem_u32(&sA[0][0][0]);
    unsigned sBu = smem_u32(&sB[0][0][0]);

    int srow = tid>>1, shalf = tid&1;
    int svrow = v0 + srow;
    int bbytes = (svrow < Vn) ? 16 : 0;
    const uint2* asrc0 = g_ap + (m0+srow)*64 + shalf*2;
    const uint2* bsrc0 = g_bp + (size_t)((svrow<Vn)?svrow:0)*64 + shalf*2;
    unsigned adst0 = sAu + (unsigned)((srow*4 + shalf*2)*8);
    unsigned bdst0 = sBu + (unsigned)((srow*4 + shalf*2)*8);

    float acc[2][8][4];
    #pragma unroll
    for (int mi=0;mi<2;mi++)
        #pragma unroll
        for (int ni=0;ni<8;ni++)
            #pragma unroll
            for (int q=0;q<4;q++) acc[mi][ni][q]=0.f;

    #pragma unroll
    for (int s=0;s<NSTAGE-1;s++){
        cp16(adst0 + (unsigned)(s*4096), asrc0 + s*4, 16);
        cp16(bdst0 + (unsigned)(s*4096), bsrc0 + s*4, bbytes);
        CP_COMMIT();
    }

    #pragma unroll 4
    for (int c=0; c<16; c++){
        CP_WAIT2();
        __syncthreads();
        // issue next-stage copies immediately after the sync (stage (c+3)%4 == (c-1)%4,
        // fully consumed by every warp that passed this sync)
        int cn = c + NSTAGE - 1;
        if (cn < 16){
            int sn = cn & (NSTAGE-1);
            cp16(adst0 + (unsigned)(sn*4096), asrc0 + cn*4, 16);
            cp16(bdst0 + (unsigned)(sn*4096), bsrc0 + cn*4, bbytes);
        }
        CP_COMMIT();
        int st = c & (NSTAGE-1);
        uint2 A0[2], A1[2], Bf[8];
        #pragma unroll
        for (int mi=0;mi<2;mi++){
            A0[mi] = sA[st][wm*32 + mi*16 + g][t];
            A1[mi] = sA[st][wm*32 + mi*16 + 8 + g][t];
        }
        #pragma unroll
        for (int ni=0;ni<8;ni++)
            Bf[ni] = sB[st][wn*64 + ni*8 + g][t];
        #pragma unroll
        for (int ni=0;ni<8;ni++){
            #pragma unroll
            for (int mi=0;mi<2;mi++){
                MMA_F16(acc[mi][ni], A0[mi].x, A1[mi].x, A0[mi].y, A1[mi].y, Bf[ni].x, Bf[ni].y);
            }
        }
    }

    const float L2E = 1.44269504f;
    float rsum[4] = {0.f,0.f,0.f,0.f};
    #pragma unroll
    for (int mi=0;mi<2;mi++){
        int r0 = m0 + wm*32 + mi*16 + g;
        #pragma unroll
        for (int ni=0;ni<8;ni++){
            int col = v0 + wn*64 + ni*8 + 2*t;
            if (col < Vn){
                float s0 = 12.f*g_inorm[col], s1 = 12.f*g_inorm[col+1];
                float v00 = acc[mi][ni][0]*s0, v01 = acc[mi][ni][1]*s1;
                float v10 = acc[mi][ni][2]*s0, v11 = acc[mi][ni][3]*s1;
                float2* p0 = (float2*)(out + (size_t)r0*Vn + col);
                float2* p1 = (float2*)(out + (size_t)(r0+8)*Vn + col);
                __stcs(p0, make_float2(v00, v01));
                __stcs(p1, make_float2(v10, v11));
                rsum[mi*2+0] += exp2_pair_sum((v00-SHIFT)*L2E, (v01-SHIFT)*L2E);
                rsum[mi*2+1] += exp2_pair_sum((v10-SHIFT)*L2E, (v11-SHIFT)*L2E);
            }
        }
    }
    #pragma unroll
    for (int o=1;o<4;o<<=1)
        #pragma unroll
        for (int j=0;j<4;j++) rsum[j] += __shfl_xor_sync(0xffffffffu, rsum[j], o);
    if (t==0){
        #pragma unroll
        for (int j=0;j<4;j++){
            int row = m0 + wm*32 + (j>>1)*16 + (j&1)*8 + g;
            atomicAdd(&g_rowsum[row], (double)rsum[j]);
        }
    }
}

// ---------------- K12: per-row shift for unmasked entries ----------------
__global__ void k_finalize(float* __restrict__ out){
    __shared__ float s_shift;
    int row = blockIdx.y;
    if (threadIdx.x==0){
        double sex = g_rowsum[row] - g_msum[row];
        s_shift = g_logphi[row*2+1] - (float)((double)SHIFT + log(sex));
    }
    __syncthreads();
    float sh = s_shift;
    int i = blockIdx.x*blockDim.x + threadIdx.x;
    if (i < Vn/4){
        float4* p = (float4*)(out + (size_t)row*Vn) + i;
        float4 o = __ldcs(p);
        o.x += sh; o.y += sh; o.z += sh; o.w += sh;
        __stcs(p, o);
    }
}

// ---------------- K13: overwrite masked entries ----------------
__global__ void k_fixup(float* __restrict__ out){
    int b = blockIdx.x, s = threadIdx.x;
    if (s >= Sn) return;
    int v = g_mask_v[b*Sn+s];
    if (v < 0) return;
    float lse_in = (float)((double)SHIFT + log(g_msum[b]));
    out[(size_t)b*Vn + v] = g_mask_l[b*Sn+s] - lse_in + g_logphi[b*2+0];
}

// ---------------- launch ----------------
extern "C" void kernel_launch(void* const* d_in, const int* in_sizes, int n_in,
                              void* d_out, int out_size){
    const int* iid      = (const int*)d_in[0];
    const int* src      = (const int*)d_in[1];
    const int* dst      = (const int*)d_in[2];
    const int* dis      = (const int*)d_in[3];
    const float* emb        = (const float*)d_in[9];
    const float* pos_emb    = (const float*)d_in[10];
    const float* dis_emb    = (const float*)d_in[11];
    const float* target_emb = (const float*)d_in[12];
    const float* pi_w  = (const float*)d_in[13];
    const float* M_w   = (const float*)d_in[14];
    const float* q_w   = (const float*)d_in[15];
    const float* r_w   = (const float*)d_in[16];
    const float* sc1_w = (const float*)d_in[17];
    const float* sc1_b = (const float*)d_in[18];
    const float* sc2_w = (const float*)d_in[19];
    const int* tid_     = (const int*)d_in[7];
    const int* last_idx = (const int*)d_in[8];
    float* out = (float*)d_out;

    k_zero<<<(Nn+255)/256,256>>>();                      // 1
    k_count<<<En/256,256>>>(dst);                        // 2
    k_scan<<<1,1024>>>();                                // 3
    k_bpacknorm<<<Vn/8,256>>>(emb);                      // 4 (profiled slot)
    k_scatter<<<En/256,256>>>(dst);                      // 5
    k_hv<<<(Nn*Dn)/256,256>>>(emb, iid);                 // 6
    k_qpack<<<Dn*64/256,256>>>(q_w);                     // 7
    k_posq<<<Sn,256>>>(pos_emb, q_w);                    // 8
    k_gat<<<Nn,256>>>(src,dis,dis_emb,pi_w,M_w);         // 9
    k_hpack<<<Nn*64/256,256>>>();                        // 10
    k_f<<<Bn/8,256>>>(tid_,last_idx,target_emb,r_w);     // 11
    dim3 ge(Nn/128, 2);
    k_eagg_mma<<<ge,256>>>();                            // 12
    k_sr<<<Bn,256>>>();
    k_apack<<<Bn*64/256,256>>>();
    k_phi<<<Bn/8,256>>>(sc1_w,sc1_b,sc2_w);
    k_masked<<<Bn,256>>>(iid, emb);
    dim3 gg(4, (Vn+127)/128);
    k_gemm_mma<<<gg, 256>>>(out);
    dim3 gf((Vn/4 + 255)/256, Bn);
    k_finalize<<<gf,256>>>(out);
    k_fixup<<<Bn,32>>>(out);
}

// round 14
// speedup vs baseline: 2.3722x; 1.0224x over previous
#include <cuda_runtime.h>
#include <cuda_bf16.h>
#include <cuda_fp16.h>
#include <math.h>
#include <stdint.h>

#define Vn 100000
#define Dn 256
#define Bn 512
#define Sn 20
#define Nn (Bn*Sn)      // 10240
#define En (8*Nn)       // 81920
#define DEGMAX 128
#define SHIFT 4.0f

// ---------------- scratch ----------------
__device__ float g_inorm[Vn];
__device__ float g_hv[Nn*Dn];
__device__ float g_h[Nn*Dn];
__device__ float g_f[Bn*Dn];
__device__ float g_mscal[Nn];
__device__ float g_srn[Bn*Dn];
__device__ float g_logphi[Bn*2];
__device__ double g_rowsum[Bn];
__device__ double g_msum[Bn];
__device__ int   g_mask_v[Bn*Sn];
__device__ float g_mask_l[Bn*Sn];
// CSR
__device__ int g_deg[Nn];
__device__ int g_off[Nn+1];
__device__ int g_pos[Nn];
__device__ int g_eidx[En];
// packed big-GEMM operands (fp16 single-term)
__device__ uint2 g_bp[(size_t)Vn*64];   // 51.2 MB
__device__ uint2 g_ap[Bn*64];           // 0.25 MB
// eagg path
__device__ uint4 g_hp[Nn*64];           // 10.5 MB
__device__ uint4 g_qp[Dn*64];           // 0.26 MB
__device__ float g_posq[Sn*Dn];

// ---------------- helpers ----------------
__device__ __forceinline__ unsigned short hfr(float x){
    __half h = __float2half_rn(x);
    return *(unsigned short*)&h;
}
__device__ __forceinline__ unsigned short bfr(float x){
    __nv_bfloat16 h = __float2bfloat16(x);
    return *(unsigned short*)&h;
}
__device__ __forceinline__ float bff(unsigned short u){
    __nv_bfloat16 h = *(__nv_bfloat16*)&u;
    return __bfloat162float(h);
}
__device__ __forceinline__ unsigned smem_u32(const void* p){
    unsigned a;
    asm("{ .reg .u64 t; cvta.to.shared.u64 t, %1; cvt.u32.u64 %0, t; }" : "=r"(a) : "l"(p));
    return a;
}
__device__ __forceinline__ float tanha(float x){
    float y; asm("tanh.approx.f32 %0, %1;" : "=f"(y) : "f"(x)); return y;
}
__device__ __forceinline__ float exp2_pair_sum(float y0, float y1){
    unsigned p, e;
    asm("cvt.rn.f16x2.f32 %0, %1, %2;" : "=r"(p) : "f"(y1), "f"(y0));
    asm("ex2.approx.f16x2 %0, %1;" : "=r"(e) : "r"(p));
    __half2 he = *reinterpret_cast<__half2*>(&e);
    float2 fe = __half22float2(he);
    return fe.x + fe.y;
}

#define MMA_F16(d, a0, a1, a2, a3, b0, b1) \
    asm volatile("mma.sync.aligned.m16n8k16.row.col.f32.f16.f16.f32 " \
        "{%0,%1,%2,%3}, {%4,%5,%6,%7}, {%8,%9}, {%0,%1,%2,%3};" \
        : "+f"((d)[0]), "+f"((d)[1]), "+f"((d)[2]), "+f"((d)[3]) \
        : "r"(a0), "r"(a1), "r"(a2), "r"(a3), "r"(b0), "r"(b1))
#define MMA_BF16(d, a0, a1, a2, a3, b0, b1) \
    asm volatile("mma.sync.aligned.m16n8k16.row.col.f32.bf16.bf16.f32 " \
        "{%0,%1,%2,%3}, {%4,%5,%6,%7}, {%8,%9}, {%0,%1,%2,%3};" \
        : "+f"((d)[0]), "+f"((d)[1]), "+f"((d)[2]), "+f"((d)[3]) \
        : "r"(a0), "r"(a1), "r"(a2), "r"(a3), "r"(b0), "r"(b1))

__device__ __forceinline__ void cp16(unsigned dst, const void* src, int src_bytes){
    asm volatile("cp.async.cg.shared.global [%0], [%1], 16, %2;"
        :: "r"(dst), "l"(src), "r"(src_bytes) : "memory");
}
#define CP_COMMIT() asm volatile("cp.async.commit_group;" ::: "memory")
#define CP_WAIT2()  asm volatile("cp.async.wait_group 2;" ::: "memory")

// ---------------- K0: zero scratch ----------------
__global__ void k_zero(){
    int i = blockIdx.x*blockDim.x + threadIdx.x;
    if (i < Nn){ g_deg[i] = 0; g_mscal[i] = 0.f; }
    if (i < Bn){ g_rowsum[i]=0.0; g_msum[i]=0.0; }
}

// ---------------- CSR build ----------------
__global__ void k_count(const int* __restrict__ dst){
    int e = blockIdx.x*blockDim.x + threadIdx.x;
    if (e < En) atomicAdd(&g_deg[dst[e]], 1);
}
__global__ void k_scan(){
    __shared__ int warp_sums[32];
    int t = threadIdx.x;
    int base = t*10;
    int local[10]; int s = 0;
    #pragma unroll
    for (int i=0;i<10;i++){ local[i]=s; s += g_deg[base+i]; }
    int lane = t&31, w = t>>5;
    int v = s;
    #pragma unroll
    for (int o=1;o<32;o<<=1){ int u=__shfl_up_sync(0xffffffffu,v,o); if(lane>=o) v+=u; }
    if (lane==31) warp_sums[w]=v;
    __syncthreads();
    if (w==0){
        int x = warp_sums[lane];
        #pragma unroll
        for (int o=1;o<32;o<<=1){ int u=__shfl_up_sync(0xffffffffu,x,o); if(lane>=o) x+=u; }
        warp_sums[lane]=x;
    }
    __syncthreads();
    int excl = v - s + (w>0 ? warp_sums[w-1] : 0);
    #pragma unroll
    for (int i=0;i<10;i++){ g_off[base+i]=excl+local[i]; g_pos[base+i]=excl+local[i]; }
    if (t==1023) g_off[Nn]=En;
}
__global__ void k_scatter(const int* __restrict__ dst){
    int e = blockIdx.x*blockDim.x + threadIdx.x;
    if (e < En){
        int p = atomicAdd(&g_pos[dst[e]], 1);
        g_eidx[p] = e;
    }
}

// ---------------- fused: emb row norms + fp16 fragment pack ----------------
__global__ void __launch_bounds__(256) k_bpacknorm(const float* __restrict__ emb){
    __shared__ float rows[8][Dn];
    int w = threadIdx.x>>5, lane = threadIdx.x&31;
    int row = blockIdx.x*8 + w;
    const float4* p = (const float4*)(emb + (size_t)row*Dn);
    float4 a = p[lane*2], b = p[lane*2+1];
    float ss = a.x*a.x+a.y*a.y+a.z*a.z+a.w*a.w + b.x*b.x+b.y*b.y+b.z*b.z+b.w*b.w;
    #pragma unroll
    for (int o=16;o;o>>=1) ss += __shfl_xor_sync(0xffffffffu, ss, o);
    if (lane==0) g_inorm[row] = 1.f / fmaxf(sqrtf(ss), 1e-12f);
    *(float4*)&rows[w][lane*8]   = a;
    *(float4*)&rows[w][lane*8+4] = b;
    __syncwarp();
    #pragma unroll
    for (int rep=0; rep<2; rep++){
        int s = lane + rep*32;
        int c = s>>2, t = s&3;
        int k0 = c*16 + 2*t;
        unsigned short h0=hfr(rows[w][k0]),   h1=hfr(rows[w][k0+1]);
        unsigned short h2=hfr(rows[w][k0+8]), h3=hfr(rows[w][k0+9]);
        uint2 o;
        o.x = ((unsigned)h1<<16) | h0;
        o.y = ((unsigned)h3<<16) | h2;
        g_bp[(size_t)row*64 + s] = o;
    }
}

// ---------------- K_setup: hv gather + q_w^T pack + posq (merged) ----------------
__global__ void k_setup(const float* __restrict__ emb, const int* __restrict__ iid,
                        const float* __restrict__ q_w, const float* __restrict__ pos_emb){
    int bid = blockIdx.x;
    int tid = threadIdx.x;
    if (bid < (Nn*Dn)/256){
        int i = bid*256 + tid;
        int n = i>>8, k = i&255;
        int id = iid[n];
        g_hv[i] = emb[(size_t)id*Dn + k] * g_inorm[id];
    } else if (bid < (Nn*Dn)/256 + (Dn*64)/256){
        int id = (bid - (Nn*Dn)/256)*256 + tid;
        int n = id>>6, s = id&63;
        int c = s>>2, t = s&3;
        int k0 = c*16 + 2*t;
        float v0=q_w[(size_t)k0*Dn+n], v1=q_w[(size_t)(k0+1)*Dn+n];
        float v2=q_w[(size_t)(k0+8)*Dn+n], v3=q_w[(size_t)(k0+9)*Dn+n];
        unsigned short h0=bfr(v0), h1=bfr(v1), h2=bfr(v2), h3=bfr(v3);
        unsigned short l0=bfr(v0-bff(h0)), l1=bfr(v1-bff(h1)), l2=bfr(v2-bff(h2)), l3=bfr(v3-bff(h3));
        uint4 o;
        o.x = ((unsigned)h1<<16) | h0;
        o.y = ((unsigned)h3<<16) | h2;
        o.z = ((unsigned)l1<<16) | l0;
        o.w = ((unsigned)l3<<16) | l2;
        g_qp[n*64 + s] = o;
    } else {
        int p = bid - (Nn*Dn)/256 - (Dn*64)/256;   // 0..19
        int d = tid;
        float s = 0.f;
        const float* pe = pos_emb + (size_t)p*Dn;
        for (int k=0;k<Dn;k++)
            s += pe[k] * q_w[(size_t)(Dn+k)*Dn + d];
        g_posq[p*Dn + d] = s;
    }
}

// ---------------- K3: fused gather GAT + bf16 hi/lo pack ----------------
__global__ void __launch_bounds__(256) k_gat(const int* __restrict__ src, const int* __restrict__ dis,
                      const float* __restrict__ dis_emb,
                      const float* __restrict__ pi_w, const float* __restrict__ M_w){
    __shared__ float hd[Dn];
    __shared__ float se[DEGMAX];
    __shared__ int   ssrc[DEGMAX];
    int d = blockIdx.x;
    int t = threadIdx.x;
    int beg = g_off[d], end = g_off[d+1];
    int deg = end - beg; if (deg > DEGMAX) deg = DEGMAX;
    float val = 0.f;
    if (deg > 0){
        hd[t] = g_hv[(size_t)d*Dn + t];
        __syncthreads();
        int warp = t>>5, lane = t&31;
        for (int slot=warp; slot<deg; slot+=8){
            int e = g_eidx[beg+slot];
            int s = src[e], di = dis[e];
            const float* hs = g_hv + (size_t)s*Dn;
            const float* he = dis_emb + (size_t)di*Dn;
            float e1 = 0.f, g = 0.f;
            for (int k=lane;k<Dn;k+=32){
                float a = hs[k], b = hd[k], c = he[k];
                float p = a*b;
                e1 += p*c*pi_w[k];
                g  += p*M_w[k] + c*M_w[Dn+k];
            }
            #pragma unroll
            for (int o=16;o;o>>=1){
                e1 += __shfl_xor_sync(0xffffffffu, e1, o);
                g  += __shfl_xor_sync(0xffffffffu, g,  o);
            }
            if (lane==0){
                se[slot] = e1 * (1.f/(1.f+__expf(-g)));
                ssrc[slot] = s;
            }
        }
        __syncthreads();
        float mx = -3.4e38f;
        for (int i=0;i<deg;i++) mx = fmaxf(mx, se[i]);
        float acc = 0.f, asum = 0.f;
        for (int i=0;i<deg;i++){
            float a = __expf(se[i]-mx);
            asum += a;
            acc += a * g_hv[(size_t)ssrc[i]*Dn + t];
        }
        val = acc / asum;
        __syncthreads();   // hd reads done before overwrite below
    }
    g_h[(size_t)d*Dn + t] = val;
    hd[t] = val;
    __syncthreads();
    if (t < 64){
        int s = t;
        int c = s>>2, tq = s&3;
        int k0 = c*16 + 2*tq;
        float v0=hd[k0], v1=hd[k0+1], v2=hd[k0+8], v3=hd[k0+9];
        unsigned short h0=bfr(v0), h1=bfr(v1), h2=bfr(v2), h3=bfr(v3);
        unsigned short l0=bfr(v0-bff(h0)), l1=bfr(v1-bff(h1)), l2=bfr(v2-bff(h2)), l3=bfr(v3-bff(h3));
        uint4 o;
        o.x = ((unsigned)h1<<16) | h0;
        o.y = ((unsigned)h3<<16) | h2;
        o.z = ((unsigned)l1<<16) | l0;
        o.w = ((unsigned)l3<<16) | l2;
        g_hp[d*64 + s] = o;
    }
}

// ---------------- K6: f = concat(h_t, last_feat) @ r_w ----------------
__global__ void k_f(const int* __restrict__ tid_, const int* __restrict__ last_idx,
                    const float* __restrict__ target_emb, const float* __restrict__ r_w){
    __shared__ float sin_[8][2*Dn];
    int b0 = blockIdx.x*8;
    int t = threadIdx.x;
    for (int idx=t; idx<8*2*Dn; idx+=256){
        int j = idx>>9, k = idx&511;
        int b = b0+j;
        float v = (k<Dn) ? target_emb[(size_t)tid_[b]*Dn + k]
                         : g_h[(size_t)last_idx[b]*Dn + (k-Dn)];
        sin_[j][k] = v;
    }
    __syncthreads();
    float acc[8] = {0,0,0,0,0,0,0,0};
    int d = t;
    for (int k=0;k<2*Dn;k++){
        float w = r_w[(size_t)k*Dn + d];
        #pragma unroll
        for (int j=0;j<8;j++) acc[j] += sin_[j][k]*w;
    }
    #pragma unroll
    for (int j=0;j<8;j++) g_f[(size_t)(b0+j)*Dn + d] = acc[j];
}

// ---------------- K7: eagg via bf16 3-term mma ----------------
__global__ void __launch_bounds__(256) k_eagg_mma(){
    int tid = threadIdx.x;
    int w = tid>>5, lane = tid&31;
    int g = lane>>2, t = lane&3;
    int wm = w>>1, wn = w&1;
    int m0 = blockIdx.x*128;
    int n0 = blockIdx.y*128;

    int ar0 = m0 + wm*32 + g;
    const uint4* aptr[2][2];
    #pragma unroll
    for (int mi=0;mi<2;mi++)
        #pragma unroll
        for (int rp=0;rp<2;rp++)
            aptr[mi][rp] = g_hp + (ar0 + mi*16 + rp*8)*64 + t;
    const uint4* bptr[8];
    #pragma unroll
    for (int ni=0;ni<8;ni++)
        bptr[ni] = g_qp + (n0 + wn*64 + ni*8 + g)*64 + t;

    float acc[2][8][4];
    #pragma unroll
    for (int mi=0;mi<2;mi++)
        #pragma unroll
        for (int ni=0;ni<8;ni++)
            #pragma unroll
            for (int q=0;q<4;q++) acc[mi][ni][q]=0.f;

    #pragma unroll 2
    for (int c=0; c<16; c++){
        int so = c*4;
        uint4 A0[2], A1[2];
        #pragma unroll
        for (int mi=0;mi<2;mi++){
            A0[mi] = __ldg(aptr[mi][0] + so);
            A1[mi] = __ldg(aptr[mi][1] + so);
        }
        #pragma unroll
        for (int ni=0;ni<8;ni++){
            uint4 b = __ldg(bptr[ni] + so);
            #pragma unroll
            for (int mi=0;mi<2;mi++){
                MMA_BF16(acc[mi][ni], A0[mi].x, A1[mi].x, A0[mi].y, A1[mi].y, b.x, b.y);
                MMA_BF16(acc[mi][ni], A0[mi].x, A1[mi].x, A0[mi].y, A1[mi].y, b.z, b.w);
                MMA_BF16(acc[mi][ni], A0[mi].z, A1[mi].z, A0[mi].w, A1[mi].w, b.x, b.y);
            }
        }
    }

    float rsum[2][2] = {{0.f,0.f},{0.f,0.f}};
    #pragma unroll
    for (int mi=0;mi<2;mi++){
        #pragma unroll
        for (int rp=0;rp<2;rp++){
            int r = ar0 + mi*16 + rp*8;
            int p = r % Sn, se = r / Sn;
            const float* pq = g_posq + p*Dn;
            const float* ff = g_f + (size_t)se*Dn;
            float s = 0.f;
            #pragma unroll
            for (int ni=0;ni<8;ni++){
                int col = n0 + wn*64 + ni*8 + 2*t;
                float2 q2 = *(const float2*)(pq + col);
                float2 f2 = *(const float2*)(ff + col);
                float a0 = acc[mi][ni][rp*2+0], a1 = acc[mi][ni][rp*2+1];
                s += tanha(a0 + q2.x)*f2.x + tanha(a1 + q2.y)*f2.y;
            }
            rsum[mi][rp] = s;
        }
    }
    #pragma unroll
    for (int o=1;o<4;o<<=1)
        #pragma unroll
        for (int mi=0;mi<2;mi++)
            #pragma unroll
            for (int rp=0;rp<2;rp++)
                rsum[mi][rp] += __shfl_xor_sync(0xffffffffu, rsum[mi][rp], o);
    if (t==0){
        #pragma unroll
        for (int mi=0;mi<2;mi++)
            #pragma unroll
            for (int rp=0;rp<2;rp++)
                atomicAdd(&g_mscal[ar0 + mi*16 + rp*8], rsum[mi][rp]);
    }
}

// ---------------- K8: sr per session + l2norm + fp16 pack (fused apack) ----------------
__global__ void k_sr(){
    __shared__ float sm[Sn];
    __shared__ float sred[8];
    __shared__ float srow[Dn];
    int b = blockIdx.x, t = threadIdx.x;
    if (t<Sn) sm[t] = g_mscal[b*Sn + t];
    __syncthreads();
    float acc = 0.f;
    #pragma unroll
    for (int s=0;s<Sn;s++) acc += g_h[(size_t)(b*Sn+s)*Dn + t]*sm[s];
    float ss = acc*acc;
    #pragma unroll
    for (int o=16;o;o>>=1) ss += __shfl_xor_sync(0xffffffffu, ss, o);
    if ((t&31)==0) sred[t>>5] = ss;
    __syncthreads();
    float tot = 0.f;
    #pragma unroll
    for (int w=0;w<8;w++) tot += sred[w];
    float val = acc / fmaxf(sqrtf(tot), 1e-12f);
    g_srn[(size_t)b*Dn + t] = val;
    srow[t] = val;
    __syncthreads();
    if (t < 64){
        int s = t;
        int c = s>>2, tq = s&3;
        int k0 = c*16 + 2*tq;
        unsigned short h0=hfr(srow[k0]),   h1=hfr(srow[k0+1]);
        unsigned short h2=hfr(srow[k0+8]), h3=hfr(srow[k0+9]);
        uint2 o;
        o.x = ((unsigned)h1<<16) | h0;
        o.y = ((unsigned)h3<<16) | h2;
        g_ap[b*64 + s] = o;
    }
}

// ---------------- K9: phi head + masked logits (merged) ----------------
__global__ void k_phimask(const float* __restrict__ sc1_w, const float* __restrict__ sc1_b,
                          const float* __restrict__ sc2_w,
                          const int* __restrict__ iid, const float* __restrict__ emb){
    if (blockIdx.x < Bn/8){
        __shared__ float ssr[8][Dn];
        __shared__ float s_p[8][2];
        int b0 = blockIdx.x*8;
        int t = threadIdx.x;
        for (int idx=t; idx<8*Dn; idx+=256){
            int j = idx>>8, k = idx&255;
            ssr[j][k] = g_srn[(size_t)(b0+j)*Dn + k];
        }
        if (t<16) s_p[t>>1][t&1] = 0.f;
        __syncthreads();
        float acc[8] = {0,0,0,0,0,0,0,0};
        int d = t;
        for (int k=0;k<Dn;k++){
            float w = sc1_w[(size_t)k*Dn + d];
            #pragma unroll
            for (int j=0;j<8;j++) acc[j] += ssr[j][k]*w;
        }
        float bb = sc1_b[d], w0 = sc2_w[d*2], w1 = sc2_w[d*2+1];
        int lane = t&31;
        #pragma unroll
        for (int j=0;j<8;j++){
            float hid = fmaxf(acc[j]+bb, 0.f);
            float p0 = hid*w0, p1 = hid*w1;
            #pragma unroll
            for (int o=16;o;o>>=1){
                p0 += __shfl_xor_sync(0xffffffffu, p0, o);
                p1 += __shfl_xor_sync(0xffffffffu, p1, o);
            }
            if (lane==0){ atomicAdd(&s_p[j][0], p0); atomicAdd(&s_p[j][1], p1); }
        }
        __syncthreads();
        if (t<8){
            float a0 = s_p[t][0], a1 = s_p[t][1];
            float m = fmaxf(a0,a1);
            float lse = m + logf(__expf(a0-m)+__expf(a1-m));
            g_logphi[(b0+t)*2+0] = a0 - lse;
            g_logphi[(b0+t)*2+1] = a1 - lse;
        }
    } else {
        __shared__ int iids[Sn];
        __shared__ float s_sr[Dn];
        int b = blockIdx.x - Bn/8;
        int t = threadIdx.x;
        if (t<Sn) iids[t] = iid[b*Sn+t];
        if (t<Dn) s_sr[t] = g_srn[(size_t)b*Dn + t];
        __syncthreads();
        int warp = t>>5, lane = t&31;
        for (int slot=warp; slot<Sn; slot+=8){
            int v = iids[slot];
            bool dup = false;
            for (int j=0;j<slot;j++) if (iids[j]==v) { dup=true; break; }
            if (dup){
                if (lane==0) g_mask_v[b*Sn+slot] = -1;
                continue;
            }
            const float* ev = emb + (size_t)v*Dn;
            float dot = 0.f;
            for (int k=lane;k<Dn;k+=32) dot += s_sr[k]*ev[k];
            #pragma unroll
            for (int o=16;o;o>>=1) dot += __shfl_xor_sync(0xffffffffu, dot, o);
            if (lane==0){
                float l = dot * g_inorm[v] * 12.f;
                g_mask_v[b*Sn+slot] = v;
                g_mask_l[b*Sn+slot] = l;
                atomicAdd(&g_msum[b], (double)__expf(l-SHIFT));
            }
        }
    }
}

// ---------------- K11: cp.async-pipelined fp16 GEMM (1 sync/chunk) ----------------
#define NSTAGE 4
__global__ void __launch_bounds__(256,2) k_gemm_mma(float* __restrict__ out){
    __shared__ __align__(16) uint2 sA[NSTAGE][128][4];
    __shared__ __align__(16) uint2 sB[NSTAGE][128][4];
    int tid = threadIdx.x;
    int w = tid>>5, lane = tid&31;
    int g = lane>>2, t = lane&3;
    int wm = w>>1, wn = w&1;
    int m0 = blockIdx.x*128;
    int v0 = blockIdx.y*128;

    unsigned sAu = smem_u32(&sA[0][0][0]);
    unsigned sBu = smem_u32(&sB[0][0][0]);

    int srow = tid>>1, shalf = tid&1;
    int svrow = v0 + srow;
    int bbytes = (svrow < Vn) ? 16 : 0;
    const uint2* asrc0 = g_ap + (m0+srow)*64 + shalf*2;
    const uint2* bsrc0 = g_bp + (size_t)((svrow<Vn)?svrow:0)*64 + shalf*2;
    unsigned adst0 = sAu + (unsigned)((srow*4 + shalf*2)*8);
    unsigned bdst0 = sBu + (unsigned)((srow*4 + shalf*2)*8);

    float acc[2][8][4];
    #pragma unroll
    for (int mi=0;mi<2;mi++)
        #pragma unroll
        for (int ni=0;ni<8;ni++)
            #pragma unroll
            for (int q=0;q<4;q++) acc[mi][ni][q]=0.f;

    #pragma unroll
    for (int s=0;s<NSTAGE-1;s++){
        cp16(adst0 + (unsigned)(s*4096), asrc0 + s*4, 16);
        cp16(bdst0 + (unsigned)(s*4096), bsrc0 + s*4, bbytes);
        CP_COMMIT();
    }

    #pragma unroll 4
    for (int c=0; c<16; c++){
        CP_WAIT2();
        __syncthreads();
        int cn = c + NSTAGE - 1;
        if (cn < 16){
            int sn = cn & (NSTAGE-1);
            cp16(adst0 + (unsigned)(sn*4096), asrc0 + cn*4, 16);
            cp16(bdst0 + (unsigned)(sn*4096), bsrc0 + cn*4, bbytes);
        }
        CP_COMMIT();
        int st = c & (NSTAGE-1);
        uint2 A0[2], A1[2], Bf[8];
        #pragma unroll
        for (int mi=0;mi<2;mi++){
            A0[mi] = sA[st][wm*32 + mi*16 + g][t];
            A1[mi] = sA[st][wm*32 + mi*16 + 8 + g][t];
        }
        #pragma unroll
        for (int ni=0;ni<8;ni++)
            Bf[ni] = sB[st][wn*64 + ni*8 + g][t];
        #pragma unroll
        for (int ni=0;ni<8;ni++){
            #pragma unroll
            for (int mi=0;mi<2;mi++){
                MMA_F16(acc[mi][ni], A0[mi].x, A1[mi].x, A0[mi].y, A1[mi].y, Bf[ni].x, Bf[ni].y);
            }
        }
    }

    const float L2E = 1.44269504f;
    float rsum[4] = {0.f,0.f,0.f,0.f};
    #pragma unroll
    for (int mi=0;mi<2;mi++){
        int r0 = m0 + wm*32 + mi*16 + g;
        #pragma unroll
        for (int ni=0;ni<8;ni++){
            int col = v0 + wn*64 + ni*8 + 2*t;
            if (col < Vn){
                float s0 = 12.f*g_inorm[col], s1 = 12.f*g_inorm[col+1];
                float v00 = acc[mi][ni][0]*s0, v01 = acc[mi][ni][1]*s1;
                float v10 = acc[mi][ni][2]*s0, v11 = acc[mi][ni][3]*s1;
                float2* p0 = (float2*)(out + (size_t)r0*Vn + col);
                float2* p1 = (float2*)(out + (size_t)(r0+8)*Vn + col);
                __stcs(p0, make_float2(v00, v01));
                __stcs(p1, make_float2(v10, v11));
                rsum[mi*2+0] += exp2_pair_sum((v00-SHIFT)*L2E, (v01-SHIFT)*L2E);
                rsum[mi*2+1] += exp2_pair_sum((v10-SHIFT)*L2E, (v11-SHIFT)*L2E);
            }
        }
    }
    #pragma unroll
    for (int o=1;o<4;o<<=1)
        #pragma unroll
        for (int j=0;j<4;j++) rsum[j] += __shfl_xor_sync(0xffffffffu, rsum[j], o);
    if (t==0){
        #pragma unroll
        for (int j=0;j<4;j++){
            int row = m0 + wm*32 + (j>>1)*16 + (j&1)*8 + g;
            atomicAdd(&g_rowsum[row], (double)rsum[j]);
        }
    }
}

// ---------------- K12: per-row shift for unmasked entries ----------------
__global__ void k_finalize(float* __restrict__ out){
    __shared__ float s_shift;
    int row = blockIdx.y;
    if (threadIdx.x==0){
        double sex = g_rowsum[row] - g_msum[row];
        s_shift = g_logphi[row*2+1] - (float)((double)SHIFT + log(sex));
    }
    __syncthreads();
    float sh = s_shift;
    int i = blockIdx.x*blockDim.x + threadIdx.x;
    if (i < Vn/4){
        float4* p = (float4*)(out + (size_t)row*Vn) + i;
        float4 o = __ldcs(p);
        o.x += sh; o.y += sh; o.z += sh; o.w += sh;
        __stcs(p, o);
    }
}

// ---------------- K13: overwrite masked entries ----------------
__global__ void k_fixup(float* __restrict__ out){
    int b = blockIdx.x, s = threadIdx.x;
    if (s >= Sn) return;
    int v = g_mask_v[b*Sn+s];
    if (v < 0) return;
    float lse_in = (float)((double)SHIFT + log(g_msum[b]));
    out[(size_t)b*Vn + v] = g_mask_l[b*Sn+s] - lse_in + g_logphi[b*2+0];
}

// ---------------- launch ----------------
extern "C" void kernel_launch(void* const* d_in, const int* in_sizes, int n_in,
                              void* d_out, int out_size){
    const int* iid      = (const int*)d_in[0];
    const int* src      = (const int*)d_in[1];
    const int* dst      = (const int*)d_in[2];
    const int* dis      = (const int*)d_in[3];
    const int* tid_     = (const int*)d_in[7];
    const int* last_idx = (const int*)d_in[8];
    const float* emb        = (const float*)d_in[9];
    const float* pos_emb    = (const float*)d_in[10];
    const float* dis_emb    = (const float*)d_in[11];
    const float* target_emb = (const float*)d_in[12];
    const float* pi_w  = (const float*)d_in[13];
    const float* M_w   = (const float*)d_in[14];
    const float* q_w   = (const float*)d_in[15];
    const float* r_w   = (const float*)d_in[16];
    const float* sc1_w = (const float*)d_in[17];
    const float* sc1_b = (const float*)d_in[18];
    const float* sc2_w = (const float*)d_in[19];
    float* out = (float*)d_out;

    k_zero<<<(Nn+255)/256,256>>>();                      // 1
    k_count<<<En/256,256>>>(dst);                        // 2
    k_scan<<<1,1024>>>();                                // 3
    k_bpacknorm<<<Vn/8,256>>>(emb);                      // 4 (profiled slot)
    k_scatter<<<En/256,256>>>(dst);                      // 5
    int setup_blocks = (Nn*Dn)/256 + (Dn*64)/256 + Sn;
    k_setup<<<setup_blocks,256>>>(emb, iid, q_w, pos_emb); // 6
    k_gat<<<Nn,256>>>(src,dis,dis_emb,pi_w,M_w);         // 7
    k_f<<<Bn/8,256>>>(tid_,last_idx,target_emb,r_w);     // 8
    dim3 ge(Nn/128, 2);
    k_eagg_mma<<<ge,256>>>();                            // 9
    k_sr<<<Bn,256>>>();                                  // 10
    k_phimask<<<Bn/8 + Bn,256>>>(sc1_w,sc1_b,sc2_w,iid,emb); // 11
    dim3 gg(4, (Vn+127)/128);
    k_gemm_mma<<<gg, 256>>>(out);                        // 12
    dim3 gf((Vn/4 + 255)/256, Bn);
    k_finalize<<<gf,256>>>(out);                         // 13
    k_fixup<<<Bn,32>>>(out);                             // 14
}

// round 15
// speedup vs baseline: 2.5950x; 1.0939x over previous
#include <cuda_runtime.h>
#include <cuda_bf16.h>
#include <cuda_fp16.h>
#include <math.h>
#include <stdint.h>

#define Vn 100000
#define Dn 256
#define Bn 512
#define Sn 20
#define Nn (Bn*Sn)      // 10240
#define En (8*Nn)       // 81920
#define DEGMAX 128
#define SHIFT 4.0f

// ---------------- scratch ----------------
__device__ float g_inorm[Vn];
__device__ float g_hv[Nn*Dn];
__device__ float g_h[Nn*Dn];
__device__ float g_f[Bn*Dn];
__device__ float g_mscal[Nn];
__device__ float g_srn[Bn*Dn];
__device__ float g_logphi[Bn*2];
__device__ double g_rowsum[Bn];
__device__ double g_msum[Bn];
__device__ int   g_mask_v[Bn*Sn];
__device__ float g_mask_l[Bn*Sn];
// CSR
__device__ int g_deg[Nn];
__device__ int g_off[Nn+1];
__device__ int g_pos[Nn];
__device__ int g_eidx[En];
// packed big-GEMM operands (fp16 single-term)
__device__ uint2 g_bp[(size_t)Vn*64];   // 51.2 MB
__device__ uint2 g_ap[Bn*64];           // 0.25 MB
// eagg path
__device__ uint4 g_hp[Nn*64];           // 10.5 MB
__device__ uint4 g_qp[Dn*64];           // 0.26 MB
__device__ float g_posq[Sn*Dn];
// fp16 staging for unshifted logits
__device__ __half g_lt[(size_t)Bn*Vn];  // 102.4 MB

// ---------------- helpers ----------------
__device__ __forceinline__ unsigned short hfr(float x){
    __half h = __float2half_rn(x);
    return *(unsigned short*)&h;
}
__device__ __forceinline__ unsigned short bfr(float x){
    __nv_bfloat16 h = __float2bfloat16(x);
    return *(unsigned short*)&h;
}
__device__ __forceinline__ float bff(unsigned short u){
    __nv_bfloat16 h = *(__nv_bfloat16*)&u;
    return __bfloat162float(h);
}
__device__ __forceinline__ unsigned smem_u32(const void* p){
    unsigned a;
    asm("{ .reg .u64 t; cvta.to.shared.u64 t, %1; cvt.u32.u64 %0, t; }" : "=r"(a) : "l"(p));
    return a;
}
__device__ __forceinline__ float tanha(float x){
    float y; asm("tanh.approx.f32 %0, %1;" : "=f"(y) : "f"(x)); return y;
}
__device__ __forceinline__ float exp2_pair_sum(float y0, float y1){
    unsigned p, e;
    asm("cvt.rn.f16x2.f32 %0, %1, %2;" : "=r"(p) : "f"(y1), "f"(y0));
    asm("ex2.approx.f16x2 %0, %1;" : "=r"(e) : "r"(p));
    __half2 he = *reinterpret_cast<__half2*>(&e);
    float2 fe = __half22float2(he);
    return fe.x + fe.y;
}

#define MMA_F16(d, a0, a1, a2, a3, b0, b1) \
    asm volatile("mma.sync.aligned.m16n8k16.row.col.f32.f16.f16.f32 " \
        "{%0,%1,%2,%3}, {%4,%5,%6,%7}, {%8,%9}, {%0,%1,%2,%3};" \
        : "+f"((d)[0]), "+f"((d)[1]), "+f"((d)[2]), "+f"((d)[3]) \
        : "r"(a0), "r"(a1), "r"(a2), "r"(a3), "r"(b0), "r"(b1))
#define MMA_BF16(d, a0, a1, a2, a3, b0, b1) \
    asm volatile("mma.sync.aligned.m16n8k16.row.col.f32.bf16.bf16.f32 " \
        "{%0,%1,%2,%3}, {%4,%5,%6,%7}, {%8,%9}, {%0,%1,%2,%3};" \
        : "+f"((d)[0]), "+f"((d)[1]), "+f"((d)[2]), "+f"((d)[3]) \
        : "r"(a0), "r"(a1), "r"(a2), "r"(a3), "r"(b0), "r"(b1))

__device__ __forceinline__ void cp16(unsigned dst, const void* src, int src_bytes){
    asm volatile("cp.async.cg.shared.global [%0], [%1], 16, %2;"
        :: "r"(dst), "l"(src), "r"(src_bytes) : "memory");
}
#define CP_COMMIT() asm volatile("cp.async.commit_group;" ::: "memory")
#define CP_WAIT2()  asm volatile("cp.async.wait_group 2;" ::: "memory")

// ---------------- K0: zero scratch ----------------
__global__ void k_zero(){
    int i = blockIdx.x*blockDim.x + threadIdx.x;
    if (i < Nn){ g_deg[i] = 0; g_mscal[i] = 0.f; }
    if (i < Bn){ g_rowsum[i]=0.0; g_msum[i]=0.0; }
}

// ---------------- CSR build ----------------
__global__ void k_count(const int* __restrict__ dst){
    int e = blockIdx.x*blockDim.x + threadIdx.x;
    if (e < En) atomicAdd(&g_deg[dst[e]], 1);
}
__global__ void k_scan(){
    __shared__ int warp_sums[32];
    int t = threadIdx.x;
    int base = t*10;
    int local[10]; int s = 0;
    #pragma unroll
    for (int i=0;i<10;i++){ local[i]=s; s += g_deg[base+i]; }
    int lane = t&31, w = t>>5;
    int v = s;
    #pragma unroll
    for (int o=1;o<32;o<<=1){ int u=__shfl_up_sync(0xffffffffu,v,o); if(lane>=o) v+=u; }
    if (lane==31) warp_sums[w]=v;
    __syncthreads();
    if (w==0){
        int x = warp_sums[lane];
        #pragma unroll
        for (int o=1;o<32;o<<=1){ int u=__shfl_up_sync(0xffffffffu,x,o); if(lane>=o) x+=u; }
        warp_sums[lane]=x;
    }
    __syncthreads();
    int excl = v - s + (w>0 ? warp_sums[w-1] : 0);
    #pragma unroll
    for (int i=0;i<10;i++){ g_off[base+i]=excl+local[i]; g_pos[base+i]=excl+local[i]; }
    if (t==1023) g_off[Nn]=En;
}
__global__ void k_scatter(const int* __restrict__ dst){
    int e = blockIdx.x*blockDim.x + threadIdx.x;
    if (e < En){
        int p = atomicAdd(&g_pos[dst[e]], 1);
        g_eidx[p] = e;
    }
}

// ---------------- fused: emb row norms + fp16 fragment pack ----------------
__global__ void __launch_bounds__(256) k_bpacknorm(const float* __restrict__ emb){
    __shared__ float rows[8][Dn];
    int w = threadIdx.x>>5, lane = threadIdx.x&31;
    int row = blockIdx.x*8 + w;
    const float4* p = (const float4*)(emb + (size_t)row*Dn);
    float4 a = p[lane*2], b = p[lane*2+1];
    float ss = a.x*a.x+a.y*a.y+a.z*a.z+a.w*a.w + b.x*b.x+b.y*b.y+b.z*b.z+b.w*b.w;
    #pragma unroll
    for (int o=16;o;o>>=1) ss += __shfl_xor_sync(0xffffffffu, ss, o);
    if (lane==0) g_inorm[row] = 1.f / fmaxf(sqrtf(ss), 1e-12f);
    *(float4*)&rows[w][lane*8]   = a;
    *(float4*)&rows[w][lane*8+4] = b;
    __syncwarp();
    #pragma unroll
    for (int rep=0; rep<2; rep++){
        int s = lane + rep*32;
        int c = s>>2, t = s&3;
        int k0 = c*16 + 2*t;
        unsigned short h0=hfr(rows[w][k0]),   h1=hfr(rows[w][k0+1]);
        unsigned short h2=hfr(rows[w][k0+8]), h3=hfr(rows[w][k0+9]);
        uint2 o;
        o.x = ((unsigned)h1<<16) | h0;
        o.y = ((unsigned)h3<<16) | h2;
        g_bp[(size_t)row*64 + s] = o;
    }
}

// ---------------- K_setup: hv gather + q_w^T pack + posq (merged) ----------------
__global__ void k_setup(const float* __restrict__ emb, const int* __restrict__ iid,
                        const float* __restrict__ q_w, const float* __restrict__ pos_emb){
    int bid = blockIdx.x;
    int tid = threadIdx.x;
    if (bid < (Nn*Dn)/256){
        int i = bid*256 + tid;
        int n = i>>8, k = i&255;
        int id = iid[n];
        g_hv[i] = emb[(size_t)id*Dn + k] * g_inorm[id];
    } else if (bid < (Nn*Dn)/256 + (Dn*64)/256){
        int id = (bid - (Nn*Dn)/256)*256 + tid;
        int n = id>>6, s = id&63;
        int c = s>>2, t = s&3;
        int k0 = c*16 + 2*t;
        float v0=q_w[(size_t)k0*Dn+n], v1=q_w[(size_t)(k0+1)*Dn+n];
        float v2=q_w[(size_t)(k0+8)*Dn+n], v3=q_w[(size_t)(k0+9)*Dn+n];
        unsigned short h0=bfr(v0), h1=bfr(v1), h2=bfr(v2), h3=bfr(v3);
        unsigned short l0=bfr(v0-bff(h0)), l1=bfr(v1-bff(h1)), l2=bfr(v2-bff(h2)), l3=bfr(v3-bff(h3));
        uint4 o;
        o.x = ((unsigned)h1<<16) | h0;
        o.y = ((unsigned)h3<<16) | h2;
        o.z = ((unsigned)l1<<16) | l0;
        o.w = ((unsigned)l3<<16) | l2;
        g_qp[n*64 + s] = o;
    } else {
        int p = bid - (Nn*Dn)/256 - (Dn*64)/256;
        int d = tid;
        float s = 0.f;
        const float* pe = pos_emb + (size_t)p*Dn;
        for (int k=0;k<Dn;k++)
            s += pe[k] * q_w[(size_t)(Dn+k)*Dn + d];
        g_posq[p*Dn + d] = s;
    }
}

// ---------------- K3: fused gather GAT + bf16 hi/lo pack ----------------
__global__ void __launch_bounds__(256) k_gat(const int* __restrict__ src, const int* __restrict__ dis,
                      const float* __restrict__ dis_emb,
                      const float* __restrict__ pi_w, const float* __restrict__ M_w){
    __shared__ float hd[Dn];
    __shared__ float se[DEGMAX];
    __shared__ int   ssrc[DEGMAX];
    int d = blockIdx.x;
    int t = threadIdx.x;
    int beg = g_off[d], end = g_off[d+1];
    int deg = end - beg; if (deg > DEGMAX) deg = DEGMAX;
    float val = 0.f;
    if (deg > 0){
        hd[t] = g_hv[(size_t)d*Dn + t];
        __syncthreads();
        int warp = t>>5, lane = t&31;
        for (int slot=warp; slot<deg; slot+=8){
            int e = g_eidx[beg+slot];
            int s = src[e], di = dis[e];
            const float* hs = g_hv + (size_t)s*Dn;
            const float* he = dis_emb + (size_t)di*Dn;
            float e1 = 0.f, g = 0.f;
            for (int k=lane;k<Dn;k+=32){
                float a = hs[k], b = hd[k], c = he[k];
                float p = a*b;
                e1 += p*c*pi_w[k];
                g  += p*M_w[k] + c*M_w[Dn+k];
            }
            #pragma unroll
            for (int o=16;o;o>>=1){
                e1 += __shfl_xor_sync(0xffffffffu, e1, o);
                g  += __shfl_xor_sync(0xffffffffu, g,  o);
            }
            if (lane==0){
                se[slot] = e1 * (1.f/(1.f+__expf(-g)));
                ssrc[slot] = s;
            }
        }
        __syncthreads();
        float mx = -3.4e38f;
        for (int i=0;i<deg;i++) mx = fmaxf(mx, se[i]);
        float acc = 0.f, asum = 0.f;
        for (int i=0;i<deg;i++){
            float a = __expf(se[i]-mx);
            asum += a;
            acc += a * g_hv[(size_t)ssrc[i]*Dn + t];
        }
        val = acc / asum;
        __syncthreads();
    }
    g_h[(size_t)d*Dn + t] = val;
    hd[t] = val;
    __syncthreads();
    if (t < 64){
        int s = t;
        int c = s>>2, tq = s&3;
        int k0 = c*16 + 2*tq;
        float v0=hd[k0], v1=hd[k0+1], v2=hd[k0+8], v3=hd[k0+9];
        unsigned short h0=bfr(v0), h1=bfr(v1), h2=bfr(v2), h3=bfr(v3);
        unsigned short l0=bfr(v0-bff(h0)), l1=bfr(v1-bff(h1)), l2=bfr(v2-bff(h2)), l3=bfr(v3-bff(h3));
        uint4 o;
        o.x = ((unsigned)h1<<16) | h0;
        o.y = ((unsigned)h3<<16) | h2;
        o.z = ((unsigned)l1<<16) | l0;
        o.w = ((unsigned)l3<<16) | l2;
        g_hp[d*64 + s] = o;
    }
}

// ---------------- K6: f = concat(h_t, last_feat) @ r_w ----------------
__global__ void k_f(const int* __restrict__ tid_, const int* __restrict__ last_idx,
                    const float* __restrict__ target_emb, const float* __restrict__ r_w){
    __shared__ float sin_[8][2*Dn];
    int b0 = blockIdx.x*8;
    int t = threadIdx.x;
    for (int idx=t; idx<8*2*Dn; idx+=256){
        int j = idx>>9, k = idx&511;
        int b = b0+j;
        float v = (k<Dn) ? target_emb[(size_t)tid_[b]*Dn + k]
                         : g_h[(size_t)last_idx[b]*Dn + (k-Dn)];
        sin_[j][k] = v;
    }
    __syncthreads();
    float acc[8] = {0,0,0,0,0,0,0,0};
    int d = t;
    for (int k=0;k<2*Dn;k++){
        float w = r_w[(size_t)k*Dn + d];
        #pragma unroll
        for (int j=0;j<8;j++) acc[j] += sin_[j][k]*w;
    }
    #pragma unroll
    for (int j=0;j<8;j++) g_f[(size_t)(b0+j)*Dn + d] = acc[j];
}

// ---------------- K7: eagg via bf16 3-term mma ----------------
__global__ void __launch_bounds__(256) k_eagg_mma(){
    int tid = threadIdx.x;
    int w = tid>>5, lane = tid&31;
    int g = lane>>2, t = lane&3;
    int wm = w>>1, wn = w&1;
    int m0 = blockIdx.x*128;
    int n0 = blockIdx.y*128;

    int ar0 = m0 + wm*32 + g;
    const uint4* aptr[2][2];
    #pragma unroll
    for (int mi=0;mi<2;mi++)
        #pragma unroll
        for (int rp=0;rp<2;rp++)
            aptr[mi][rp] = g_hp + (ar0 + mi*16 + rp*8)*64 + t;
    const uint4* bptr[8];
    #pragma unroll
    for (int ni=0;ni<8;ni++)
        bptr[ni] = g_qp + (n0 + wn*64 + ni*8 + g)*64 + t;

    float acc[2][8][4];
    #pragma unroll
    for (int mi=0;mi<2;mi++)
        #pragma unroll
        for (int ni=0;ni<8;ni++)
            #pragma unroll
            for (int q=0;q<4;q++) acc[mi][ni][q]=0.f;

    #pragma unroll 2
    for (int c=0; c<16; c++){
        int so = c*4;
        uint4 A0[2], A1[2];
        #pragma unroll
        for (int mi=0;mi<2;mi++){
            A0[mi] = __ldg(aptr[mi][0] + so);
            A1[mi] = __ldg(aptr[mi][1] + so);
        }
        #pragma unroll
        for (int ni=0;ni<8;ni++){
            uint4 b = __ldg(bptr[ni] + so);
            #pragma unroll
            for (int mi=0;mi<2;mi++){
                MMA_BF16(acc[mi][ni], A0[mi].x, A1[mi].x, A0[mi].y, A1[mi].y, b.x, b.y);
                MMA_BF16(acc[mi][ni], A0[mi].x, A1[mi].x, A0[mi].y, A1[mi].y, b.z, b.w);
                MMA_BF16(acc[mi][ni], A0[mi].z, A1[mi].z, A0[mi].w, A1[mi].w, b.x, b.y);
            }
        }
    }

    float rsum[2][2] = {{0.f,0.f},{0.f,0.f}};
    #pragma unroll
    for (int mi=0;mi<2;mi++){
        #pragma unroll
        for (int rp=0;rp<2;rp++){
            int r = ar0 + mi*16 + rp*8;
            int p = r % Sn, se = r / Sn;
            const float* pq = g_posq + p*Dn;
            const float* ff = g_f + (size_t)se*Dn;
            float s = 0.f;
            #pragma unroll
            for (int ni=0;ni<8;ni++){
                int col = n0 + wn*64 + ni*8 + 2*t;
                float2 q2 = *(const float2*)(pq + col);
                float2 f2 = *(const float2*)(ff + col);
                float a0 = acc[mi][ni][rp*2+0], a1 = acc[mi][ni][rp*2+1];
                s += tanha(a0 + q2.x)*f2.x + tanha(a1 + q2.y)*f2.y;
            }
            rsum[mi][rp] = s;
        }
    }
    #pragma unroll
    for (int o=1;o<4;o<<=1)
        #pragma unroll
        for (int mi=0;mi<2;mi++)
            #pragma unroll
            for (int rp=0;rp<2;rp++)
                rsum[mi][rp] += __shfl_xor_sync(0xffffffffu, rsum[mi][rp], o);
    if (t==0){
        #pragma unroll
        for (int mi=0;mi<2;mi++)
            #pragma unroll
            for (int rp=0;rp<2;rp++)
                atomicAdd(&g_mscal[ar0 + mi*16 + rp*8], rsum[mi][rp]);
    }
}

// ---------------- K8: sr per session + l2norm + fp16 pack ----------------
__global__ void k_sr(){
    __shared__ float sm[Sn];
    __shared__ float sred[8];
    __shared__ float srow[Dn];
    int b = blockIdx.x, t = threadIdx.x;
    if (t<Sn) sm[t] = g_mscal[b*Sn + t];
    __syncthreads();
    float acc = 0.f;
    #pragma unroll
    for (int s=0;s<Sn;s++) acc += g_h[(size_t)(b*Sn+s)*Dn + t]*sm[s];
    float ss = acc*acc;
    #pragma unroll
    for (int o=16;o;o>>=1) ss += __shfl_xor_sync(0xffffffffu, ss, o);
    if ((t&31)==0) sred[t>>5] = ss;
    __syncthreads();
    float tot = 0.f;
    #pragma unroll
    for (int w=0;w<8;w++) tot += sred[w];
    float val = acc / fmaxf(sqrtf(tot), 1e-12f);
    g_srn[(size_t)b*Dn + t] = val;
    srow[t] = val;
    __syncthreads();
    if (t < 64){
        int s = t;
        int c = s>>2, tq = s&3;
        int k0 = c*16 + 2*tq;
        unsigned short h0=hfr(srow[k0]),   h1=hfr(srow[k0+1]);
        unsigned short h2=hfr(srow[k0+8]), h3=hfr(srow[k0+9]);
        uint2 o;
        o.x = ((unsigned)h1<<16) | h0;
        o.y = ((unsigned)h3<<16) | h2;
        g_ap[b*64 + s] = o;
    }
}

// ---------------- K9: phi head + masked logits (merged) ----------------
__global__ void k_phimask(const float* __restrict__ sc1_w, const float* __restrict__ sc1_b,
                          const float* __restrict__ sc2_w,
                          const int* __restrict__ iid, const float* __restrict__ emb){
    if (blockIdx.x < Bn/8){
        __shared__ float ssr[8][Dn];
        __shared__ float s_p[8][2];
        int b0 = blockIdx.x*8;
        int t = threadIdx.x;
        for (int idx=t; idx<8*Dn; idx+=256){
            int j = idx>>8, k = idx&255;
            ssr[j][k] = g_srn[(size_t)(b0+j)*Dn + k];
        }
        if (t<16) s_p[t>>1][t&1] = 0.f;
        __syncthreads();
        float acc[8] = {0,0,0,0,0,0,0,0};
        int d = t;
        for (int k=0;k<Dn;k++){
            float w = sc1_w[(size_t)k*Dn + d];
            #pragma unroll
            for (int j=0;j<8;j++) acc[j] += ssr[j][k]*w;
        }
        float bb = sc1_b[d], w0 = sc2_w[d*2], w1 = sc2_w[d*2+1];
        int lane = t&31;
        #pragma unroll
        for (int j=0;j<8;j++){
            float hid = fmaxf(acc[j]+bb, 0.f);
            float p0 = hid*w0, p1 = hid*w1;
            #pragma unroll
            for (int o=16;o;o>>=1){
                p0 += __shfl_xor_sync(0xffffffffu, p0, o);
                p1 += __shfl_xor_sync(0xffffffffu, p1, o);
            }
            if (lane==0){ atomicAdd(&s_p[j][0], p0); atomicAdd(&s_p[j][1], p1); }
        }
        __syncthreads();
        if (t<8){
            float a0 = s_p[t][0], a1 = s_p[t][1];
            float m = fmaxf(a0,a1);
            float lse = m + logf(__expf(a0-m)+__expf(a1-m));
            g_logphi[(b0+t)*2+0] = a0 - lse;
            g_logphi[(b0+t)*2+1] = a1 - lse;
        }
    } else {
        __shared__ int iids[Sn];
        __shared__ float s_sr[Dn];
        int b = blockIdx.x - Bn/8;
        int t = threadIdx.x;
        if (t<Sn) iids[t] = iid[b*Sn+t];
        if (t<Dn) s_sr[t] = g_srn[(size_t)b*Dn + t];
        __syncthreads();
        int warp = t>>5, lane = t&31;
        for (int slot=warp; slot<Sn; slot+=8){
            int v = iids[slot];
            bool dup = false;
            for (int j=0;j<slot;j++) if (iids[j]==v) { dup=true; break; }
            if (dup){
                if (lane==0) g_mask_v[b*Sn+slot] = -1;
                continue;
            }
            const float* ev = emb + (size_t)v*Dn;
            float dot = 0.f;
            for (int k=lane;k<Dn;k+=32) dot += s_sr[k]*ev[k];
            #pragma unroll
            for (int o=16;o;o>>=1) dot += __shfl_xor_sync(0xffffffffu, dot, o);
            if (lane==0){
                float l = dot * g_inorm[v] * 12.f;
                g_mask_v[b*Sn+slot] = v;
                g_mask_l[b*Sn+slot] = l;
                atomicAdd(&g_msum[b], (double)__expf(l-SHIFT));
            }
        }
    }
}

// ---------------- K11: cp.async-pipelined fp16 GEMM, fp16 logit staging ----------------
#define NSTAGE 4
__global__ void __launch_bounds__(256,2) k_gemm_mma(){
    __shared__ __align__(16) uint2 sA[NSTAGE][128][4];
    __shared__ __align__(16) uint2 sB[NSTAGE][128][4];
    int tid = threadIdx.x;
    int w = tid>>5, lane = tid&31;
    int g = lane>>2, t = lane&3;
    int wm = w>>1, wn = w&1;
    int m0 = blockIdx.x*128;
    int v0 = blockIdx.y*128;

    unsigned sAu = smem_u32(&sA[0][0][0]);
    unsigned sBu = smem_u32(&sB[0][0][0]);

    int srow = tid>>1, shalf = tid&1;
    int svrow = v0 + srow;
    int bbytes = (svrow < Vn) ? 16 : 0;
    const uint2* asrc0 = g_ap + (m0+srow)*64 + shalf*2;
    const uint2* bsrc0 = g_bp + (size_t)((svrow<Vn)?svrow:0)*64 + shalf*2;
    unsigned adst0 = sAu + (unsigned)((srow*4 + shalf*2)*8);
    unsigned bdst0 = sBu + (unsigned)((srow*4 + shalf*2)*8);

    float acc[2][8][4];
    #pragma unroll
    for (int mi=0;mi<2;mi++)
        #pragma unroll
        for (int ni=0;ni<8;ni++)
            #pragma unroll
            for (int q=0;q<4;q++) acc[mi][ni][q]=0.f;

    #pragma unroll
    for (int s=0;s<NSTAGE-1;s++){
        cp16(adst0 + (unsigned)(s*4096), asrc0 + s*4, 16);
        cp16(bdst0 + (unsigned)(s*4096), bsrc0 + s*4, bbytes);
        CP_COMMIT();
    }

    #pragma unroll 4
    for (int c=0; c<16; c++){
        CP_WAIT2();
        __syncthreads();
        int cn = c + NSTAGE - 1;
        if (cn < 16){
            int sn = cn & (NSTAGE-1);
            cp16(adst0 + (unsigned)(sn*4096), asrc0 + cn*4, 16);
            cp16(bdst0 + (unsigned)(sn*4096), bsrc0 + cn*4, bbytes);
        }
        CP_COMMIT();
        int st = c & (NSTAGE-1);
        uint2 A0[2], A1[2], Bf[8];
        #pragma unroll
        for (int mi=0;mi<2;mi++){
            A0[mi] = sA[st][wm*32 + mi*16 + g][t];
            A1[mi] = sA[st][wm*32 + mi*16 + 8 + g][t];
        }
        #pragma unroll
        for (int ni=0;ni<8;ni++)
            Bf[ni] = sB[st][wn*64 + ni*8 + g][t];
        #pragma unroll
        for (int ni=0;ni<8;ni++){
            #pragma unroll
            for (int mi=0;mi<2;mi++){
                MMA_F16(acc[mi][ni], A0[mi].x, A1[mi].x, A0[mi].y, A1[mi].y, Bf[ni].x, Bf[ni].y);
            }
        }
    }

    const float L2E = 1.44269504f;
    float rsum[4] = {0.f,0.f,0.f,0.f};
    #pragma unroll
    for (int mi=0;mi<2;mi++){
        int r0 = m0 + wm*32 + mi*16 + g;
        #pragma unroll
        for (int ni=0;ni<8;ni++){
            int col = v0 + wn*64 + ni*8 + 2*t;
            if (col < Vn){
                float s0 = 12.f*g_inorm[col], s1 = 12.f*g_inorm[col+1];
                float v00 = acc[mi][ni][0]*s0, v01 = acc[mi][ni][1]*s1;
                float v10 = acc[mi][ni][2]*s0, v11 = acc[mi][ni][3]*s1;
                __half2 h0 = __floats2half2_rn(v00, v01);
                __half2 h1 = __floats2half2_rn(v10, v11);
                unsigned* p0 = (unsigned*)(g_lt + (size_t)r0*Vn + col);
                unsigned* p1 = (unsigned*)(g_lt + (size_t)(r0+8)*Vn + col);
                __stcs(p0, *(unsigned*)&h0);
                __stcs(p1, *(unsigned*)&h1);
                rsum[mi*2+0] += exp2_pair_sum((v00-SHIFT)*L2E, (v01-SHIFT)*L2E);
                rsum[mi*2+1] += exp2_pair_sum((v10-SHIFT)*L2E, (v11-SHIFT)*L2E);
            }
        }
    }
    #pragma unroll
    for (int o=1;o<4;o<<=1)
        #pragma unroll
        for (int j=0;j<4;j++) rsum[j] += __shfl_xor_sync(0xffffffffu, rsum[j], o);
    if (t==0){
        #pragma unroll
        for (int j=0;j<4;j++){
            int row = m0 + wm*32 + (j>>1)*16 + (j&1)*8 + g;
            atomicAdd(&g_rowsum[row], (double)rsum[j]);
        }
    }
}

// ---------------- K12: shift + fp16->fp32 expand ----------------
__global__ void k_finalize(float* __restrict__ out){
    __shared__ float s_shift;
    int row = blockIdx.y;
    if (threadIdx.x==0){
        double sex = g_rowsum[row] - g_msum[row];
        s_shift = g_logphi[row*2+1] - (float)((double)SHIFT + log(sex));
    }
    __syncthreads();
    float sh = s_shift;
    int i = blockIdx.x*blockDim.x + threadIdx.x;   // 8 halves per thread
    if (i < Vn/8){
        const uint4* lp = (const uint4*)(g_lt + (size_t)row*Vn) + i;
        uint4 u = __ldcs(lp);
        __half2 a = *(__half2*)&u.x, b = *(__half2*)&u.y;
        __half2 cc = *(__half2*)&u.z, d = *(__half2*)&u.w;
        float2 fa = __half22float2(a), fb = __half22float2(b);
        float2 fc = __half22float2(cc), fd = __half22float2(d);
        float4* op = (float4*)(out + (size_t)row*Vn) + i*2;
        __stcs(op,   make_float4(fa.x+sh, fa.y+sh, fb.x+sh, fb.y+sh));
        __stcs(op+1, make_float4(fc.x+sh, fc.y+sh, fd.x+sh, fd.y+sh));
    }
}

// ---------------- K13: overwrite masked entries ----------------
__global__ void k_fixup(float* __restrict__ out){
    int b = blockIdx.x, s = threadIdx.x;
    if (s >= Sn) return;
    int v = g_mask_v[b*Sn+s];
    if (v < 0) return;
    float lse_in = (float)((double)SHIFT + log(g_msum[b]));
    out[(size_t)b*Vn + v] = g_mask_l[b*Sn+s] - lse_in + g_logphi[b*2+0];
}

// ---------------- launch ----------------
extern "C" void kernel_launch(void* const* d_in, const int* in_sizes, int n_in,
                              void* d_out, int out_size){
    const int* iid      = (const int*)d_in[0];
    const int* src      = (const int*)d_in[1];
    const int* dst      = (const int*)d_in[2];
    const int* dis      = (const int*)d_in[3];
    const int* tid_     = (const int*)d_in[7];
    const int* last_idx = (const int*)d_in[8];
    const float* emb        = (const float*)d_in[9];
    const float* pos_emb    = (const float*)d_in[10];
    const float* dis_emb    = (const float*)d_in[11];
    const float* target_emb = (const float*)d_in[12];
    const float* pi_w  = (const float*)d_in[13];
    const float* M_w   = (const float*)d_in[14];
    const float* q_w   = (const float*)d_in[15];
    const float* r_w   = (const float*)d_in[16];
    const float* sc1_w = (const float*)d_in[17];
    const float* sc1_b = (const float*)d_in[18];
    const float* sc2_w = (const float*)d_in[19];
    float* out = (float*)d_out;

    k_zero<<<(Nn+255)/256,256>>>();                      // 1
    k_count<<<En/256,256>>>(dst);                        // 2
    k_scan<<<1,1024>>>();                                // 3
    k_bpacknorm<<<Vn/8,256>>>(emb);                      // 4 (profiled slot)
    k_scatter<<<En/256,256>>>(dst);                      // 5
    int setup_blocks = (Nn*Dn)/256 + (Dn*64)/256 + Sn;
    k_setup<<<setup_blocks,256>>>(emb, iid, q_w, pos_emb); // 6
    k_gat<<<Nn,256>>>(src,dis,dis_emb,pi_w,M_w);         // 7
    k_f<<<Bn/8,256>>>(tid_,last_idx,target_emb,r_w);     // 8
    dim3 ge(Nn/128, 2);
    k_eagg_mma<<<ge,256>>>();                            // 9
    k_sr<<<Bn,256>>>();                                  // 10
    k_phimask<<<Bn/8 + Bn,256>>>(sc1_w,sc1_b,sc2_w,iid,emb); // 11
    dim3 gg(4, (Vn+127)/128);
    k_gemm_mma<<<gg, 256>>>();                           // 12
    dim3 gf((Vn/8 + 255)/256, Bn);
    k_finalize<<<gf,256>>>(out);                         // 13
    k_fixup<<<Bn,32>>>(out);                             // 14
}

// round 16
// speedup vs baseline: 2.6200x; 1.0096x over previous
#include <cuda_runtime.h>
#include <cuda_bf16.h>
#include <cuda_fp16.h>
#include <math.h>
#include <stdint.h>

#define Vn 100000
#define Dn 256
#define Bn 512
#define Sn 20
#define Nn (Bn*Sn)      // 10240
#define En (8*Nn)       // 81920
#define DEGMAX 128
#define DCACHE 24
#define SHIFT 4.0f

// ---------------- scratch ----------------
__device__ float g_inorm[Vn];
__device__ float g_hv[Nn*Dn];
__device__ float g_h[Nn*Dn];
__device__ float g_f[Bn*Dn];
__device__ float g_mscal[Nn];
__device__ float g_srn[Bn*Dn];
__device__ float g_logphi[Bn*2];
__device__ double g_rowsum[Bn];
__device__ double g_msum[Bn];
__device__ int   g_mask_v[Bn*Sn];
__device__ float g_mask_l[Bn*Sn];
// CSR
__device__ int g_deg[Nn];
__device__ int g_off[Nn+1];
__device__ int g_pos[Nn];
__device__ int g_eidx[En];
// packed big-GEMM operands (fp16 single-term)
__device__ uint2 g_bp[(size_t)Vn*64];   // 51.2 MB
__device__ uint2 g_ap[Bn*64];           // 0.25 MB
// eagg path
__device__ uint4 g_hp[Nn*64];           // 10.5 MB
__device__ uint4 g_qp[Dn*64];           // 0.26 MB
__device__ float g_posq[Sn*Dn];
// fp16 staging for unshifted logits (kept L2-resident: plain stores)
__device__ __half g_lt[(size_t)Bn*Vn];  // 102.4 MB

// ---------------- helpers ----------------
__device__ __forceinline__ unsigned short hfr(float x){
    __half h = __float2half_rn(x);
    return *(unsigned short*)&h;
}
__device__ __forceinline__ unsigned short bfr(float x){
    __nv_bfloat16 h = __float2bfloat16(x);
    return *(unsigned short*)&h;
}
__device__ __forceinline__ float bff(unsigned short u){
    __nv_bfloat16 h = *(__nv_bfloat16*)&u;
    return __bfloat162float(h);
}
__device__ __forceinline__ unsigned smem_u32(const void* p){
    unsigned a;
    asm("{ .reg .u64 t; cvta.to.shared.u64 t, %1; cvt.u32.u64 %0, t; }" : "=r"(a) : "l"(p));
    return a;
}
__device__ __forceinline__ float tanha(float x){
    float y; asm("tanh.approx.f32 %0, %1;" : "=f"(y) : "f"(x)); return y;
}
__device__ __forceinline__ float exp2_pair_sum(float y0, float y1){
    unsigned p, e;
    asm("cvt.rn.f16x2.f32 %0, %1, %2;" : "=r"(p) : "f"(y1), "f"(y0));
    asm("ex2.approx.f16x2 %0, %1;" : "=r"(e) : "r"(p));
    __half2 he = *reinterpret_cast<__half2*>(&e);
    float2 fe = __half22float2(he);
    return fe.x + fe.y;
}

#define MMA_F16(d, a0, a1, a2, a3, b0, b1) \
    asm volatile("mma.sync.aligned.m16n8k16.row.col.f32.f16.f16.f32 " \
        "{%0,%1,%2,%3}, {%4,%5,%6,%7}, {%8,%9}, {%0,%1,%2,%3};" \
        : "+f"((d)[0]), "+f"((d)[1]), "+f"((d)[2]), "+f"((d)[3]) \
        : "r"(a0), "r"(a1), "r"(a2), "r"(a3), "r"(b0), "r"(b1))
#define MMA_BF16(d, a0, a1, a2, a3, b0, b1) \
    asm volatile("mma.sync.aligned.m16n8k16.row.col.f32.bf16.bf16.f32 " \
        "{%0,%1,%2,%3}, {%4,%5,%6,%7}, {%8,%9}, {%0,%1,%2,%3};" \
        : "+f"((d)[0]), "+f"((d)[1]), "+f"((d)[2]), "+f"((d)[3]) \
        : "r"(a0), "r"(a1), "r"(a2), "r"(a3), "r"(b0), "r"(b1))

__device__ __forceinline__ void cp16(unsigned dst, const void* src, int src_bytes){
    asm volatile("cp.async.cg.shared.global [%0], [%1], 16, %2;"
        :: "r"(dst), "l"(src), "r"(src_bytes) : "memory");
}
#define CP_COMMIT() asm volatile("cp.async.commit_group;" ::: "memory")
#define CP_WAIT2()  asm volatile("cp.async.wait_group 2;" ::: "memory")

// ---------------- K0: zero scratch ----------------
__global__ void k_zero(){
    int i = blockIdx.x*blockDim.x + threadIdx.x;
    if (i < Nn){ g_deg[i] = 0; g_mscal[i] = 0.f; }
    if (i < Bn){ g_rowsum[i]=0.0; g_msum[i]=0.0; }
}

// ---------------- CSR build ----------------
__global__ void k_count(const int* __restrict__ dst){
    int e = blockIdx.x*blockDim.x + threadIdx.x;
    if (e < En) atomicAdd(&g_deg[dst[e]], 1);
}
__global__ void k_scan(){
    __shared__ int warp_sums[32];
    int t = threadIdx.x;
    int base = t*10;
    int local[10]; int s = 0;
    #pragma unroll
    for (int i=0;i<10;i++){ local[i]=s; s += g_deg[base+i]; }
    int lane = t&31, w = t>>5;
    int v = s;
    #pragma unroll
    for (int o=1;o<32;o<<=1){ int u=__shfl_up_sync(0xffffffffu,v,o); if(lane>=o) v+=u; }
    if (lane==31) warp_sums[w]=v;
    __syncthreads();
    if (w==0){
        int x = warp_sums[lane];
        #pragma unroll
        for (int o=1;o<32;o<<=1){ int u=__shfl_up_sync(0xffffffffu,x,o); if(lane>=o) x+=u; }
        warp_sums[lane]=x;
    }
    __syncthreads();
    int excl = v - s + (w>0 ? warp_sums[w-1] : 0);
    #pragma unroll
    for (int i=0;i<10;i++){ g_off[base+i]=excl+local[i]; g_pos[base+i]=excl+local[i]; }
    if (t==1023) g_off[Nn]=En;
}
__global__ void k_scatter(const int* __restrict__ dst){
    int e = blockIdx.x*blockDim.x + threadIdx.x;
    if (e < En){
        int p = atomicAdd(&g_pos[dst[e]], 1);
        g_eidx[p] = e;
    }
}

// ---------------- fused: emb row norms + fp16 fragment pack ----------------
__global__ void __launch_bounds__(256) k_bpacknorm(const float* __restrict__ emb){
    __shared__ float rows[8][Dn];
    int w = threadIdx.x>>5, lane = threadIdx.x&31;
    int row = blockIdx.x*8 + w;
    const float4* p = (const float4*)(emb + (size_t)row*Dn);
    float4 a = p[lane*2], b = p[lane*2+1];
    float ss = a.x*a.x+a.y*a.y+a.z*a.z+a.w*a.w + b.x*b.x+b.y*b.y+b.z*b.z+b.w*b.w;
    #pragma unroll
    for (int o=16;o;o>>=1) ss += __shfl_xor_sync(0xffffffffu, ss, o);
    if (lane==0) g_inorm[row] = 1.f / fmaxf(sqrtf(ss), 1e-12f);
    *(float4*)&rows[w][lane*8]   = a;
    *(float4*)&rows[w][lane*8+4] = b;
    __syncwarp();
    #pragma unroll
    for (int rep=0; rep<2; rep++){
        int s = lane + rep*32;
        int c = s>>2, t = s&3;
        int k0 = c*16 + 2*t;
        unsigned short h0=hfr(rows[w][k0]),   h1=hfr(rows[w][k0+1]);
        unsigned short h2=hfr(rows[w][k0+8]), h3=hfr(rows[w][k0+9]);
        uint2 o;
        o.x = ((unsigned)h1<<16) | h0;
        o.y = ((unsigned)h3<<16) | h2;
        g_bp[(size_t)row*64 + s] = o;
    }
}

// ---------------- K_setup: hv gather + q_w^T pack + posq (merged) ----------------
__global__ void k_setup(const float* __restrict__ emb, const int* __restrict__ iid,
                        const float* __restrict__ q_w, const float* __restrict__ pos_emb){
    int bid = blockIdx.x;
    int tid = threadIdx.x;
    if (bid < (Nn*Dn)/256){
        int i = bid*256 + tid;
        int n = i>>8, k = i&255;
        int id = iid[n];
        g_hv[i] = emb[(size_t)id*Dn + k] * g_inorm[id];
    } else if (bid < (Nn*Dn)/256 + (Dn*64)/256){
        int id = (bid - (Nn*Dn)/256)*256 + tid;
        int n = id>>6, s = id&63;
        int c = s>>2, t = s&3;
        int k0 = c*16 + 2*t;
        float v0=q_w[(size_t)k0*Dn+n], v1=q_w[(size_t)(k0+1)*Dn+n];
        float v2=q_w[(size_t)(k0+8)*Dn+n], v3=q_w[(size_t)(k0+9)*Dn+n];
        unsigned short h0=bfr(v0), h1=bfr(v1), h2=bfr(v2), h3=bfr(v3);
        unsigned short l0=bfr(v0-bff(h0)), l1=bfr(v1-bff(h1)), l2=bfr(v2-bff(h2)), l3=bfr(v3-bff(h3));
        uint4 o;
        o.x = ((unsigned)h1<<16) | h0;
        o.y = ((unsigned)h3<<16) | h2;
        o.z = ((unsigned)l1<<16) | l0;
        o.w = ((unsigned)l3<<16) | l2;
        g_qp[n*64 + s] = o;
    } else {
        int p = bid - (Nn*Dn)/256 - (Dn*64)/256;
        int d = tid;
        float s = 0.f;
        const float* pe = pos_emb + (size_t)p*Dn;
        for (int k=0;k<Dn;k++)
            s += pe[k] * q_w[(size_t)(Dn+k)*Dn + d];
        g_posq[p*Dn + d] = s;
    }
}

// ---------------- K3: fused gather GAT + bf16 hi/lo pack (src rows cached in smem) ----------------
__global__ void __launch_bounds__(256) k_gat(const int* __restrict__ src, const int* __restrict__ dis,
                      const float* __restrict__ dis_emb,
                      const float* __restrict__ pi_w, const float* __restrict__ M_w){
    __shared__ float hd[Dn];
    __shared__ float se[DEGMAX];
    __shared__ int   ssrc[DEGMAX];
    __shared__ float cache[DCACHE][Dn];   // 24 KB: first DCACHE source rows
    int d = blockIdx.x;
    int t = threadIdx.x;
    int beg = g_off[d], end = g_off[d+1];
    int deg = end - beg; if (deg > DEGMAX) deg = DEGMAX;
    float val = 0.f;
    if (deg > 0){
        hd[t] = g_hv[(size_t)d*Dn + t];
        __syncthreads();
        int warp = t>>5, lane = t&31;
        for (int slot=warp; slot<deg; slot+=8){
            int e = g_eidx[beg+slot];
            int s = src[e], di = dis[e];
            const float* hs = g_hv + (size_t)s*Dn;
            const float* he = dis_emb + (size_t)di*Dn;
            float e1 = 0.f, g = 0.f;
            bool cz = (slot < DCACHE);
            for (int k=lane;k<Dn;k+=32){
                float a = hs[k], b = hd[k], c = he[k];
                if (cz) cache[slot][k] = a;
                float p = a*b;
                e1 += p*c*pi_w[k];
                g  += p*M_w[k] + c*M_w[Dn+k];
            }
            #pragma unroll
            for (int o=16;o;o>>=1){
                e1 += __shfl_xor_sync(0xffffffffu, e1, o);
                g  += __shfl_xor_sync(0xffffffffu, g,  o);
            }
            if (lane==0){
                se[slot] = e1 * (1.f/(1.f+__expf(-g)));
                ssrc[slot] = s;
            }
        }
        __syncthreads();
        float mx = -3.4e38f;
        for (int i=0;i<deg;i++) mx = fmaxf(mx, se[i]);
        float acc = 0.f, asum = 0.f;
        for (int i=0;i<deg;i++){
            float a = __expf(se[i]-mx);
            asum += a;
            float hv = (i < DCACHE) ? cache[i][t] : g_hv[(size_t)ssrc[i]*Dn + t];
            acc += a * hv;
        }
        val = acc / asum;
        __syncthreads();
    }
    g_h[(size_t)d*Dn + t] = val;
    hd[t] = val;
    __syncthreads();
    if (t < 64){
        int s = t;
        int c = s>>2, tq = s&3;
        int k0 = c*16 + 2*tq;
        float v0=hd[k0], v1=hd[k0+1], v2=hd[k0+8], v3=hd[k0+9];
        unsigned short h0=bfr(v0), h1=bfr(v1), h2=bfr(v2), h3=bfr(v3);
        unsigned short l0=bfr(v0-bff(h0)), l1=bfr(v1-bff(h1)), l2=bfr(v2-bff(h2)), l3=bfr(v3-bff(h3));
        uint4 o;
        o.x = ((unsigned)h1<<16) | h0;
        o.y = ((unsigned)h3<<16) | h2;
        o.z = ((unsigned)l1<<16) | l0;
        o.w = ((unsigned)l3<<16) | l2;
        g_hp[d*64 + s] = o;
    }
}

// ---------------- K6: f = concat(h_t, last_feat) @ r_w ----------------
__global__ void k_f(const int* __restrict__ tid_, const int* __restrict__ last_idx,
                    const float* __restrict__ target_emb, const float* __restrict__ r_w){
    __shared__ float sin_[8][2*Dn];
    int b0 = blockIdx.x*8;
    int t = threadIdx.x;
    for (int idx=t; idx<8*2*Dn; idx+=256){
        int j = idx>>9, k = idx&511;
        int b = b0+j;
        float v = (k<Dn) ? target_emb[(size_t)tid_[b]*Dn + k]
                         : g_h[(size_t)last_idx[b]*Dn + (k-Dn)];
        sin_[j][k] = v;
    }
    __syncthreads();
    float acc[8] = {0,0,0,0,0,0,0,0};
    int d = t;
    for (int k=0;k<2*Dn;k++){
        float w = r_w[(size_t)k*Dn + d];
        #pragma unroll
        for (int j=0;j<8;j++) acc[j] += sin_[j][k]*w;
    }
    #pragma unroll
    for (int j=0;j<8;j++) g_f[(size_t)(b0+j)*Dn + d] = acc[j];
}

// ---------------- K7: eagg via bf16 3-term mma ----------------
__global__ void __launch_bounds__(256) k_eagg_mma(){
    int tid = threadIdx.x;
    int w = tid>>5, lane = tid&31;
    int g = lane>>2, t = lane&3;
    int wm = w>>1, wn = w&1;
    int m0 = blockIdx.x*128;
    int n0 = blockIdx.y*128;

    int ar0 = m0 + wm*32 + g;
    const uint4* aptr[2][2];
    #pragma unroll
    for (int mi=0;mi<2;mi++)
        #pragma unroll
        for (int rp=0;rp<2;rp++)
            aptr[mi][rp] = g_hp + (ar0 + mi*16 + rp*8)*64 + t;
    const uint4* bptr[8];
    #pragma unroll
    for (int ni=0;ni<8;ni++)
        bptr[ni] = g_qp + (n0 + wn*64 + ni*8 + g)*64 + t;

    float acc[2][8][4];
    #pragma unroll
    for (int mi=0;mi<2;mi++)
        #pragma unroll
        for (int ni=0;ni<8;ni++)
            #pragma unroll
            for (int q=0;q<4;q++) acc[mi][ni][q]=0.f;

    #pragma unroll 2
    for (int c=0; c<16; c++){
        int so = c*4;
        uint4 A0[2], A1[2];
        #pragma unroll
        for (int mi=0;mi<2;mi++){
            A0[mi] = __ldg(aptr[mi][0] + so);
            A1[mi] = __ldg(aptr[mi][1] + so);
        }
        #pragma unroll
        for (int ni=0;ni<8;ni++){
            uint4 b = __ldg(bptr[ni] + so);
            #pragma unroll
            for (int mi=0;mi<2;mi++){
                MMA_BF16(acc[mi][ni], A0[mi].x, A1[mi].x, A0[mi].y, A1[mi].y, b.x, b.y);
                MMA_BF16(acc[mi][ni], A0[mi].x, A1[mi].x, A0[mi].y, A1[mi].y, b.z, b.w);
                MMA_BF16(acc[mi][ni], A0[mi].z, A1[mi].z, A0[mi].w, A1[mi].w, b.x, b.y);
            }
        }
    }

    float rsum[2][2] = {{0.f,0.f},{0.f,0.f}};
    #pragma unroll
    for (int mi=0;mi<2;mi++){
        #pragma unroll
        for (int rp=0;rp<2;rp++){
            int r = ar0 + mi*16 + rp*8;
            int p = r % Sn, se = r / Sn;
            const float* pq = g_posq + p*Dn;
            const float* ff = g_f + (size_t)se*Dn;
            float s = 0.f;
            #pragma unroll
            for (int ni=0;ni<8;ni++){
                int col = n0 + wn*64 + ni*8 + 2*t;
                float2 q2 = *(const float2*)(pq + col);
                float2 f2 = *(const float2*)(ff + col);
                float a0 = acc[mi][ni][rp*2+0], a1 = acc[mi][ni][rp*2+1];
                s += tanha(a0 + q2.x)*f2.x + tanha(a1 + q2.y)*f2.y;
            }
            rsum[mi][rp] = s;
        }
    }
    #pragma unroll
    for (int o=1;o<4;o<<=1)
        #pragma unroll
        for (int mi=0;mi<2;mi++)
            #pragma unroll
            for (int rp=0;rp<2;rp++)
                rsum[mi][rp] += __shfl_xor_sync(0xffffffffu, rsum[mi][rp], o);
    if (t==0){
        #pragma unroll
        for (int mi=0;mi<2;mi++)
            #pragma unroll
            for (int rp=0;rp<2;rp++)
                atomicAdd(&g_mscal[ar0 + mi*16 + rp*8], rsum[mi][rp]);
    }
}

// ---------------- K8: sr per session + l2norm + fp16 pack ----------------
__global__ void k_sr(){
    __shared__ float sm[Sn];
    __shared__ float sred[8];
    __shared__ float srow[Dn];
    int b = blockIdx.x, t = threadIdx.x;
    if (t<Sn) sm[t] = g_mscal[b*Sn + t];
    __syncthreads();
    float acc = 0.f;
    #pragma unroll
    for (int s=0;s<Sn;s++) acc += g_h[(size_t)(b*Sn+s)*Dn + t]*sm[s];
    float ss = acc*acc;
    #pragma unroll
    for (int o=16;o;o>>=1) ss += __shfl_xor_sync(0xffffffffu, ss, o);
    if ((t&31)==0) sred[t>>5] = ss;
    __syncthreads();
    float tot = 0.f;
    #pragma unroll
    for (int w=0;w<8;w++) tot += sred[w];
    float val = acc / fmaxf(sqrtf(tot), 1e-12f);
    g_srn[(size_t)b*Dn + t] = val;
    srow[t] = val;
    __syncthreads();
    if (t < 64){
        int s = t;
        int c = s>>2, tq = s&3;
        int k0 = c*16 + 2*tq;
        unsigned short h0=hfr(srow[k0]),   h1=hfr(srow[k0+1]);
        unsigned short h2=hfr(srow[k0+8]), h3=hfr(srow[k0+9]);
        uint2 o;
        o.x = ((unsigned)h1<<16) | h0;
        o.y = ((unsigned)h3<<16) | h2;
        g_ap[b*64 + s] = o;
    }
}

// ---------------- K9: phi head + masked logits (merged) ----------------
__global__ void k_phimask(const float* __restrict__ sc1_w, const float* __restrict__ sc1_b,
                          const float* __restrict__ sc2_w,
                          const int* __restrict__ iid, const float* __restrict__ emb){
    if (blockIdx.x < Bn/8){
        __shared__ float ssr[8][Dn];
        __shared__ float s_p[8][2];
        int b0 = blockIdx.x*8;
        int t = threadIdx.x;
        for (int idx=t; idx<8*Dn; idx+=256){
            int j = idx>>8, k = idx&255;
            ssr[j][k] = g_srn[(size_t)(b0+j)*Dn + k];
        }
        if (t<16) s_p[t>>1][t&1] = 0.f;
        __syncthreads();
        float acc[8] = {0,0,0,0,0,0,0,0};
        int d = t;
        for (int k=0;k<Dn;k++){
            float w = sc1_w[(size_t)k*Dn + d];
            #pragma unroll
            for (int j=0;j<8;j++) acc[j] += ssr[j][k]*w;
        }
        float bb = sc1_b[d], w0 = sc2_w[d*2], w1 = sc2_w[d*2+1];
        int lane = t&31;
        #pragma unroll
        for (int j=0;j<8;j++){
            float hid = fmaxf(acc[j]+bb, 0.f);
            float p0 = hid*w0, p1 = hid*w1;
            #pragma unroll
            for (int o=16;o;o>>=1){
                p0 += __shfl_xor_sync(0xffffffffu, p0, o);
                p1 += __shfl_xor_sync(0xffffffffu, p1, o);
            }
            if (lane==0){ atomicAdd(&s_p[j][0], p0); atomicAdd(&s_p[j][1], p1); }
        }
        __syncthreads();
        if (t<8){
            float a0 = s_p[t][0], a1 = s_p[t][1];
            float m = fmaxf(a0,a1);
            float lse = m + logf(__expf(a0-m)+__expf(a1-m));
            g_logphi[(b0+t)*2+0] = a0 - lse;
            g_logphi[(b0+t)*2+1] = a1 - lse;
        }
    } else {
        __shared__ int iids[Sn];
        __shared__ float s_sr[Dn];
        int b = blockIdx.x - Bn/8;
        int t = threadIdx.x;
        if (t<Sn) iids[t] = iid[b*Sn+t];
        if (t<Dn) s_sr[t] = g_srn[(size_t)b*Dn + t];
        __syncthreads();
        int warp = t>>5, lane = t&31;
        for (int slot=warp; slot<Sn; slot+=8){
            int v = iids[slot];
            bool dup = false;
            for (int j=0;j<slot;j++) if (iids[j]==v) { dup=true; break; }
            if (dup){
                if (lane==0) g_mask_v[b*Sn+slot] = -1;
                continue;
            }
            const float* ev = emb + (size_t)v*Dn;
            float dot = 0.f;
            for (int k=lane;k<Dn;k+=32) dot += s_sr[k]*ev[k];
            #pragma unroll
            for (int o=16;o;o>>=1) dot += __shfl_xor_sync(0xffffffffu, dot, o);
            if (lane==0){
                float l = dot * g_inorm[v] * 12.f;
                g_mask_v[b*Sn+slot] = v;
                g_mask_l[b*Sn+slot] = l;
                atomicAdd(&g_msum[b], (double)__expf(l-SHIFT));
            }
        }
    }
}

// ---------------- K11: cp.async-pipelined fp16 GEMM, fp16 logit staging (L2-resident) ----------------
#define NSTAGE 4
__global__ void __launch_bounds__(256,2) k_gemm_mma(){
    __shared__ __align__(16) uint2 sA[NSTAGE][128][4];
    __shared__ __align__(16) uint2 sB[NSTAGE][128][4];
    int tid = threadIdx.x;
    int w = tid>>5, lane = tid&31;
    int g = lane>>2, t = lane&3;
    int wm = w>>1, wn = w&1;
    int m0 = blockIdx.x*128;
    int v0 = blockIdx.y*128;

    unsigned sAu = smem_u32(&sA[0][0][0]);
    unsigned sBu = smem_u32(&sB[0][0][0]);

    int srow = tid>>1, shalf = tid&1;
    int svrow = v0 + srow;
    int bbytes = (svrow < Vn) ? 16 : 0;
    const uint2* asrc0 = g_ap + (m0+srow)*64 + shalf*2;
    const uint2* bsrc0 = g_bp + (size_t)((svrow<Vn)?svrow:0)*64 + shalf*2;
    unsigned adst0 = sAu + (unsigned)((srow*4 + shalf*2)*8);
    unsigned bdst0 = sBu + (unsigned)((srow*4 + shalf*2)*8);

    float acc[2][8][4];
    #pragma unroll
    for (int mi=0;mi<2;mi++)
        #pragma unroll
        for (int ni=0;ni<8;ni++)
            #pragma unroll
            for (int q=0;q<4;q++) acc[mi][ni][q]=0.f;

    #pragma unroll
    for (int s=0;s<NSTAGE-1;s++){
        cp16(adst0 + (unsigned)(s*4096), asrc0 + s*4, 16);
        cp16(bdst0 + (unsigned)(s*4096), bsrc0 + s*4, bbytes);
        CP_COMMIT();
    }

    #pragma unroll 4
    for (int c=0; c<16; c++){
        CP_WAIT2();
        __syncthreads();
        int cn = c + NSTAGE - 1;
        if (cn < 16){
            int sn = cn & (NSTAGE-1);
            cp16(adst0 + (unsigned)(sn*4096), asrc0 + cn*4, 16);
            cp16(bdst0 + (unsigned)(sn*4096), bsrc0 + cn*4, bbytes);
        }
        CP_COMMIT();
        int st = c & (NSTAGE-1);
        uint2 A0[2], A1[2], Bf[8];
        #pragma unroll
        for (int mi=0;mi<2;mi++){
            A0[mi] = sA[st][wm*32 + mi*16 + g][t];
            A1[mi] = sA[st][wm*32 + mi*16 + 8 + g][t];
        }
        #pragma unroll
        for (int ni=0;ni<8;ni++)
            Bf[ni] = sB[st][wn*64 + ni*8 + g][t];
        #pragma unroll
        for (int ni=0;ni<8;ni++){
            #pragma unroll
            for (int mi=0;mi<2;mi++){
                MMA_F16(acc[mi][ni], A0[mi].x, A1[mi].x, A0[mi].y, A1[mi].y, Bf[ni].x, Bf[ni].y);
            }
        }
    }

    const float L2E = 1.44269504f;
    float rsum[4] = {0.f,0.f,0.f,0.f};
    #pragma unroll
    for (int mi=0;mi<2;mi++){
        int r0 = m0 + wm*32 + mi*16 + g;
        #pragma unroll
        for (int ni=0;ni<8;ni++){
            int col = v0 + wn*64 + ni*8 + 2*t;
            if (col < Vn){
                float s0 = 12.f*g_inorm[col], s1 = 12.f*g_inorm[col+1];
                float v00 = acc[mi][ni][0]*s0, v01 = acc[mi][ni][1]*s1;
                float v10 = acc[mi][ni][2]*s0, v11 = acc[mi][ni][3]*s1;
                __half2 h0 = __floats2half2_rn(v00, v01);
                __half2 h1 = __floats2half2_rn(v10, v11);
                unsigned* p0 = (unsigned*)(g_lt + (size_t)r0*Vn + col);
                unsigned* p1 = (unsigned*)(g_lt + (size_t)(r0+8)*Vn + col);
                *p0 = *(unsigned*)&h0;          // plain store -> L2-resident for finalize
                *p1 = *(unsigned*)&h1;
                rsum[mi*2+0] += exp2_pair_sum((v00-SHIFT)*L2E, (v01-SHIFT)*L2E);
                rsum[mi*2+1] += exp2_pair_sum((v10-SHIFT)*L2E, (v11-SHIFT)*L2E);
            }
        }
    }
    #pragma unroll
    for (int o=1;o<4;o<<=1)
        #pragma unroll
        for (int j=0;j<4;j++) rsum[j] += __shfl_xor_sync(0xffffffffu, rsum[j], o);
    if (t==0){
        #pragma unroll
        for (int j=0;j<4;j++){
            int row = m0 + wm*32 + (j>>1)*16 + (j&1)*8 + g;
            atomicAdd(&g_rowsum[row], (double)rsum[j]);
        }
    }
}

// ---------------- K12: shift + fp16->fp32 expand ----------------
__global__ void k_finalize(float* __restrict__ out){
    __shared__ float s_shift;
    int row = blockIdx.y;
    if (threadIdx.x==0){
        double sex = g_rowsum[row] - g_msum[row];
        s_shift = g_logphi[row*2+1] - (float)((double)SHIFT + log(sex));
    }
    __syncthreads();
    float sh = s_shift;
    int i = blockIdx.x*blockDim.x + threadIdx.x;   // 8 halves per thread
    if (i < Vn/8){
        const uint4* lp = (const uint4*)(g_lt + (size_t)row*Vn) + i;
        uint4 u = __ldcs(lp);
        __half2 a = *(__half2*)&u.x, b = *(__half2*)&u.y;
        __half2 cc = *(__half2*)&u.z, d = *(__half2*)&u.w;
        float2 fa = __half22float2(a), fb = __half22float2(b);
        float2 fc = __half22float2(cc), fd = __half22float2(d);
        float4* op = (float4*)(out + (size_t)row*Vn) + i*2;
        __stcs(op,   make_float4(fa.x+sh, fa.y+sh, fb.x+sh, fb.y+sh));
        __stcs(op+1, make_float4(fc.x+sh, fc.y+sh, fd.x+sh, fd.y+sh));
    }
}

// ---------------- K13: overwrite masked entries ----------------
__global__ void k_fixup(float* __restrict__ out){
    int b = blockIdx.x, s = threadIdx.x;
    if (s >= Sn) return;
    int v = g_mask_v[b*Sn+s];
    if (v < 0) return;
    float lse_in = (float)((double)SHIFT + log(g_msum[b]));
    out[(size_t)b*Vn + v] = g_mask_l[b*Sn+s] - lse_in + g_logphi[b*2+0];
}

// ---------------- launch ----------------
extern "C" void kernel_launch(void* const* d_in, const int* in_sizes, int n_in,
                              void* d_out, int out_size){
    const int* iid      = (const int*)d_in[0];
    const int* src      = (const int*)d_in[1];
    const int* dst      = (const int*)d_in[2];
    const int* dis      = (const int*)d_in[3];
    const int* tid_     = (const int*)d_in[7];
    const int* last_idx = (const int*)d_in[8];
    const float* emb        = (const float*)d_in[9];
    const float* pos_emb    = (const float*)d_in[10];
    const float* dis_emb    = (const float*)d_in[11];
    const float* target_emb = (const float*)d_in[12];
    const float* pi_w  = (const float*)d_in[13];
    const float* M_w   = (const float*)d_in[14];
    const float* q_w   = (const float*)d_in[15];
    const float* r_w   = (const float*)d_in[16];
    const float* sc1_w = (const float*)d_in[17];
    const float* sc1_b = (const float*)d_in[18];
    const float* sc2_w = (const float*)d_in[19];
    float* out = (float*)d_out;

    k_zero<<<(Nn+255)/256,256>>>();                      // 1
    k_count<<<En/256,256>>>(dst);                        // 2
    k_scan<<<1,1024>>>();                                // 3
    k_bpacknorm<<<Vn/8,256>>>(emb);                      // 4 (profiled slot)
    k_scatter<<<En/256,256>>>(dst);                      // 5
    int setup_blocks = (Nn*Dn)/256 + (Dn*64)/256 + Sn;
    k_setup<<<setup_blocks,256>>>(emb, iid, q_w, pos_emb); // 6
    k_gat<<<Nn,256>>>(src,dis,dis_emb,pi_w,M_w);         // 7
    k_f<<<Bn/8,256>>>(tid_,last_idx,target_emb,r_w);     // 8
    dim3 ge(Nn/128, 2);
    k_eagg_mma<<<ge,256>>>();                            // 9
    k_sr<<<Bn,256>>>();                                  // 10
    k_phimask<<<Bn/8 + Bn,256>>>(sc1_w,sc1_b,sc2_w,iid,emb); // 11
    dim3 gg(4, (Vn+127)/128);
    k_gemm_mma<<<gg, 256>>>();                           // 12
    dim3 gf((Vn/8 + 255)/256, Bn);
    k_finalize<<<gf,256>>>(out);                         // 13
    k_fixup<<<Bn,32>>>(out);                             // 14
}